// round 1
// baseline (speedup 1.0000x reference)
#include <cuda_runtime.h>
#include <cuda_bf16.h>
#include <math.h>

// Problem constants
#define B_    2
#define N_    8192
#define C_    256
#define HEADS_ 8
#define DH_   32
#define HM_   128           // H = W = 128
#define HW_   (HM_*HM_)     // 16384
#define NS_   1024          // (128/4)^2
#define KCOL_ 4096          // 256*4*4 im2col K

// ---------------- scratch (device globals; no allocation allowed) -------------
__device__ float g_Fmap[B_ * HW_ * C_];     // scatter accum / normalized feature
__device__ float g_Cnt [B_ * HW_];
__device__ float g_Mask[B_ * HW_];
__device__ float g_Xm  [B_ * HW_ * C_];     // reconstructed map, channels-last
__device__ float g_Acol[B_ * NS_ * KCOL_];  // im2col
__device__ float g_Wc  [C_ * KCOL_];        // permuted conv weights
__device__ float g_ConvOut[B_ * NS_ * C_];
__device__ float g_Xs  [B_ * NS_ * C_];
__device__ float g_Q   [B_ * N_ * C_];
__device__ float g_K   [B_ * NS_ * C_];
__device__ float g_V   [B_ * NS_ * C_];
__device__ float g_AO  [B_ * N_ * C_];

// ---------------- zero map ----------------------------------------------------
__global__ void __launch_bounds__(256) zero_kernel() {
    int i = blockIdx.x * 256 + threadIdx.x;           // 2097152 float4 slots
    float4 z = make_float4(0.f, 0.f, 0.f, 0.f);
    ((float4*)g_Fmap)[i] = z;
    if (i < (B_ * HW_) / 4) ((float4*)g_Cnt)[i] = z;
}

// ---------------- scatter: token2map segment_sum ------------------------------
__global__ void __launch_bounds__(256) scatter_kernel(const float* __restrict__ xs,
                                                      const float* __restrict__ loc) {
    int token = blockIdx.x;                  // 0 .. B*N-1
    int b = token >> 13;                     // /8192
    float lx = loc[(size_t)token * 2 + 0];
    float ly = loc[(size_t)token * 2 + 1];
    lx = fminf(fmaxf(lx, 0.f), 1.f) * 127.f;
    ly = fminf(fmaxf(ly, 0.f), 1.f) * 127.f;
    int ix = (int)rintf(lx);                 // round half-to-even, matches jnp.round
    int iy = (int)rintf(ly);
    int p = (b << 14) + iy * HM_ + ix;
    int c = threadIdx.x;
    atomicAdd(&g_Fmap[(size_t)p * C_ + c], xs[(size_t)token * C_ + c]);
    if (c == 0) atomicAdd(&g_Cnt[p], 1.0f);
}

// ---------------- normalize: feature /= (cnt+eps); mask binary ----------------
__global__ void __launch_bounds__(256) normalize_kernel() {
    int e = blockIdx.x * 256 + threadIdx.x;          // B*HW*C elems
    int pix = e >> 8;
    float c = g_Cnt[pix];
    float f = g_Fmap[e] / (c + 1e-6f);
    f = (c > 0.f) ? f : 0.f;
    g_Fmap[e] = f;
    if ((e & 255) == 0) g_Mask[pix] = (c > 0.f) ? 1.f : 0.f;
}

// ---------------- 3x3 gaussian reconstruct ------------------------------------
__global__ void __launch_bounds__(256) blur_kernel() {
    int blk = blockIdx.x;                 // b*HW + p
    int c = threadIdx.x;
    int b = blk >> 14;
    int p = blk & (HW_ - 1);
    int y = p >> 7, x = p & 127;

    // gaussian 3x3, sigma=2 (mean=1): exp(-(dy^2+dx^2)/8), normalized
    const float e1 = 0.88249690258459546f;   // exp(-1/8)
    const float e2 = 0.77880078307140487f;   // exp(-2/8)
    const float norm = 1.0f / (1.0f + 4.0f * e1 + 4.0f * e2);
    const float wcen = norm, wedg = e1 * norm, wcor = e2 * norm;

    float fsum = 0.f, msum = 0.f;
#pragma unroll
    for (int dy = -1; dy <= 1; dy++) {
#pragma unroll
        for (int dx = -1; dx <= 1; dx++) {
            int ny = y + dy, nx = x + dx;
            if (ny < 0 || ny >= HM_ || nx < 0 || nx >= HM_) continue;
            float g = (dy == 0 && dx == 0) ? wcen : ((dy != 0 && dx != 0) ? wcor : wedg);
            int np = (b << 14) + ny * HM_ + nx;
            fsum += g * g_Fmap[(size_t)np * C_ + c];
            msum += g * g_Mask[np];
        }
    }
    int cp = (b << 14) + p;
    float fc = g_Fmap[(size_t)cp * C_ + c];
    float mc = g_Mask[cp];
    float fint = fsum / (msum + 1e-6f);
    fint = (msum > 0.f) ? fint : 0.f;
    g_Xm[(size_t)cp * C_ + c] = fc + (1.f - mc) * fint;
}

// ---------------- conv weight permute: [co][ci][ky][kx] -> [co][(ky,kx)*256+ci]
__global__ void __launch_bounds__(256) wperm_kernel(const float* __restrict__ srw) {
    int idx = blockIdx.x * 256 + threadIdx.x;       // 256*4096
    int co = idx >> 12;
    int r  = idx & 4095;
    int kk = r >> 8;        // ky*4+kx
    int ci = r & 255;
    g_Wc[idx] = srw[(size_t)co * 4096 + ci * 16 + kk];
}

// ---------------- im2col ------------------------------------------------------
__global__ void __launch_bounds__(256) im2col_kernel() {
    int row = blockIdx.x;                 // b*1024 + oy*32+ox
    int kk  = blockIdx.y;                 // 0..15  (ky*4+kx)
    int ci  = threadIdx.x;
    int b = row >> 10;
    int rr = row & 1023;
    int oy = rr >> 5, ox = rr & 31;
    int ky = kk >> 2, kx = kk & 3;
    int py = oy * 4 + ky, px = ox * 4 + kx;
    g_Acol[(size_t)row * KCOL_ + kk * 256 + ci] =
        g_Xm[((size_t)((b << 14) + py * HM_ + px)) * C_ + ci];
}

// ---------------- tiled fp32 GEMM:  C[M,N] = A[M,K] @ W[N,K]^T (+bias) --------
__global__ void __launch_bounds__(256) gemm_nt_kernel(const float* __restrict__ A,
                                                      const float* __restrict__ W,
                                                      const float* __restrict__ bias,
                                                      float* __restrict__ C,
                                                      int M, int N, int K) {
    __shared__ float As[16][68];
    __shared__ float Ws[16][68];
    int t = threadIdx.x;
    int tx = t & 15, ty = t >> 4;
    int m0 = blockIdx.y << 6, n0 = blockIdx.x << 6;

    int lrow = t >> 2;             // 0..63
    int lk   = (t & 3) << 2;       // 0,4,8,12
    const float* Ap = A + (size_t)(m0 + lrow) * K + lk;
    const float* Wp = W + (size_t)(n0 + lrow) * K + lk;

    float acc[4][4];
#pragma unroll
    for (int i = 0; i < 4; i++)
#pragma unroll
        for (int j = 0; j < 4; j++) acc[i][j] = 0.f;

    for (int k0 = 0; k0 < K; k0 += 16) {
        float4 av = *(const float4*)(Ap + k0);
        float4 wv = *(const float4*)(Wp + k0);
        __syncthreads();
        As[lk + 0][lrow] = av.x; As[lk + 1][lrow] = av.y;
        As[lk + 2][lrow] = av.z; As[lk + 3][lrow] = av.w;
        Ws[lk + 0][lrow] = wv.x; Ws[lk + 1][lrow] = wv.y;
        Ws[lk + 2][lrow] = wv.z; Ws[lk + 3][lrow] = wv.w;
        __syncthreads();
#pragma unroll
        for (int kk = 0; kk < 16; kk++) {
            float4 a4 = *(const float4*)&As[kk][ty << 2];
            float4 b4 = *(const float4*)&Ws[kk][tx << 2];
            float ar[4] = {a4.x, a4.y, a4.z, a4.w};
            float br[4] = {b4.x, b4.y, b4.z, b4.w};
#pragma unroll
            for (int i = 0; i < 4; i++)
#pragma unroll
                for (int j = 0; j < 4; j++) acc[i][j] += ar[i] * br[j];
        }
    }
#pragma unroll
    for (int i = 0; i < 4; i++) {
        int row = m0 + (ty << 2) + i;
#pragma unroll
        for (int j = 0; j < 4; j++) {
            int col = n0 + (tx << 2) + j;
            float v = acc[i][j];
            if (bias) v += bias[col];
            C[(size_t)row * N + col] = v;
        }
    }
}

// ---------------- LayerNorm over C (input = conv_out + sr_b) ------------------
__global__ void __launch_bounds__(256) ln_kernel(const float* __restrict__ srb,
                                                 const float* __restrict__ lnw,
                                                 const float* __restrict__ lnb) {
    __shared__ float red[8];
    int row = blockIdx.x, c = threadIdx.x;
    int lane = c & 31, wrp = c >> 5;
    float v = g_ConvOut[(size_t)row * C_ + c] + srb[c];
    float s = v;
#pragma unroll
    for (int o = 16; o; o >>= 1) s += __shfl_xor_sync(~0u, s, o);
    if (lane == 0) red[wrp] = s;
    __syncthreads();
    float mu = (red[0] + red[1] + red[2] + red[3] + red[4] + red[5] + red[6] + red[7]) * (1.f / 256.f);
    float d = v - mu;
    float s2 = d * d;
#pragma unroll
    for (int o = 16; o; o >>= 1) s2 += __shfl_xor_sync(~0u, s2, o);
    __syncthreads();
    if (lane == 0) red[wrp] = s2;
    __syncthreads();
    float var = (red[0] + red[1] + red[2] + red[3] + red[4] + red[5] + red[6] + red[7]) * (1.f / 256.f);
    g_Xs[(size_t)row * C_ + c] = d * rsqrtf(var + 1e-5f) * lnw[c] + lnb[c];
}

// ---------------- fused flash attention --------------------------------------
// grid: (N/32, B*HEADS), block 256.  Q tile 32 rows, key tiles of 64, Ns=1024.
__global__ void __launch_bounds__(256) attn_kernel(const float* __restrict__ conf) {
    const int bh = blockIdx.y;
    const int b = bh >> 3, h = bh & 7;
    const int n0 = blockIdx.x << 5;
    const int t = threadIdx.x;
    const int lane = t & 31, wrp = t >> 5;

    __shared__ float Qs[32][32];
    __shared__ float Kst[32][68];   // transposed K tile [d][m], padded stride 68
    __shared__ float Vs[64][32];
    __shared__ float Sc[32][64];
    __shared__ float confs[64];

    {
        const float scale = 0.17677669529663687f;   // 1/sqrt(32)
#pragma unroll
        for (int i = 0; i < 4; i++) {
            int idx = t + i * 256;
            int r = idx >> 5, d = idx & 31;
            Qs[r][d] = g_Q[((size_t)(b * N_ + n0 + r)) * C_ + h * DH_ + d] * scale;
        }
    }

    float m_i[4], l_i[4], acc[4];
#pragma unroll
    for (int i = 0; i < 4; i++) { m_i[i] = -1e30f; l_i[i] = 0.f; acc[i] = 0.f; }

    for (int tile = 0; tile < 16; tile++) {
        int mbase = tile << 6;
        __syncthreads();
#pragma unroll
        for (int i = 0; i < 8; i++) {
            int idx = t + i * 256;
            int mm = idx >> 5, d = idx & 31;
            size_t g = ((size_t)(b * NS_ + mbase + mm)) * C_ + h * DH_ + d;
            Kst[d][mm] = g_K[g];
            Vs[mm][d] = g_V[g];
        }
        if (t < 64) confs[t] = conf[b * NS_ + mbase + t];
        __syncthreads();

        // scores: each thread 2 rows x 4 cols
        {
            int r0 = (t >> 4) << 1;
            int c0 = (t & 15) << 2;
            float s0[4] = {0, 0, 0, 0}, s1[4] = {0, 0, 0, 0};
#pragma unroll
            for (int d = 0; d < 32; d++) {
                float q0 = Qs[r0][d], q1 = Qs[r0 + 1][d];
                float4 k4 = *(const float4*)&Kst[d][c0];
                float kr[4] = {k4.x, k4.y, k4.z, k4.w};
#pragma unroll
                for (int j = 0; j < 4; j++) { s0[j] += q0 * kr[j]; s1[j] += q1 * kr[j]; }
            }
#pragma unroll
            for (int j = 0; j < 4; j++) {
                float cb = confs[c0 + j];
                Sc[r0][c0 + j] = s0[j] + cb;
                Sc[r0 + 1][c0 + j] = s1[j] + cb;
            }
        }
        __syncthreads();

        // online softmax per warp: rows 4*wrp .. 4*wrp+3
#pragma unroll
        for (int i = 0; i < 4; i++) {
            int r = (wrp << 2) + i;
            float x0 = Sc[r][lane], x1 = Sc[r][lane + 32];
            float mx = fmaxf(x0, x1);
#pragma unroll
            for (int o = 16; o; o >>= 1) mx = fmaxf(mx, __shfl_xor_sync(~0u, mx, o));
            float newm = fmaxf(m_i[i], mx);
            float alpha = __expf(m_i[i] - newm);
            float p0 = __expf(x0 - newm), p1 = __expf(x1 - newm);
            Sc[r][lane] = p0; Sc[r][lane + 32] = p1;
            float ps = p0 + p1;
#pragma unroll
            for (int o = 16; o; o >>= 1) ps += __shfl_xor_sync(~0u, ps, o);
            l_i[i] = l_i[i] * alpha + ps;
            m_i[i] = newm;
            acc[i] *= alpha;
        }
        __syncwarp();

        // P @ V : float4 broadcast of P, lane-indexed V
#pragma unroll
        for (int mg = 0; mg < 16; mg++) {
            float4 p0 = *(const float4*)&Sc[(wrp << 2) + 0][mg << 2];
            float4 p1 = *(const float4*)&Sc[(wrp << 2) + 1][mg << 2];
            float4 p2 = *(const float4*)&Sc[(wrp << 2) + 2][mg << 2];
            float4 p3 = *(const float4*)&Sc[(wrp << 2) + 3][mg << 2];
            float v0 = Vs[(mg << 2) + 0][lane];
            float v1 = Vs[(mg << 2) + 1][lane];
            float v2 = Vs[(mg << 2) + 2][lane];
            float v3 = Vs[(mg << 2) + 3][lane];
            acc[0] += p0.x * v0 + p0.y * v1 + p0.z * v2 + p0.w * v3;
            acc[1] += p1.x * v0 + p1.y * v1 + p1.z * v2 + p1.w * v3;
            acc[2] += p2.x * v0 + p2.y * v1 + p2.z * v2 + p2.w * v3;
            acc[3] += p3.x * v0 + p3.y * v1 + p3.z * v2 + p3.w * v3;
        }
    }

#pragma unroll
    for (int i = 0; i < 4; i++) {
        int r = (wrp << 2) + i;
        g_AO[((size_t)(b * N_ + n0 + r)) * C_ + h * DH_ + lane] = acc[i] / l_i[i];
    }
}

// ---------------- launch ------------------------------------------------------
extern "C" void kernel_launch(void* const* d_in, const int* in_sizes, int n_in,
                              void* d_out, int out_size) {
    const float* x        = (const float*)d_in[0];
    const float* x_source = (const float*)d_in[1];
    const float* loc      = (const float*)d_in[2];
    const float* conf     = (const float*)d_in[3];
    const float* Wq       = (const float*)d_in[4];
    const float* Wk       = (const float*)d_in[5];
    const float* Wv       = (const float*)d_in[6];
    const float* sr_w     = (const float*)d_in[7];
    const float* sr_b     = (const float*)d_in[8];
    const float* ln_w     = (const float*)d_in[9];
    const float* ln_b     = (const float*)d_in[10];
    const float* Wp       = (const float*)d_in[11];
    const float* bp       = (const float*)d_in[12];
    float* out = (float*)d_out;

    float* pFmap;   cudaGetSymbolAddress((void**)&pFmap, g_Fmap);
    float* pAcol;   cudaGetSymbolAddress((void**)&pAcol, g_Acol);
    float* pWc;     cudaGetSymbolAddress((void**)&pWc, g_Wc);
    float* pConvOut;cudaGetSymbolAddress((void**)&pConvOut, g_ConvOut);
    float* pXs;     cudaGetSymbolAddress((void**)&pXs, g_Xs);
    float* pQ;      cudaGetSymbolAddress((void**)&pQ, g_Q);
    float* pK;      cudaGetSymbolAddress((void**)&pK, g_K);
    float* pV;      cudaGetSymbolAddress((void**)&pV, g_V);
    float* pAO;     cudaGetSymbolAddress((void**)&pAO, g_AO);

    // token2map
    zero_kernel<<<(B_ * HW_ * C_) / 4 / 256, 256>>>();
    scatter_kernel<<<B_ * N_, 256>>>(x_source, loc);
    normalize_kernel<<<(B_ * HW_ * C_) / 256, 256>>>();
    blur_kernel<<<B_ * HW_, 256>>>();

    // stride-4 conv as GEMM
    wperm_kernel<<<(C_ * KCOL_) / 256, 256>>>(sr_w);
    im2col_kernel<<<dim3(B_ * NS_, 16), 256>>>();
    gemm_nt_kernel<<<dim3(C_ / 64, (B_ * NS_) / 64), 256>>>(pAcol, pWc, nullptr,
                                                            pConvOut, B_ * NS_, C_, KCOL_);
    ln_kernel<<<B_ * NS_, 256>>>(sr_b, ln_w, ln_b);

    // projections
    gemm_nt_kernel<<<dim3(C_ / 64, (B_ * N_) / 64), 256>>>(x, Wq, nullptr, pQ,
                                                           B_ * N_, C_, C_);
    gemm_nt_kernel<<<dim3(C_ / 64, (B_ * NS_) / 64), 256>>>(pXs, Wk, nullptr, pK,
                                                            B_ * NS_, C_, C_);
    gemm_nt_kernel<<<dim3(C_ / 64, (B_ * NS_) / 64), 256>>>(pXs, Wv, nullptr, pV,
                                                            B_ * NS_, C_, C_);

    // attention
    attn_kernel<<<dim3(N_ / 32, B_ * HEADS_), 256>>>(conf);

    // output projection (+bias)
    gemm_nt_kernel<<<dim3(C_ / 64, (B_ * N_) / 64), 256>>>(pAO, Wp, bp, out,
                                                           B_ * N_, C_, C_);
}

// round 3
// speedup vs baseline: 1.1781x; 1.1781x over previous
#include <cuda_runtime.h>
#include <cuda_bf16.h>
#include <cstdint>
#include <math.h>

// Problem constants
#define B_    2
#define N_    8192
#define C_    256
#define HEADS_ 8
#define DH_   32
#define HM_   128
#define HW_   (HM_*HM_)
#define NS_   1024
#define KCOL_ 4096

// ---------------- scratch (device globals) ------------------------------------
__device__ float g_Fmap[B_ * HW_ * C_];
__device__ float g_Cnt [B_ * HW_];
__device__ float g_Mask[B_ * HW_];
__device__ float g_Xm  [B_ * HW_ * C_];
__device__ float g_Acol[B_ * NS_ * KCOL_];
__device__ float g_Wc  [C_ * KCOL_];
__device__ float g_ConvOut[B_ * NS_ * C_];
__device__ float g_Xs  [B_ * NS_ * C_];
__device__ float g_Q   [B_ * N_ * C_];
__device__ float g_K   [B_ * NS_ * C_];
__device__ float g_V   [B_ * NS_ * C_];
__device__ float g_Vt  [B_ * HEADS_ * 64 * NS_];   // [bh][64][1024]: rows 0-31 V^T, row32 ones, rest 0
__device__ float g_S   [B_ * HEADS_ * N_ * NS_];   // P = exp(scores)
__device__ float g_AO  [B_ * N_ * C_];

// ================= tf32 mma helpers ===========================================
__device__ __forceinline__ void tf32split(float x, uint32_t& hi, uint32_t& lo) {
    float h, l2;
    asm("cvt.rna.tf32.f32 %0, %1;" : "=f"(h) : "f"(x));
    float l = x - h;
    asm("cvt.rna.tf32.f32 %0, %1;" : "=f"(l2) : "f"(l));
    hi = __float_as_uint(h);
    lo = __float_as_uint(l2);
}
__device__ __forceinline__ void mma8(float* c, const uint32_t* a, const uint32_t* b) {
    asm volatile(
        "mma.sync.aligned.m16n8k8.row.col.f32.tf32.tf32.f32 "
        "{%0,%1,%2,%3}, {%4,%5,%6,%7}, {%8,%9}, {%0,%1,%2,%3};"
        : "+f"(c[0]), "+f"(c[1]), "+f"(c[2]), "+f"(c[3])
        : "r"(a[0]), "r"(a[1]), "r"(a[2]), "r"(a[3]), "r"(b[0]), "r"(b[1]));
}

// ================= generic 3xTF32 GEMM ========================================
// C[z][M,N] = alpha * A[z][M,K] @ B[z][N,K]^T (+bias / exp / PV-normalize)
// BM=128, BK=32, 8 warps. Smem stride 36 floats -> conflict-free fragment loads.
template<int BN, int WARPS_M, int WARPS_N, bool PV>
__global__ void __launch_bounds__(256, 1)
tf32_gemm(const float* __restrict__ A, int lda, long long sAb, long long sAh,
          const float* __restrict__ Bw, int ldb, long long sBb, long long sBh,
          float* __restrict__ Cm, int ldc, long long sCb, long long sCh,
          int K, const float* __restrict__ bias, int sbias_b, float alpha, int do_exp) {
    constexpr int WM_T = 128 / WARPS_M / 16;   // m16 tiles per warp
    constexpr int WN_T = BN / WARPS_N / 8;     // n8 tiles per warp
    constexpr int NB4 = BN / 32;               // B float4 loads per thread
    constexpr int ES = BN + 4;                 // epilogue smem stride

    extern __shared__ float smem[];
    float* As = smem;                 // [128][36]
    float* Bs = smem + 128 * 36;      // [BN][36]
    float* epi = smem;                // reused: [128][ES]

    const int t = threadIdx.x, lane = t & 31, warp = t >> 5;
    const int g = lane >> 2, tig = lane & 3;
    const int warpM = warp / WARPS_N, warpN = warp % WARPS_N;
    const int wrb = warpM * WM_T * 16, wcb = warpN * WN_T * 8;

    const int n0 = blockIdx.x * BN;
    const int m0 = blockIdx.y * 128;
    const int z = blockIdx.z, zb = z >> 3, zh = z & 7;
    const float* Ab = A + (long long)zb * sAb + (long long)zh * sAh;
    const float* Bb = Bw + (long long)zb * sBb + (long long)zh * sBh;
    float* Cb = Cm + (long long)zb * sCb + (long long)zh * sCh;

    const int lr = t >> 3;          // 0..31
    const int lc = (t & 7) * 4;     // 0,4,...,28

    float acc[WM_T][WN_T][4];
#pragma unroll
    for (int i = 0; i < WM_T; i++)
#pragma unroll
        for (int j = 0; j < WN_T; j++)
#pragma unroll
            for (int q = 0; q < 4; q++) acc[i][j][q] = 0.f;

    const int nc = K >> 5;
    float4 pa[4], pb[NB4];

    // initial global prefetch (chunk 0)
#pragma unroll
    for (int i = 0; i < 4; i++)
        pa[i] = *(const float4*)(Ab + (size_t)(m0 + lr + i * 32) * lda + lc);
#pragma unroll
    for (int i = 0; i < NB4; i++)
        pb[i] = *(const float4*)(Bb + (size_t)(n0 + lr + i * 32) * ldb + lc);

    for (int c = 0; c < nc; c++) {
        if (c > 0) __syncthreads();
        // store prefetched regs to smem
#pragma unroll
        for (int i = 0; i < 4; i++)
            *(float4*)&As[(lr + i * 32) * 36 + lc] = pa[i];
#pragma unroll
        for (int i = 0; i < NB4; i++)
            *(float4*)&Bs[(lr + i * 32) * 36 + lc] = pb[i];
        __syncthreads();
        if (c + 1 < nc) {
            int k0 = (c + 1) << 5;
#pragma unroll
            for (int i = 0; i < 4; i++)
                pa[i] = *(const float4*)(Ab + (size_t)(m0 + lr + i * 32) * lda + k0 + lc);
#pragma unroll
            for (int i = 0; i < NB4; i++)
                pb[i] = *(const float4*)(Bb + (size_t)(n0 + lr + i * 32) * ldb + k0 + lc);
        }
        // compute chunk: 4 k-steps of 8
#pragma unroll
        for (int ks = 0; ks < 4; ks++) {
            const int k0 = ks * 8;
            uint32_t ah[WM_T][4], al[WM_T][4];
#pragma unroll
            for (int mt = 0; mt < WM_T; mt++) {
                int r0 = wrb + mt * 16;
                float x0 = As[(r0 + g) * 36 + k0 + tig];
                float x1 = As[(r0 + 8 + g) * 36 + k0 + tig];
                float x2 = As[(r0 + g) * 36 + k0 + tig + 4];
                float x3 = As[(r0 + 8 + g) * 36 + k0 + tig + 4];
                tf32split(x0, ah[mt][0], al[mt][0]);
                tf32split(x1, ah[mt][1], al[mt][1]);
                tf32split(x2, ah[mt][2], al[mt][2]);
                tf32split(x3, ah[mt][3], al[mt][3]);
            }
            uint32_t bh[WN_T][2], bl[WN_T][2];
#pragma unroll
            for (int nt = 0; nt < WN_T; nt++) {
                int nr = wcb + nt * 8 + g;
                float y0 = Bs[nr * 36 + k0 + tig];
                float y1 = Bs[nr * 36 + k0 + tig + 4];
                tf32split(y0, bh[nt][0], bl[nt][0]);
                tf32split(y1, bh[nt][1], bl[nt][1]);
            }
#pragma unroll
            for (int mt = 0; mt < WM_T; mt++)
#pragma unroll
                for (int nt = 0; nt < WN_T; nt++) {
                    mma8(acc[mt][nt], ah[mt], bh[nt]);
                    mma8(acc[mt][nt], al[mt], bh[nt]);
                    mma8(acc[mt][nt], ah[mt], bl[nt]);
                }
        }
    }
    __syncthreads();

    // stage accumulators through smem
#pragma unroll
    for (int mt = 0; mt < WM_T; mt++)
#pragma unroll
        for (int nt = 0; nt < WN_T; nt++) {
            int r = wrb + mt * 16 + g;
            int cc = wcb + nt * 8 + 2 * tig;
            epi[r * ES + cc] = acc[mt][nt][0];
            epi[r * ES + cc + 1] = acc[mt][nt][1];
            epi[(r + 8) * ES + cc] = acc[mt][nt][2];
            epi[(r + 8) * ES + cc + 1] = acc[mt][nt][3];
        }
    __syncthreads();

    if (PV) {
        // cols 0..31 = sum(P*V); col 32 = sum(P) -> normalize
        for (int idx = t; idx < 128 * 32; idx += 256) {
            int r = idx >> 5, cc = idx & 31;
            float l = epi[r * ES + 32];
            Cb[(size_t)(m0 + r) * ldc + cc] = epi[r * ES + cc] / l;
        }
    } else {
        const float* bp2 = bias ? (bias + (long long)zb * sbias_b) : nullptr;
        for (int idx = t; idx < 128 * BN; idx += 256) {
            int r = idx / BN, cc = idx % BN;
            float v = epi[r * ES + cc] * alpha;
            if (bp2) v += bp2[n0 + cc];
            if (do_exp) v = __expf(v);
            Cb[(size_t)(m0 + r) * ldc + n0 + cc] = v;
        }
    }
}

// ================= pre/post processing kernels ================================
__global__ void __launch_bounds__(256) zero_kernel() {
    int i = blockIdx.x * 256 + threadIdx.x;
    float4 zf = make_float4(0.f, 0.f, 0.f, 0.f);
    ((float4*)g_Fmap)[i] = zf;
    if (i < (B_ * HW_) / 4) ((float4*)g_Cnt)[i] = zf;
}

__global__ void __launch_bounds__(256) scatter_kernel(const float* __restrict__ xs,
                                                      const float* __restrict__ loc) {
    int token = blockIdx.x;
    int b = token >> 13;
    float lx = loc[(size_t)token * 2 + 0];
    float ly = loc[(size_t)token * 2 + 1];
    lx = fminf(fmaxf(lx, 0.f), 1.f) * 127.f;
    ly = fminf(fmaxf(ly, 0.f), 1.f) * 127.f;
    int ix = (int)rintf(lx);
    int iy = (int)rintf(ly);
    int p = (b << 14) + iy * HM_ + ix;
    int c = threadIdx.x;
    atomicAdd(&g_Fmap[(size_t)p * C_ + c], xs[(size_t)token * C_ + c]);
    if (c == 0) atomicAdd(&g_Cnt[p], 1.0f);
}

__global__ void __launch_bounds__(256) normalize_kernel() {
    int e = blockIdx.x * 256 + threadIdx.x;
    int pix = e >> 8;
    float c = g_Cnt[pix];
    float f = g_Fmap[e] / (c + 1e-6f);
    f = (c > 0.f) ? f : 0.f;
    g_Fmap[e] = f;
    if ((e & 255) == 0) g_Mask[pix] = (c > 0.f) ? 1.f : 0.f;
}

__global__ void __launch_bounds__(256) blur_kernel() {
    int blk = blockIdx.x;
    int c = threadIdx.x;
    int b = blk >> 14;
    int p = blk & (HW_ - 1);
    int y = p >> 7, x = p & 127;
    const float e1 = 0.88249690258459546f;
    const float e2 = 0.77880078307140487f;
    const float norm = 1.0f / (1.0f + 4.0f * e1 + 4.0f * e2);
    const float wcen = norm, wedg = e1 * norm, wcor = e2 * norm;
    float fsum = 0.f, msum = 0.f;
#pragma unroll
    for (int dy = -1; dy <= 1; dy++) {
#pragma unroll
        for (int dx = -1; dx <= 1; dx++) {
            int ny = y + dy, nx = x + dx;
            if (ny < 0 || ny >= HM_ || nx < 0 || nx >= HM_) continue;
            float gg = (dy == 0 && dx == 0) ? wcen : ((dy != 0 && dx != 0) ? wcor : wedg);
            int np = (b << 14) + ny * HM_ + nx;
            fsum += gg * g_Fmap[(size_t)np * C_ + c];
            msum += gg * g_Mask[np];
        }
    }
    int cp = (b << 14) + p;
    float fc = g_Fmap[(size_t)cp * C_ + c];
    float mc = g_Mask[cp];
    float fint = fsum / (msum + 1e-6f);
    fint = (msum > 0.f) ? fint : 0.f;
    g_Xm[(size_t)cp * C_ + c] = fc + (1.f - mc) * fint;
}

__global__ void __launch_bounds__(256) wperm_kernel(const float* __restrict__ srw) {
    int idx = blockIdx.x * 256 + threadIdx.x;
    int co = idx >> 12;
    int r = idx & 4095;
    int kk = r >> 8;
    int ci = r & 255;
    g_Wc[idx] = srw[(size_t)co * 4096 + ci * 16 + kk];
}

__global__ void __launch_bounds__(256) im2col_kernel() {
    int row = blockIdx.x;
    int kk = blockIdx.y;
    int ci = threadIdx.x;
    int b = row >> 10;
    int rr = row & 1023;
    int oy = rr >> 5, ox = rr & 31;
    int ky = kk >> 2, kx = kk & 3;
    int py = oy * 4 + ky, px = ox * 4 + kx;
    g_Acol[(size_t)row * KCOL_ + kk * 256 + ci] =
        g_Xm[((size_t)((b << 14) + py * HM_ + px)) * C_ + ci];
}

__global__ void __launch_bounds__(256) ln_kernel(const float* __restrict__ srb,
                                                 const float* __restrict__ lnw,
                                                 const float* __restrict__ lnb) {
    __shared__ float red[8];
    int row = blockIdx.x, c = threadIdx.x;
    int lane = c & 31, wrp = c >> 5;
    float v = g_ConvOut[(size_t)row * C_ + c] + srb[c];
    float s = v;
#pragma unroll
    for (int o = 16; o; o >>= 1) s += __shfl_xor_sync(~0u, s, o);
    if (lane == 0) red[wrp] = s;
    __syncthreads();
    float mu = (red[0] + red[1] + red[2] + red[3] + red[4] + red[5] + red[6] + red[7]) * (1.f / 256.f);
    float d = v - mu;
    float s2 = d * d;
#pragma unroll
    for (int o = 16; o; o >>= 1) s2 += __shfl_xor_sync(~0u, s2, o);
    __syncthreads();
    if (lane == 0) red[wrp] = s2;
    __syncthreads();
    float var = (red[0] + red[1] + red[2] + red[3] + red[4] + red[5] + red[6] + red[7]) * (1.f / 256.f);
    g_Xs[(size_t)row * C_ + c] = d * rsqrtf(var + 1e-5f) * lnw[c] + lnb[c];
}

// Build Vt[bh][64][1024]: rows 0-31 = V^T per head, row 32 = ones, rows 33-63 = 0
__global__ void __launch_bounds__(256) vt_kernel() {
    int bh = blockIdx.x, row = blockIdx.y;
    int b = bh >> 3, h = bh & 7;
    for (int m = threadIdx.x; m < NS_; m += 256) {
        float v;
        if (row < 32)       v = g_V[((size_t)(b * NS_ + m)) * C_ + h * DH_ + row];
        else if (row == 32) v = 1.0f;
        else                v = 0.0f;
        g_Vt[(size_t)bh * 64 * NS_ + row * NS_ + m] = v;
    }
}

// ================= launch =====================================================
extern "C" void kernel_launch(void* const* d_in, const int* in_sizes, int n_in,
                              void* d_out, int out_size) {
    const float* x        = (const float*)d_in[0];
    const float* x_source = (const float*)d_in[1];
    const float* loc      = (const float*)d_in[2];
    const float* conf     = (const float*)d_in[3];
    const float* Wq       = (const float*)d_in[4];
    const float* Wk       = (const float*)d_in[5];
    const float* Wv       = (const float*)d_in[6];
    const float* sr_w     = (const float*)d_in[7];
    const float* sr_b     = (const float*)d_in[8];
    const float* ln_w     = (const float*)d_in[9];
    const float* ln_b     = (const float*)d_in[10];
    const float* Wp       = (const float*)d_in[11];
    const float* bp       = (const float*)d_in[12];
    float* out = (float*)d_out;

    float *pAcol, *pWc, *pConvOut, *pXs, *pQ, *pK, *pV, *pVt, *pS, *pAO;
    cudaGetSymbolAddress((void**)&pAcol, g_Acol);
    cudaGetSymbolAddress((void**)&pWc, g_Wc);
    cudaGetSymbolAddress((void**)&pConvOut, g_ConvOut);
    cudaGetSymbolAddress((void**)&pXs, g_Xs);
    cudaGetSymbolAddress((void**)&pQ, g_Q);
    cudaGetSymbolAddress((void**)&pK, g_K);
    cudaGetSymbolAddress((void**)&pV, g_V);
    cudaGetSymbolAddress((void**)&pVt, g_Vt);
    cudaGetSymbolAddress((void**)&pS, g_S);
    cudaGetSymbolAddress((void**)&pAO, g_AO);

    // smem: BN=128 -> max(A+B=36864, epi=128*132*4=67584) = 67584
    //       BN=64  -> max(27648, 128*68*4=34816) = 34816
    const size_t SM128 = 67584;
    const size_t SM64  = 34816;
    cudaFuncSetAttribute((const void*)tf32_gemm<128, 2, 4, false>,
                         cudaFuncAttributeMaxDynamicSharedMemorySize, (int)SM128);
    cudaFuncSetAttribute((const void*)tf32_gemm<64, 4, 2, true>,
                         cudaFuncAttributeMaxDynamicSharedMemorySize, (int)SM64);

    // token2map
    zero_kernel<<<(B_ * HW_ * C_) / 4 / 256, 256>>>();
    scatter_kernel<<<B_ * N_, 256>>>(x_source, loc);
    normalize_kernel<<<(B_ * HW_ * C_) / 256, 256>>>();
    blur_kernel<<<B_ * HW_, 256>>>();

    // stride-4 conv as GEMM  (M=2048, N=256, K=4096)
    wperm_kernel<<<(C_ * KCOL_) / 256, 256>>>(sr_w);
    im2col_kernel<<<dim3(B_ * NS_, 16), 256>>>();
    tf32_gemm<128, 2, 4, false><<<dim3(2, 16, 1), 256, SM128>>>(
        pAcol, KCOL_, 0, 0, pWc, KCOL_, 0, 0, pConvOut, C_, 0, 0,
        KCOL_, nullptr, 0, 1.f, 0);
    ln_kernel<<<B_ * NS_, 256>>>(sr_b, ln_w, ln_b);

    // projections q/k/v
    tf32_gemm<128, 2, 4, false><<<dim3(2, 128, 1), 256, SM128>>>(
        x, C_, 0, 0, Wq, C_, 0, 0, pQ, C_, 0, 0, C_, nullptr, 0, 1.f, 0);
    tf32_gemm<128, 2, 4, false><<<dim3(2, 16, 1), 256, SM128>>>(
        pXs, C_, 0, 0, Wk, C_, 0, 0, pK, C_, 0, 0, C_, nullptr, 0, 1.f, 0);
    tf32_gemm<128, 2, 4, false><<<dim3(2, 16, 1), 256, SM128>>>(
        pXs, C_, 0, 0, Wv, C_, 0, 0, pV, C_, 0, 0, C_, nullptr, 0, 1.f, 0);
    vt_kernel<<<dim3(B_ * HEADS_, 64), 256>>>();

    // S = exp(scale * Q K^T + conf)   batched over bh  (M=8192, N=1024, K=32)
    const float scale = 0.17677669529663687f;
    tf32_gemm<128, 2, 4, false><<<dim3(NS_ / 128, N_ / 128, B_ * HEADS_), 256, SM128>>>(
        pQ, C_, (long long)N_ * C_, DH_,
        pK, C_, (long long)NS_ * C_, DH_,
        pS, NS_, (long long)HEADS_ * N_ * NS_, (long long)N_ * NS_,
        DH_, conf, NS_, scale, 1);

    // O = (P @ [V^T; 1]) with per-row normalization  (M=8192, N=64pad, K=1024)
    tf32_gemm<64, 4, 2, true><<<dim3(1, N_ / 128, B_ * HEADS_), 256, SM64>>>(
        pS, NS_, (long long)HEADS_ * N_ * NS_, (long long)N_ * NS_,
        pVt, NS_, (long long)HEADS_ * 64 * NS_, (long long)64 * NS_,
        pAO, C_, (long long)N_ * C_, DH_,
        NS_, nullptr, 0, 1.f, 0);

    // output projection (+bias)
    tf32_gemm<128, 2, 4, false><<<dim3(2, 128, 1), 256, SM128>>>(
        pAO, C_, 0, 0, Wp, C_, 0, 0, out, C_, 0, 0, C_, bp, 0, 1.f, 0);
}

// round 4
// speedup vs baseline: 2.1874x; 1.8568x over previous
#include <cuda_runtime.h>
#include <cuda_bf16.h>
#include <cstdint>
#include <math.h>

// Problem constants
#define B_    2
#define N_    8192
#define C_    256
#define HEADS_ 8
#define DH_   32
#define HM_   128
#define HW_   (HM_*HM_)
#define NS_   1024
#define KCOL_ 4096
#define KSPL_ 8
#define KCH_  (KCOL_/KSPL_)   // 512

// ---------------- scratch (device globals) ------------------------------------
__device__ float g_Fmap[B_ * HW_ * C_];
__device__ float g_Cnt [B_ * HW_];
__device__ float g_Mask[B_ * HW_];
__device__ float g_Xm  [B_ * HW_ * C_];
__device__ float g_Acol[B_ * NS_ * KCOL_];
__device__ float g_Wc  [C_ * KCOL_];
__device__ float g_CPart[KSPL_ * B_ * NS_ * C_];   // conv split-K partials
__device__ float g_Xs  [B_ * NS_ * C_];
__device__ float g_Q   [B_ * N_ * C_];
__device__ float g_K   [B_ * NS_ * C_];
__device__ float g_V   [B_ * NS_ * C_];
__device__ float g_AO  [B_ * N_ * C_];

// ================= tf32 mma helpers ===========================================
__device__ __forceinline__ void tf32split(float x, uint32_t& hi, uint32_t& lo) {
    float h, l2;
    asm("cvt.rna.tf32.f32 %0, %1;" : "=f"(h) : "f"(x));
    float l = x - h;
    asm("cvt.rna.tf32.f32 %0, %1;" : "=f"(l2) : "f"(l));
    hi = __float_as_uint(h);
    lo = __float_as_uint(l2);
}
__device__ __forceinline__ uint32_t tf32one(float x) {
    float h;
    asm("cvt.rna.tf32.f32 %0, %1;" : "=f"(h) : "f"(x));
    return __float_as_uint(h);
}
__device__ __forceinline__ void mma8(float* c, const uint32_t* a, const uint32_t* b) {
    asm volatile(
        "mma.sync.aligned.m16n8k8.row.col.f32.tf32.tf32.f32 "
        "{%0,%1,%2,%3}, {%4,%5,%6,%7}, {%8,%9}, {%0,%1,%2,%3};"
        : "+f"(c[0]), "+f"(c[1]), "+f"(c[2]), "+f"(c[3])
        : "r"(a[0]), "r"(a[1]), "r"(a[2]), "r"(a[3]), "r"(b[0]), "r"(b[1]));
}

// ================= generic 3xTF32 GEMM (non-attention) ========================
// C[z] = alpha * A[z][M,K] @ B[z][N,K]^T (+bias)
template<int BN, int WARPS_M, int WARPS_N>
__global__ void __launch_bounds__(256, 1)
tf32_gemm(const float* __restrict__ A, int lda, long long sAb, long long sAh,
          const float* __restrict__ Bw, int ldb, long long sBb, long long sBh,
          float* __restrict__ Cm, int ldc, long long sCb, long long sCh,
          int K, const float* __restrict__ bias, float alpha) {
    constexpr int WM_T = 128 / WARPS_M / 16;
    constexpr int WN_T = BN / WARPS_N / 8;
    constexpr int NB4 = BN / 32;
    constexpr int ES = BN + 4;

    extern __shared__ float smem[];
    float* As = smem;
    float* Bs = smem + 128 * 36;
    float* epi = smem;

    const int t = threadIdx.x, lane = t & 31, warp = t >> 5;
    const int g = lane >> 2, tig = lane & 3;
    const int warpM = warp / WARPS_N, warpN = warp % WARPS_N;
    const int wrb = warpM * WM_T * 16, wcb = warpN * WN_T * 8;

    const int n0 = blockIdx.x * BN;
    const int m0 = blockIdx.y * 128;
    const int z = blockIdx.z, zb = z >> 3, zh = z & 7;
    const float* Ab = A + (long long)zb * sAb + (long long)zh * sAh;
    const float* Bb = Bw + (long long)zb * sBb + (long long)zh * sBh;
    float* Cb = Cm + (long long)zb * sCb + (long long)zh * sCh;

    const int lr = t >> 3;
    const int lc = (t & 7) * 4;

    float acc[WM_T][WN_T][4];
#pragma unroll
    for (int i = 0; i < WM_T; i++)
#pragma unroll
        for (int j = 0; j < WN_T; j++)
#pragma unroll
            for (int q = 0; q < 4; q++) acc[i][j][q] = 0.f;

    const int nc = K >> 5;
    float4 pa[4], pb[NB4];
#pragma unroll
    for (int i = 0; i < 4; i++)
        pa[i] = *(const float4*)(Ab + (size_t)(m0 + lr + i * 32) * lda + lc);
#pragma unroll
    for (int i = 0; i < NB4; i++)
        pb[i] = *(const float4*)(Bb + (size_t)(n0 + lr + i * 32) * ldb + lc);

    for (int c = 0; c < nc; c++) {
        if (c > 0) __syncthreads();
#pragma unroll
        for (int i = 0; i < 4; i++)
            *(float4*)&As[(lr + i * 32) * 36 + lc] = pa[i];
#pragma unroll
        for (int i = 0; i < NB4; i++)
            *(float4*)&Bs[(lr + i * 32) * 36 + lc] = pb[i];
        __syncthreads();
        if (c + 1 < nc) {
            int k0 = (c + 1) << 5;
#pragma unroll
            for (int i = 0; i < 4; i++)
                pa[i] = *(const float4*)(Ab + (size_t)(m0 + lr + i * 32) * lda + k0 + lc);
#pragma unroll
            for (int i = 0; i < NB4; i++)
                pb[i] = *(const float4*)(Bb + (size_t)(n0 + lr + i * 32) * ldb + k0 + lc);
        }
#pragma unroll
        for (int ks = 0; ks < 4; ks++) {
            const int k0 = ks * 8;
            uint32_t ah[WM_T][4], al[WM_T][4];
#pragma unroll
            for (int mt = 0; mt < WM_T; mt++) {
                int r0 = wrb + mt * 16;
                tf32split(As[(r0 + g) * 36 + k0 + tig],     ah[mt][0], al[mt][0]);
                tf32split(As[(r0 + 8 + g) * 36 + k0 + tig], ah[mt][1], al[mt][1]);
                tf32split(As[(r0 + g) * 36 + k0 + tig + 4], ah[mt][2], al[mt][2]);
                tf32split(As[(r0 + 8 + g) * 36 + k0 + tig + 4], ah[mt][3], al[mt][3]);
            }
            uint32_t bh[WN_T][2], bl[WN_T][2];
#pragma unroll
            for (int nt = 0; nt < WN_T; nt++) {
                int nr = wcb + nt * 8 + g;
                tf32split(Bs[nr * 36 + k0 + tig],     bh[nt][0], bl[nt][0]);
                tf32split(Bs[nr * 36 + k0 + tig + 4], bh[nt][1], bl[nt][1]);
            }
#pragma unroll
            for (int mt = 0; mt < WM_T; mt++)
#pragma unroll
                for (int nt = 0; nt < WN_T; nt++) {
                    mma8(acc[mt][nt], ah[mt], bh[nt]);
                    mma8(acc[mt][nt], al[mt], bh[nt]);
                    mma8(acc[mt][nt], ah[mt], bl[nt]);
                }
        }
    }
    __syncthreads();
#pragma unroll
    for (int mt = 0; mt < WM_T; mt++)
#pragma unroll
        for (int nt = 0; nt < WN_T; nt++) {
            int r = wrb + mt * 16 + g;
            int cc = wcb + nt * 8 + 2 * tig;
            epi[r * ES + cc] = acc[mt][nt][0];
            epi[r * ES + cc + 1] = acc[mt][nt][1];
            epi[(r + 8) * ES + cc] = acc[mt][nt][2];
            epi[(r + 8) * ES + cc + 1] = acc[mt][nt][3];
        }
    __syncthreads();
    for (int idx = t; idx < 128 * BN; idx += 256) {
        int r = idx / BN, cc = idx % BN;
        float v = epi[r * ES + cc] * alpha;
        if (bias) v += bias[n0 + cc];
        Cb[(size_t)(m0 + r) * ldc + n0 + cc] = v;
    }
}

// ================= fused flash attention (tf32 mma) ===========================
// grid (64, 16), block 256.  Per CTA: 128 queries x one (b,h), 8 key chunks of 128.
__global__ void __launch_bounds__(256, 1)
attn_fused(const float* __restrict__ conf) {
    extern __shared__ float smem[];
    float* Qh = smem;                    // [128][36] hi
    float* Ql = Qh + 128 * 36;           // [128][36] lo
    float* Ksh = Ql + 128 * 36;          // [128][36] hi
    float* Ksl = Ksh + 128 * 36;         // [128][36] lo
    float* Vs = Ksl + 128 * 36;          // [32][132] tf32-rounded V^T
    float* confs = Vs + 32 * 132;        // [128]

    const int t = threadIdx.x, lane = t & 31, warp = t >> 5;
    const int g = lane >> 2, tig = lane & 3;
    const int bh = blockIdx.y, b = bh >> 3, h = bh & 7;
    const int m0 = blockIdx.x << 7;
    const int wrb = warp << 4;
    const float scale = 0.17677669529663687f;

    // load Q tile (x scale), split hi/lo
    {
        const int lr = t >> 3, lc = (t & 7) * 4;
#pragma unroll
        for (int i = 0; i < 4; i++) {
            int r = lr + i * 32;
            float4 v = *(const float4*)(g_Q + (size_t)(b * N_ + m0 + r) * C_ + h * DH_ + lc);
            float vv[4] = {v.x * scale, v.y * scale, v.z * scale, v.w * scale};
#pragma unroll
            for (int j = 0; j < 4; j++) {
                uint32_t hi, lo;
                tf32split(vv[j], hi, lo);
                Qh[r * 36 + lc + j] = __uint_as_float(hi);
                Ql[r * 36 + lc + j] = __uint_as_float(lo);
            }
        }
    }

    float Oacc[4][4];
#pragma unroll
    for (int i = 0; i < 4; i++)
#pragma unroll
        for (int j = 0; j < 4; j++) Oacc[i][j] = 0.f;
    float l0 = 0.f, l1 = 0.f;

    for (int kc = 0; kc < 8; kc++) {
        const int kb = kc << 7;
        if (kc > 0) __syncthreads();
        // load K chunk, split hi/lo
        {
            const int lr = t >> 3, lc = (t & 7) * 4;
#pragma unroll
            for (int i = 0; i < 4; i++) {
                int r = lr + i * 32;
                float4 v = *(const float4*)(g_K + (size_t)(b * NS_ + kb + r) * C_ + h * DH_ + lc);
                float vv[4] = {v.x, v.y, v.z, v.w};
#pragma unroll
                for (int j = 0; j < 4; j++) {
                    uint32_t hi, lo;
                    tf32split(vv[j], hi, lo);
                    Ksh[r * 36 + lc + j] = __uint_as_float(hi);
                    Ksl[r * 36 + lc + j] = __uint_as_float(lo);
                }
            }
        }
        // load V chunk transposed, pre-rounded to tf32
        for (int idx = t; idx < 128 * 32; idx += 256) {
            int key = idx >> 5, d = idx & 31;
            float v = g_V[(size_t)(b * NS_ + kb + key) * C_ + h * DH_ + d];
            Vs[d * 132 + key] = __uint_as_float(tf32one(v));
        }
        if (t < 128) confs[t] = conf[b * NS_ + kb + t];
        __syncthreads();

        // S = Q K^T (3xTF32): warp rows [wrb, wrb+16), 16 n8 tiles
        float Sacc[16][4];
#pragma unroll
        for (int nt = 0; nt < 16; nt++)
#pragma unroll
            for (int q = 0; q < 4; q++) Sacc[nt][q] = 0.f;

#pragma unroll
        for (int ks = 0; ks < 4; ks++) {
            const int k0 = ks * 8;
            uint32_t ah[4], al[4];
            ah[0] = __float_as_uint(Qh[(wrb + g) * 36 + k0 + tig]);
            ah[1] = __float_as_uint(Qh[(wrb + 8 + g) * 36 + k0 + tig]);
            ah[2] = __float_as_uint(Qh[(wrb + g) * 36 + k0 + tig + 4]);
            ah[3] = __float_as_uint(Qh[(wrb + 8 + g) * 36 + k0 + tig + 4]);
            al[0] = __float_as_uint(Ql[(wrb + g) * 36 + k0 + tig]);
            al[1] = __float_as_uint(Ql[(wrb + 8 + g) * 36 + k0 + tig]);
            al[2] = __float_as_uint(Ql[(wrb + g) * 36 + k0 + tig + 4]);
            al[3] = __float_as_uint(Ql[(wrb + 8 + g) * 36 + k0 + tig + 4]);
#pragma unroll
            for (int nt = 0; nt < 16; nt++) {
                int nr = nt * 8 + g;
                uint32_t bhv[2], blv[2];
                bhv[0] = __float_as_uint(Ksh[nr * 36 + k0 + tig]);
                bhv[1] = __float_as_uint(Ksh[nr * 36 + k0 + tig + 4]);
                blv[0] = __float_as_uint(Ksl[nr * 36 + k0 + tig]);
                blv[1] = __float_as_uint(Ksl[nr * 36 + k0 + tig + 4]);
                mma8(Sacc[nt], ah, bhv);
                mma8(Sacc[nt], al, bhv);
                mma8(Sacc[nt], ah, blv);
            }
        }

        // exp + row-sum + PV (P via c->a fragment shuffle)
        const int srcA = (g << 2) + (tig >> 1);
        const int srcB = srcA + 2;
        const bool odd = (tig & 1);
#pragma unroll
        for (int nt = 0; nt < 16; nt++) {
            float ca = confs[nt * 8 + 2 * tig];
            float cb2 = confs[nt * 8 + 2 * tig + 1];
            float p0 = __expf(Sacc[nt][0] + ca);
            float p1 = __expf(Sacc[nt][1] + cb2);
            float p2 = __expf(Sacc[nt][2] + ca);
            float p3 = __expf(Sacc[nt][3] + cb2);
            l0 += p0 + p1;
            l1 += p2 + p3;

            float s0 = __shfl_sync(~0u, p0, srcA);
            float s1 = __shfl_sync(~0u, p1, srcA);
            float s2 = __shfl_sync(~0u, p2, srcA);
            float s3 = __shfl_sync(~0u, p3, srcA);
            float u0 = __shfl_sync(~0u, p0, srcB);
            float u1 = __shfl_sync(~0u, p1, srcB);
            float u2 = __shfl_sync(~0u, p2, srcB);
            float u3 = __shfl_sync(~0u, p3, srcB);

            uint32_t a[4];
            a[0] = tf32one(odd ? s1 : s0);
            a[1] = tf32one(odd ? s3 : s2);
            a[2] = tf32one(odd ? u1 : u0);
            a[3] = tf32one(odd ? u3 : u2);

#pragma unroll
            for (int dt = 0; dt < 4; dt++) {
                uint32_t bv[2];
                bv[0] = __float_as_uint(Vs[(dt * 8 + g) * 132 + nt * 8 + tig]);
                bv[1] = __float_as_uint(Vs[(dt * 8 + g) * 132 + nt * 8 + tig + 4]);
                mma8(Oacc[dt], a, bv);
            }
        }
    }

    // reduce row sums across the 4-thread group
    l0 += __shfl_xor_sync(~0u, l0, 1); l0 += __shfl_xor_sync(~0u, l0, 2);
    l1 += __shfl_xor_sync(~0u, l1, 1); l1 += __shfl_xor_sync(~0u, l1, 2);
    float r0inv = 1.f / l0, r1inv = 1.f / l1;

    // write O
#pragma unroll
    for (int dt = 0; dt < 4; dt++) {
        int cc = h * DH_ + dt * 8 + 2 * tig;
        size_t rowa = (size_t)(b * N_ + m0 + wrb + g) * C_;
        size_t rowb = (size_t)(b * N_ + m0 + wrb + 8 + g) * C_;
        g_AO[rowa + cc]     = Oacc[dt][0] * r0inv;
        g_AO[rowa + cc + 1] = Oacc[dt][1] * r0inv;
        g_AO[rowb + cc]     = Oacc[dt][2] * r1inv;
        g_AO[rowb + cc + 1] = Oacc[dt][3] * r1inv;
    }
}

// ================= pre/post processing kernels ================================
__global__ void __launch_bounds__(256) zero_kernel() {
    int i = blockIdx.x * 256 + threadIdx.x;
    float4 zf = make_float4(0.f, 0.f, 0.f, 0.f);
    ((float4*)g_Fmap)[i] = zf;
    if (i < (B_ * HW_) / 4) ((float4*)g_Cnt)[i] = zf;
}

__global__ void __launch_bounds__(256) scatter_kernel(const float* __restrict__ xs,
                                                      const float* __restrict__ loc) {
    int token = blockIdx.x;
    int b = token >> 13;
    float lx = loc[(size_t)token * 2 + 0];
    float ly = loc[(size_t)token * 2 + 1];
    lx = fminf(fmaxf(lx, 0.f), 1.f) * 127.f;
    ly = fminf(fmaxf(ly, 0.f), 1.f) * 127.f;
    int ix = (int)rintf(lx);
    int iy = (int)rintf(ly);
    int p = (b << 14) + iy * HM_ + ix;
    int c = threadIdx.x;
    atomicAdd(&g_Fmap[(size_t)p * C_ + c], xs[(size_t)token * C_ + c]);
    if (c == 0) atomicAdd(&g_Cnt[p], 1.0f);
}

__global__ void __launch_bounds__(256) normalize_kernel() {
    int e = blockIdx.x * 256 + threadIdx.x;
    int pix = e >> 8;
    float c = g_Cnt[pix];
    float f = g_Fmap[e] / (c + 1e-6f);
    f = (c > 0.f) ? f : 0.f;
    g_Fmap[e] = f;
    if ((e & 255) == 0) g_Mask[pix] = (c > 0.f) ? 1.f : 0.f;
}

__global__ void __launch_bounds__(256) blur_kernel() {
    int blk = blockIdx.x;
    int c = threadIdx.x;
    int b = blk >> 14;
    int p = blk & (HW_ - 1);
    int y = p >> 7, x = p & 127;
    const float e1 = 0.88249690258459546f;
    const float e2 = 0.77880078307140487f;
    const float norm = 1.0f / (1.0f + 4.0f * e1 + 4.0f * e2);
    const float wcen = norm, wedg = e1 * norm, wcor = e2 * norm;
    float fsum = 0.f, msum = 0.f;
#pragma unroll
    for (int dy = -1; dy <= 1; dy++) {
#pragma unroll
        for (int dx = -1; dx <= 1; dx++) {
            int ny = y + dy, nx = x + dx;
            if (ny < 0 || ny >= HM_ || nx < 0 || nx >= HM_) continue;
            float gg = (dy == 0 && dx == 0) ? wcen : ((dy != 0 && dx != 0) ? wcor : wedg);
            int np = (b << 14) + ny * HM_ + nx;
            fsum += gg * g_Fmap[(size_t)np * C_ + c];
            msum += gg * g_Mask[np];
        }
    }
    int cp = (b << 14) + p;
    float fc = g_Fmap[(size_t)cp * C_ + c];
    float mc = g_Mask[cp];
    float fint = fsum / (msum + 1e-6f);
    fint = (msum > 0.f) ? fint : 0.f;
    g_Xm[(size_t)cp * C_ + c] = fc + (1.f - mc) * fint;
}

__global__ void __launch_bounds__(256) wperm_kernel(const float* __restrict__ srw) {
    int idx = blockIdx.x * 256 + threadIdx.x;
    int co = idx >> 12;
    int r = idx & 4095;
    int kk = r >> 8;
    int ci = r & 255;
    g_Wc[idx] = srw[(size_t)co * 4096 + ci * 16 + kk];
}

__global__ void __launch_bounds__(256) im2col_kernel() {
    int row = blockIdx.x;
    int kk = blockIdx.y;
    int ci = threadIdx.x;
    int b = row >> 10;
    int rr = row & 1023;
    int oy = rr >> 5, ox = rr & 31;
    int ky = kk >> 2, kx = kk & 3;
    int py = oy * 4 + ky, px = ox * 4 + kx;
    g_Acol[(size_t)row * KCOL_ + kk * 256 + ci] =
        g_Xm[((size_t)((b << 14) + py * HM_ + px)) * C_ + ci];
}

// LN over C; input = sum of split-K conv partials + sr_b
__global__ void __launch_bounds__(256) ln_kernel(const float* __restrict__ srb,
                                                 const float* __restrict__ lnw,
                                                 const float* __restrict__ lnb) {
    __shared__ float red[8];
    int row = blockIdx.x, c = threadIdx.x;
    int lane = c & 31, wrp = c >> 5;
    float v = srb[c];
#pragma unroll
    for (int s = 0; s < KSPL_; s++)
        v += g_CPart[(size_t)s * (B_ * NS_ * C_) + (size_t)row * C_ + c];
    float s = v;
#pragma unroll
    for (int o = 16; o; o >>= 1) s += __shfl_xor_sync(~0u, s, o);
    if (lane == 0) red[wrp] = s;
    __syncthreads();
    float mu = (red[0] + red[1] + red[2] + red[3] + red[4] + red[5] + red[6] + red[7]) * (1.f / 256.f);
    float d = v - mu;
    float s2 = d * d;
#pragma unroll
    for (int o = 16; o; o >>= 1) s2 += __shfl_xor_sync(~0u, s2, o);
    __syncthreads();
    if (lane == 0) red[wrp] = s2;
    __syncthreads();
    float var = (red[0] + red[1] + red[2] + red[3] + red[4] + red[5] + red[6] + red[7]) * (1.f / 256.f);
    g_Xs[(size_t)row * C_ + c] = d * rsqrtf(var + 1e-5f) * lnw[c] + lnb[c];
}

// ================= launch =====================================================
extern "C" void kernel_launch(void* const* d_in, const int* in_sizes, int n_in,
                              void* d_out, int out_size) {
    const float* x        = (const float*)d_in[0];
    const float* x_source = (const float*)d_in[1];
    const float* loc      = (const float*)d_in[2];
    const float* conf     = (const float*)d_in[3];
    const float* Wq       = (const float*)d_in[4];
    const float* Wk       = (const float*)d_in[5];
    const float* Wv       = (const float*)d_in[6];
    const float* sr_w     = (const float*)d_in[7];
    const float* sr_b     = (const float*)d_in[8];
    const float* ln_w     = (const float*)d_in[9];
    const float* ln_b     = (const float*)d_in[10];
    const float* Wp       = (const float*)d_in[11];
    const float* bp       = (const float*)d_in[12];
    float* out = (float*)d_out;

    float *pAcol, *pWc, *pCPart, *pXs, *pQ, *pK, *pV, *pAO;
    cudaGetSymbolAddress((void**)&pAcol, g_Acol);
    cudaGetSymbolAddress((void**)&pWc, g_Wc);
    cudaGetSymbolAddress((void**)&pCPart, g_CPart);
    cudaGetSymbolAddress((void**)&pXs, g_Xs);
    cudaGetSymbolAddress((void**)&pQ, g_Q);
    cudaGetSymbolAddress((void**)&pK, g_K);
    cudaGetSymbolAddress((void**)&pV, g_V);
    cudaGetSymbolAddress((void**)&pAO, g_AO);

    const size_t SM128 = 67584;                               // BN=128 gemm
    const size_t SMATT = (4 * 128 * 36 + 32 * 132 + 128) * 4; // 91136 attention
    cudaFuncSetAttribute((const void*)tf32_gemm<128, 2, 4>,
                         cudaFuncAttributeMaxDynamicSharedMemorySize, (int)SM128);
    cudaFuncSetAttribute((const void*)attn_fused,
                         cudaFuncAttributeMaxDynamicSharedMemorySize, (int)SMATT);

    // token2map
    zero_kernel<<<(B_ * HW_ * C_) / 4 / 256, 256>>>();
    scatter_kernel<<<B_ * N_, 256>>>(x_source, loc);
    normalize_kernel<<<(B_ * HW_ * C_) / 256, 256>>>();
    blur_kernel<<<B_ * HW_, 256>>>();

    // stride-4 conv as GEMM, split-K x8  (M=2048, N=256, K=8x512)
    wperm_kernel<<<(C_ * KCOL_) / 256, 256>>>(sr_w);
    im2col_kernel<<<dim3(B_ * NS_, 16), 256>>>();
    tf32_gemm<128, 2, 4><<<dim3(2, 16, KSPL_), 256, SM128>>>(
        pAcol, KCOL_, 0, KCH_, pWc, KCOL_, 0, KCH_,
        pCPart, C_, 0, (long long)B_ * NS_ * C_,
        KCH_, nullptr, 1.f);
    ln_kernel<<<B_ * NS_, 256>>>(sr_b, ln_w, ln_b);

    // projections q/k/v
    tf32_gemm<128, 2, 4><<<dim3(2, 128, 1), 256, SM128>>>(
        x, C_, 0, 0, Wq, C_, 0, 0, pQ, C_, 0, 0, C_, nullptr, 1.f);
    tf32_gemm<128, 2, 4><<<dim3(2, 16, 1), 256, SM128>>>(
        pXs, C_, 0, 0, Wk, C_, 0, 0, pK, C_, 0, 0, C_, nullptr, 1.f);
    tf32_gemm<128, 2, 4><<<dim3(2, 16, 1), 256, SM128>>>(
        pXs, C_, 0, 0, Wv, C_, 0, 0, pV, C_, 0, 0, C_, nullptr, 1.f);

    // fused attention
    attn_fused<<<dim3(N_ / 128, B_ * HEADS_), 256, SMATT>>>(conf);

    // output projection (+bias)
    tf32_gemm<128, 2, 4><<<dim3(2, 128, 1), 256, SM128>>>(
        pAO, C_, 0, 0, Wp, C_, 0, 0, out, C_, 0, 0, C_, bp, 1.f);
}

// round 5
// speedup vs baseline: 2.3798x; 1.0879x over previous
#include <cuda_runtime.h>
#include <cuda_bf16.h>
#include <cstdint>
#include <math.h>

// Problem constants
#define B_    2
#define N_    8192
#define C_    256
#define HEADS_ 8
#define DH_   32
#define HM_   128
#define HW_   (HM_*HM_)
#define NS_   1024
#define KCOL_ 4096
#define KSPL_ 8
#define KCH_  (KCOL_/KSPL_)   // 512

// ---------------- scratch (device globals) ------------------------------------
__device__ float g_Fmap[B_ * HW_ * C_];
__device__ float g_Cnt [B_ * HW_];
__device__ float g_Xm  [B_ * HW_ * C_];
__device__ float g_Wc  [C_ * KCOL_];              // permuted conv weights
__device__ float g_Wkv [2 * C_ * C_];             // [Wk;Wv]
__device__ float g_CPart[KSPL_ * B_ * NS_ * C_];  // conv split-K partials
__device__ float g_Xs  [B_ * NS_ * C_];
__device__ float g_Q   [B_ * N_ * C_];
__device__ float g_KV  [B_ * NS_ * 2 * C_];       // [row][0:256]=K, [256:512]=V
__device__ float g_AO  [B_ * N_ * C_];

// ================= tf32 mma helpers ===========================================
__device__ __forceinline__ void tf32split(float x, uint32_t& hi, uint32_t& lo) {
    float h, l2;
    asm("cvt.rna.tf32.f32 %0, %1;" : "=f"(h) : "f"(x));
    float l = x - h;
    asm("cvt.rna.tf32.f32 %0, %1;" : "=f"(l2) : "f"(l));
    hi = __float_as_uint(h);
    lo = __float_as_uint(l2);
}
__device__ __forceinline__ uint32_t tf32one(float x) {
    float h;
    asm("cvt.rna.tf32.f32 %0, %1;" : "=f"(h) : "f"(x));
    return __float_as_uint(h);
}
__device__ __forceinline__ void mma8(float* c, const uint32_t* a, const uint32_t* b) {
    asm volatile(
        "mma.sync.aligned.m16n8k8.row.col.f32.tf32.tf32.f32 "
        "{%0,%1,%2,%3}, {%4,%5,%6,%7}, {%8,%9}, {%0,%1,%2,%3};"
        : "+f"(c[0]), "+f"(c[1]), "+f"(c[2]), "+f"(c[3])
        : "r"(a[0]), "r"(a[1]), "r"(a[2]), "r"(a[3]), "r"(b[0]), "r"(b[1]));
}

// implicit-im2col address for conv A: A[m][k] = g_Xm[pixel(m, k>>8)*256 + (k&255)]
__device__ __forceinline__ const float* convA_addr(int m, int k) {
    int b = m >> 10, rr = m & 1023;
    int oy = rr >> 5, ox = rr & 31;
    int kk = k >> 8, ci = k & 255;
    int ky = kk >> 2, kx = kk & 3;
    int pix = (b << 14) + (oy * 4 + ky) * HM_ + ox * 4 + kx;
    return g_Xm + (size_t)pix * 256 + ci;
}

// ================= generic 3xTF32 GEMM ========================================
// C[z] = alpha * A[z][M,K] @ B[z][N,K]^T (+bias).  CONVA: A loads via implicit im2col.
template<int BN, int WARPS_M, int WARPS_N, bool CONVA>
__global__ void __launch_bounds__(256, 1)
tf32_gemm(const float* __restrict__ A, int lda, long long sAb, long long sAh,
          const float* __restrict__ Bw, int ldb, long long sBb, long long sBh,
          float* __restrict__ Cm, int ldc, long long sCb, long long sCh,
          int K, const float* __restrict__ bias, float alpha) {
    constexpr int WM_T = 128 / WARPS_M / 16;
    constexpr int WN_T = BN / WARPS_N / 8;
    constexpr int NB4 = BN / 32;
    constexpr int ES = BN + 4;

    extern __shared__ float smem[];
    float* As = smem;
    float* Bs = smem + 128 * 36;
    float* epi = smem;

    const int t = threadIdx.x, lane = t & 31, warp = t >> 5;
    const int g = lane >> 2, tig = lane & 3;
    const int warpM = warp / WARPS_N, warpN = warp % WARPS_N;
    const int wrb = warpM * WM_T * 16, wcb = warpN * WN_T * 8;

    const int n0 = blockIdx.x * BN;
    const int m0 = blockIdx.y * 128;
    const int z = blockIdx.z, zb = z >> 3, zh = z & 7;
    const float* Ab = A + (long long)zb * sAb + (CONVA ? 0 : (long long)zh * sAh);
    const int kbase = CONVA ? (int)(zh * sAh) : 0;
    const float* Bb = Bw + (long long)zb * sBb + (long long)zh * sBh;
    float* Cb = Cm + (long long)zb * sCb + (long long)zh * sCh;

    const int lr = t >> 3;
    const int lc = (t & 7) * 4;

    float acc[WM_T][WN_T][4];
#pragma unroll
    for (int i = 0; i < WM_T; i++)
#pragma unroll
        for (int j = 0; j < WN_T; j++)
#pragma unroll
            for (int q = 0; q < 4; q++) acc[i][j][q] = 0.f;

    const int nc = K >> 5;
    float4 pa[4], pb[NB4];
#pragma unroll
    for (int i = 0; i < 4; i++) {
        if (CONVA)
            pa[i] = *(const float4*)convA_addr(m0 + lr + i * 32, kbase + lc);
        else
            pa[i] = *(const float4*)(Ab + (size_t)(m0 + lr + i * 32) * lda + lc);
    }
#pragma unroll
    for (int i = 0; i < NB4; i++)
        pb[i] = *(const float4*)(Bb + (size_t)(n0 + lr + i * 32) * ldb + lc);

    for (int c = 0; c < nc; c++) {
        if (c > 0) __syncthreads();
#pragma unroll
        for (int i = 0; i < 4; i++)
            *(float4*)&As[(lr + i * 32) * 36 + lc] = pa[i];
#pragma unroll
        for (int i = 0; i < NB4; i++)
            *(float4*)&Bs[(lr + i * 32) * 36 + lc] = pb[i];
        __syncthreads();
        if (c + 1 < nc) {
            int k0 = (c + 1) << 5;
#pragma unroll
            for (int i = 0; i < 4; i++) {
                if (CONVA)
                    pa[i] = *(const float4*)convA_addr(m0 + lr + i * 32, kbase + k0 + lc);
                else
                    pa[i] = *(const float4*)(Ab + (size_t)(m0 + lr + i * 32) * lda + k0 + lc);
            }
#pragma unroll
            for (int i = 0; i < NB4; i++)
                pb[i] = *(const float4*)(Bb + (size_t)(n0 + lr + i * 32) * ldb + k0 + lc);
        }
#pragma unroll
        for (int ks = 0; ks < 4; ks++) {
            const int k0 = ks * 8;
            uint32_t ah[WM_T][4], al[WM_T][4];
#pragma unroll
            for (int mt = 0; mt < WM_T; mt++) {
                int r0 = wrb + mt * 16;
                tf32split(As[(r0 + g) * 36 + k0 + tig],     ah[mt][0], al[mt][0]);
                tf32split(As[(r0 + 8 + g) * 36 + k0 + tig], ah[mt][1], al[mt][1]);
                tf32split(As[(r0 + g) * 36 + k0 + tig + 4], ah[mt][2], al[mt][2]);
                tf32split(As[(r0 + 8 + g) * 36 + k0 + tig + 4], ah[mt][3], al[mt][3]);
            }
            uint32_t bh[WN_T][2], bl[WN_T][2];
#pragma unroll
            for (int nt = 0; nt < WN_T; nt++) {
                int nr = wcb + nt * 8 + g;
                tf32split(Bs[nr * 36 + k0 + tig],     bh[nt][0], bl[nt][0]);
                tf32split(Bs[nr * 36 + k0 + tig + 4], bh[nt][1], bl[nt][1]);
            }
#pragma unroll
            for (int mt = 0; mt < WM_T; mt++)
#pragma unroll
                for (int nt = 0; nt < WN_T; nt++) {
                    mma8(acc[mt][nt], ah[mt], bh[nt]);
                    mma8(acc[mt][nt], al[mt], bh[nt]);
                    mma8(acc[mt][nt], ah[mt], bl[nt]);
                }
        }
    }
    __syncthreads();
#pragma unroll
    for (int mt = 0; mt < WM_T; mt++)
#pragma unroll
        for (int nt = 0; nt < WN_T; nt++) {
            int r = wrb + mt * 16 + g;
            int cc = wcb + nt * 8 + 2 * tig;
            epi[r * ES + cc] = acc[mt][nt][0];
            epi[r * ES + cc + 1] = acc[mt][nt][1];
            epi[(r + 8) * ES + cc] = acc[mt][nt][2];
            epi[(r + 8) * ES + cc + 1] = acc[mt][nt][3];
        }
    __syncthreads();
    for (int idx = t; idx < 128 * BN; idx += 256) {
        int r = idx / BN, cc = idx % BN;
        float v = epi[r * ES + cc] * alpha;
        if (bias) v += bias[n0 + cc];
        Cb[(size_t)(m0 + r) * ldc + n0 + cc] = v;
    }
}

// ================= fused flash attention (tf32 mma) ===========================
__global__ void __launch_bounds__(256, 1)
attn_fused(const float* __restrict__ conf) {
    extern __shared__ float smem[];
    float* Qh = smem;
    float* Ql = Qh + 128 * 36;
    float* Ksh = Ql + 128 * 36;
    float* Ksl = Ksh + 128 * 36;
    float* Vs = Ksl + 128 * 36;          // [32][132]
    float* confs = Vs + 32 * 132;        // [128]

    const int t = threadIdx.x, lane = t & 31, warp = t >> 5;
    const int g = lane >> 2, tig = lane & 3;
    const int bh = blockIdx.y, b = bh >> 3, h = bh & 7;
    const int m0 = blockIdx.x << 7;
    const int wrb = warp << 4;
    const float scale = 0.17677669529663687f;

    {
        const int lr = t >> 3, lc = (t & 7) * 4;
#pragma unroll
        for (int i = 0; i < 4; i++) {
            int r = lr + i * 32;
            float4 v = *(const float4*)(g_Q + (size_t)(b * N_ + m0 + r) * C_ + h * DH_ + lc);
            float vv[4] = {v.x * scale, v.y * scale, v.z * scale, v.w * scale};
#pragma unroll
            for (int j = 0; j < 4; j++) {
                uint32_t hi, lo;
                tf32split(vv[j], hi, lo);
                Qh[r * 36 + lc + j] = __uint_as_float(hi);
                Ql[r * 36 + lc + j] = __uint_as_float(lo);
            }
        }
    }

    float Oacc[4][4];
#pragma unroll
    for (int i = 0; i < 4; i++)
#pragma unroll
        for (int j = 0; j < 4; j++) Oacc[i][j] = 0.f;
    float l0 = 0.f, l1 = 0.f;

    for (int kc = 0; kc < 8; kc++) {
        const int kb = kc << 7;
        if (kc > 0) __syncthreads();
        {
            const int lr = t >> 3, lc = (t & 7) * 4;
#pragma unroll
            for (int i = 0; i < 4; i++) {
                int r = lr + i * 32;
                float4 v = *(const float4*)(g_KV + (size_t)(b * NS_ + kb + r) * 512 + h * DH_ + lc);
                float vv[4] = {v.x, v.y, v.z, v.w};
#pragma unroll
                for (int j = 0; j < 4; j++) {
                    uint32_t hi, lo;
                    tf32split(vv[j], hi, lo);
                    Ksh[r * 36 + lc + j] = __uint_as_float(hi);
                    Ksl[r * 36 + lc + j] = __uint_as_float(lo);
                }
            }
        }
        for (int idx = t; idx < 128 * 32; idx += 256) {
            int key = idx >> 5, d = idx & 31;
            float v = g_KV[(size_t)(b * NS_ + kb + key) * 512 + 256 + h * DH_ + d];
            Vs[d * 132 + key] = __uint_as_float(tf32one(v));
        }
        if (t < 128) confs[t] = conf[b * NS_ + kb + t];
        __syncthreads();

        float Sacc[16][4];
#pragma unroll
        for (int nt = 0; nt < 16; nt++)
#pragma unroll
            for (int q = 0; q < 4; q++) Sacc[nt][q] = 0.f;

#pragma unroll
        for (int ks = 0; ks < 4; ks++) {
            const int k0 = ks * 8;
            uint32_t ah[4], al[4];
            ah[0] = __float_as_uint(Qh[(wrb + g) * 36 + k0 + tig]);
            ah[1] = __float_as_uint(Qh[(wrb + 8 + g) * 36 + k0 + tig]);
            ah[2] = __float_as_uint(Qh[(wrb + g) * 36 + k0 + tig + 4]);
            ah[3] = __float_as_uint(Qh[(wrb + 8 + g) * 36 + k0 + tig + 4]);
            al[0] = __float_as_uint(Ql[(wrb + g) * 36 + k0 + tig]);
            al[1] = __float_as_uint(Ql[(wrb + 8 + g) * 36 + k0 + tig]);
            al[2] = __float_as_uint(Ql[(wrb + g) * 36 + k0 + tig + 4]);
            al[3] = __float_as_uint(Ql[(wrb + 8 + g) * 36 + k0 + tig + 4]);
#pragma unroll
            for (int nt = 0; nt < 16; nt++) {
                int nr = nt * 8 + g;
                uint32_t bhv[2], blv[2];
                bhv[0] = __float_as_uint(Ksh[nr * 36 + k0 + tig]);
                bhv[1] = __float_as_uint(Ksh[nr * 36 + k0 + tig + 4]);
                blv[0] = __float_as_uint(Ksl[nr * 36 + k0 + tig]);
                blv[1] = __float_as_uint(Ksl[nr * 36 + k0 + tig + 4]);
                mma8(Sacc[nt], ah, bhv);
                mma8(Sacc[nt], al, bhv);
                mma8(Sacc[nt], ah, blv);
            }
        }

        const int srcA = (g << 2) + (tig >> 1);
        const int srcB = srcA + 2;
        const bool odd = (tig & 1);
#pragma unroll
        for (int nt = 0; nt < 16; nt++) {
            float ca = confs[nt * 8 + 2 * tig];
            float cb2 = confs[nt * 8 + 2 * tig + 1];
            float p0 = __expf(Sacc[nt][0] + ca);
            float p1 = __expf(Sacc[nt][1] + cb2);
            float p2 = __expf(Sacc[nt][2] + ca);
            float p3 = __expf(Sacc[nt][3] + cb2);
            l0 += p0 + p1;
            l1 += p2 + p3;

            float s0 = __shfl_sync(~0u, p0, srcA);
            float s1 = __shfl_sync(~0u, p1, srcA);
            float s2 = __shfl_sync(~0u, p2, srcA);
            float s3 = __shfl_sync(~0u, p3, srcA);
            float u0 = __shfl_sync(~0u, p0, srcB);
            float u1 = __shfl_sync(~0u, p1, srcB);
            float u2 = __shfl_sync(~0u, p2, srcB);
            float u3 = __shfl_sync(~0u, p3, srcB);

            uint32_t a[4];
            a[0] = tf32one(odd ? s1 : s0);
            a[1] = tf32one(odd ? s3 : s2);
            a[2] = tf32one(odd ? u1 : u0);
            a[3] = tf32one(odd ? u3 : u2);

#pragma unroll
            for (int dt = 0; dt < 4; dt++) {
                uint32_t bv[2];
                bv[0] = __float_as_uint(Vs[(dt * 8 + g) * 132 + nt * 8 + tig]);
                bv[1] = __float_as_uint(Vs[(dt * 8 + g) * 132 + nt * 8 + tig + 4]);
                mma8(Oacc[dt], a, bv);
            }
        }
    }

    l0 += __shfl_xor_sync(~0u, l0, 1); l0 += __shfl_xor_sync(~0u, l0, 2);
    l1 += __shfl_xor_sync(~0u, l1, 1); l1 += __shfl_xor_sync(~0u, l1, 2);
    float r0inv = 1.f / l0, r1inv = 1.f / l1;

#pragma unroll
    for (int dt = 0; dt < 4; dt++) {
        int cc = h * DH_ + dt * 8 + 2 * tig;
        size_t rowa = (size_t)(b * N_ + m0 + wrb + g) * C_;
        size_t rowb = (size_t)(b * N_ + m0 + wrb + 8 + g) * C_;
        g_AO[rowa + cc]     = Oacc[dt][0] * r0inv;
        g_AO[rowa + cc + 1] = Oacc[dt][1] * r0inv;
        g_AO[rowb + cc]     = Oacc[dt][2] * r1inv;
        g_AO[rowb + cc + 1] = Oacc[dt][3] * r1inv;
    }
}

// ================= preprocessing ==============================================
__global__ void __launch_bounds__(256) zero_kernel() {
    int i = blockIdx.x * 256 + threadIdx.x;
    float4 zf = make_float4(0.f, 0.f, 0.f, 0.f);
    ((float4*)g_Fmap)[i] = zf;
    if (i < (B_ * HW_) / 4) ((float4*)g_Cnt)[i] = zf;
}

__global__ void __launch_bounds__(256) scatter_kernel(const float* __restrict__ xs,
                                                      const float* __restrict__ loc) {
    int token = blockIdx.x;
    int b = token >> 13;
    float lx = loc[(size_t)token * 2 + 0];
    float ly = loc[(size_t)token * 2 + 1];
    lx = fminf(fmaxf(lx, 0.f), 1.f) * 127.f;
    ly = fminf(fmaxf(ly, 0.f), 1.f) * 127.f;
    int ix = (int)rintf(lx);
    int iy = (int)rintf(ly);
    int p = (b << 14) + iy * HM_ + ix;
    int c = threadIdx.x;
    atomicAdd(&g_Fmap[(size_t)p * C_ + c], xs[(size_t)token * C_ + c]);
    if (c == 0) atomicAdd(&g_Cnt[p], 1.0f);
}

// fused normalize + 3x3 gaussian reconstruct.
// grid (4, 128, 8): x-tile(32px), y-row, z = b*4 + channel-group(64ch). block 256.
__global__ void __launch_bounds__(256) blur_fused_kernel() {
    __shared__ float sf[3][34][64];
    __shared__ float minv[3][34];   // (cnt>0)? 1/(cnt+1e-6) : 0
    __shared__ float msk[3][34];    // (cnt>0)? 1 : 0

    const int t = threadIdx.x;
    const int x0 = blockIdx.x << 5;
    const int y = blockIdx.y;
    const int b = blockIdx.z >> 2, cg = blockIdx.z & 3;
    const int cbase = cg << 6;

    // mask/inv loader
    if (t < 102) {
        int r = t / 34, px = t % 34;
        int gy = y + r - 1, gx = x0 + px - 1;
        float inv = 0.f, mk = 0.f;
        if (gy >= 0 && gy < HM_ && gx >= 0 && gx < HM_) {
            float cnt = g_Cnt[(b << 14) + gy * HM_ + gx];
            if (cnt > 0.f) { inv = 1.f / (cnt + 1e-6f); mk = 1.f; }
        }
        minv[r][px] = inv;
        msk[r][px] = mk;
    }
    __syncthreads();

    // feature loader (normalized on the fly)
    for (int idx = t; idx < 3 * 34 * 64; idx += 256) {
        int r = idx / (34 * 64);
        int rem = idx - r * (34 * 64);
        int px = rem >> 6, c = rem & 63;
        int gy = y + r - 1, gx = x0 + px - 1;
        float val = 0.f;
        if (gy >= 0 && gy < HM_ && gx >= 0 && gx < HM_) {
            int pix = (b << 14) + gy * HM_ + gx;
            val = g_Fmap[(size_t)pix * 256 + cbase + c] * minv[r][px];
        }
        sf[r][px][c] = val;
    }
    __syncthreads();

    const float e1 = 0.88249690258459546f;
    const float e2 = 0.77880078307140487f;
    const float nrm = 1.0f / (1.0f + 4.0f * e1 + 4.0f * e2);
    const float wc = nrm, we = e1 * nrm, wo = e2 * nrm;

    const int c = t & 63;
    const int pg = t >> 6;
#pragma unroll
    for (int i = 0; i < 8; i++) {
        int px = pg * 8 + i;        // 0..31 output pixel within tile
        int ps = px + 1;            // smem index of center
        float msum =
            wo * (msk[0][ps - 1] + msk[0][ps + 1] + msk[2][ps - 1] + msk[2][ps + 1]) +
            we * (msk[0][ps] + msk[1][ps - 1] + msk[1][ps + 1] + msk[2][ps]) +
            wc * msk[1][ps];
        float fsum =
            wo * (sf[0][ps - 1][c] + sf[0][ps + 1][c] + sf[2][ps - 1][c] + sf[2][ps + 1][c]) +
            we * (sf[0][ps][c] + sf[1][ps - 1][c] + sf[1][ps + 1][c] + sf[2][ps][c]) +
            wc * sf[1][ps][c];
        float fint = (msum > 0.f) ? fsum / (msum + 1e-6f) : 0.f;
        float fc = sf[1][ps][c];
        float mc = msk[1][ps];
        int cp = (b << 14) + y * HM_ + x0 + px;
        g_Xm[(size_t)cp * 256 + cbase + c] = fc + (1.f - mc) * fint;
    }
}

__global__ void __launch_bounds__(256) wperm_kernel(const float* __restrict__ srw) {
    int idx = blockIdx.x * 256 + threadIdx.x;
    int co = idx >> 12;
    int r = idx & 4095;
    int kk = r >> 8;
    int ci = r & 255;
    g_Wc[idx] = srw[(size_t)co * 4096 + ci * 16 + kk];
}

__global__ void __launch_bounds__(256) wcat_kernel(const float* __restrict__ Wk,
                                                   const float* __restrict__ Wv) {
    int idx = blockIdx.x * 256 + threadIdx.x;    // 512*256
    int row = idx >> 8, c = idx & 255;
    g_Wkv[idx] = (row < 256) ? Wk[row * 256 + c] : Wv[(row - 256) * 256 + c];
}

// LN over C; input = sum of split-K conv partials + sr_b
__global__ void __launch_bounds__(256) ln_kernel(const float* __restrict__ srb,
                                                 const float* __restrict__ lnw,
                                                 const float* __restrict__ lnb) {
    __shared__ float red[8];
    int row = blockIdx.x, c = threadIdx.x;
    int lane = c & 31, wrp = c >> 5;
    float v = srb[c];
#pragma unroll
    for (int s = 0; s < KSPL_; s++)
        v += g_CPart[(size_t)s * (B_ * NS_ * C_) + (size_t)row * C_ + c];
    float s = v;
#pragma unroll
    for (int o = 16; o; o >>= 1) s += __shfl_xor_sync(~0u, s, o);
    if (lane == 0) red[wrp] = s;
    __syncthreads();
    float mu = (red[0] + red[1] + red[2] + red[3] + red[4] + red[5] + red[6] + red[7]) * (1.f / 256.f);
    float d = v - mu;
    float s2 = d * d;
#pragma unroll
    for (int o = 16; o; o >>= 1) s2 += __shfl_xor_sync(~0u, s2, o);
    __syncthreads();
    if (lane == 0) red[wrp] = s2;
    __syncthreads();
    float var = (red[0] + red[1] + red[2] + red[3] + red[4] + red[5] + red[6] + red[7]) * (1.f / 256.f);
    g_Xs[(size_t)row * C_ + c] = d * rsqrtf(var + 1e-5f) * lnw[c] + lnb[c];
}

// ================= launch =====================================================
extern "C" void kernel_launch(void* const* d_in, const int* in_sizes, int n_in,
                              void* d_out, int out_size) {
    const float* x        = (const float*)d_in[0];
    const float* x_source = (const float*)d_in[1];
    const float* loc      = (const float*)d_in[2];
    const float* conf     = (const float*)d_in[3];
    const float* Wq       = (const float*)d_in[4];
    const float* Wk       = (const float*)d_in[5];
    const float* Wv       = (const float*)d_in[6];
    const float* sr_w     = (const float*)d_in[7];
    const float* sr_b     = (const float*)d_in[8];
    const float* ln_w     = (const float*)d_in[9];
    const float* ln_b     = (const float*)d_in[10];
    const float* Wp       = (const float*)d_in[11];
    const float* bp       = (const float*)d_in[12];
    float* out = (float*)d_out;

    float *pWc, *pWkv, *pCPart, *pXs, *pQ, *pKV, *pAO;
    cudaGetSymbolAddress((void**)&pWc, g_Wc);
    cudaGetSymbolAddress((void**)&pWkv, g_Wkv);
    cudaGetSymbolAddress((void**)&pCPart, g_CPart);
    cudaGetSymbolAddress((void**)&pXs, g_Xs);
    cudaGetSymbolAddress((void**)&pQ, g_Q);
    cudaGetSymbolAddress((void**)&pKV, g_KV);
    cudaGetSymbolAddress((void**)&pAO, g_AO);

    const size_t SM128 = 67584;
    const size_t SMATT = (4 * 128 * 36 + 32 * 132 + 128) * 4;   // 91136
    cudaFuncSetAttribute((const void*)tf32_gemm<128, 2, 4, false>,
                         cudaFuncAttributeMaxDynamicSharedMemorySize, (int)SM128);
    cudaFuncSetAttribute((const void*)tf32_gemm<128, 2, 4, true>,
                         cudaFuncAttributeMaxDynamicSharedMemorySize, (int)SM128);
    cudaFuncSetAttribute((const void*)attn_fused,
                         cudaFuncAttributeMaxDynamicSharedMemorySize, (int)SMATT);

    // token2map
    zero_kernel<<<(B_ * HW_ * C_) / 4 / 256, 256>>>();
    scatter_kernel<<<B_ * N_, 256>>>(x_source, loc);
    blur_fused_kernel<<<dim3(4, HM_, B_ * 4), 256>>>();

    // weights prep
    wperm_kernel<<<(C_ * KCOL_) / 256, 256>>>(sr_w);
    wcat_kernel<<<(2 * C_ * C_) / 256, 256>>>(Wk, Wv);

    // stride-4 conv as GEMM with implicit im2col, split-K x8
    tf32_gemm<128, 2, 4, true><<<dim3(2, 16, KSPL_), 256, SM128>>>(
        nullptr, 0, 0, KCH_, pWc, KCOL_, 0, KCH_,
        pCPart, C_, 0, (long long)B_ * NS_ * C_,
        KCH_, nullptr, 1.f);
    ln_kernel<<<B_ * NS_, 256>>>(sr_b, ln_w, ln_b);

    // q projection
    tf32_gemm<128, 2, 4, false><<<dim3(2, 128, 1), 256, SM128>>>(
        x, C_, 0, 0, Wq, C_, 0, 0, pQ, C_, 0, 0, C_, nullptr, 1.f);
    // fused k+v projection -> interleaved KV
    tf32_gemm<128, 2, 4, false><<<dim3(4, 16, 1), 256, SM128>>>(
        pXs, C_, 0, 0, pWkv, C_, 0, 0, pKV, 2 * C_, 0, 0, C_, nullptr, 1.f);

    // fused attention
    attn_fused<<<dim3(N_ / 128, B_ * HEADS_), 256, SMATT>>>(conf);

    // output projection (+bias)
    tf32_gemm<128, 2, 4, false><<<dim3(2, 128, 1), 256, SM128>>>(
        pAO, C_, 0, 0, Wp, C_, 0, 0, out, C_, 0, 0, C_, bp, 1.f);
}

// round 6
// speedup vs baseline: 2.8431x; 1.1947x over previous
#include <cuda_runtime.h>
#include <cuda_bf16.h>
#include <cstdint>
#include <math.h>

// Problem constants
#define B_    2
#define N_    8192
#define C_    256
#define HEADS_ 8
#define DH_   32
#define HM_   128
#define HW_   (HM_*HM_)
#define NS_   1024
#define KCOL_ 4096
#define KSPL_ 8
#define KCH_  (KCOL_/KSPL_)   // 512

// ---------------- scratch (device globals) ------------------------------------
__device__ float g_Fmap[B_ * HW_ * C_];
__device__ float g_Cnt [B_ * HW_];
__device__ float g_Xm  [B_ * HW_ * C_];
__device__ float g_Wc  [C_ * KCOL_];              // permuted conv weights
__device__ float g_Wkv [2 * C_ * C_];             // [Wk;Wv]
__device__ float g_CPart[KSPL_ * B_ * NS_ * C_];  // conv split-K partials
__device__ float g_Xs  [B_ * NS_ * C_];
__device__ float g_Q   [B_ * N_ * C_];
__device__ float g_KV  [B_ * NS_ * 2 * C_];       // [row][0:256]=K, [256:512]=V
__device__ float g_AO  [B_ * N_ * C_];

// ================= tf32 mma helpers ===========================================
__device__ __forceinline__ void tf32split(float x, float& hi, float& lo) {
    float h, l2;
    asm("cvt.rna.tf32.f32 %0, %1;" : "=f"(h) : "f"(x));
    float l = x - h;
    asm("cvt.rna.tf32.f32 %0, %1;" : "=f"(l2) : "f"(l));
    hi = h; lo = l2;
}
__device__ __forceinline__ uint32_t tf32one(float x) {
    float h;
    asm("cvt.rna.tf32.f32 %0, %1;" : "=f"(h) : "f"(x));
    return __float_as_uint(h);
}
__device__ __forceinline__ float tf32onef(float x) {
    float h;
    asm("cvt.rna.tf32.f32 %0, %1;" : "=f"(h) : "f"(x));
    return h;
}
__device__ __forceinline__ void mma8(float* c, const uint32_t* a, const uint32_t* b) {
    asm volatile(
        "mma.sync.aligned.m16n8k8.row.col.f32.tf32.tf32.f32 "
        "{%0,%1,%2,%3}, {%4,%5,%6,%7}, {%8,%9}, {%0,%1,%2,%3};"
        : "+f"(c[0]), "+f"(c[1]), "+f"(c[2]), "+f"(c[3])
        : "r"(a[0]), "r"(a[1]), "r"(a[2]), "r"(a[3]), "r"(b[0]), "r"(b[1]));
}

// implicit-im2col address for conv A: A[m][k] = g_Xm[pixel(m, k>>8)*256 + (k&255)]
__device__ __forceinline__ const float* convA_addr(int m, int k) {
    int b = m >> 10, rr = m & 1023;
    int oy = rr >> 5, ox = rr & 31;
    int kk = k >> 8, ci = k & 255;
    int ky = kk >> 2, kx = kk & 3;
    int pix = (b << 14) + (oy * 4 + ky) * HM_ + ox * 4 + kx;
    return g_Xm + (size_t)pix * 256 + ci;
}

// ================= asymmetric 2xTF32 GEMM =====================================
// C[z] = alpha * A[z][M,K] @ B[z][N,K]^T (+bias).  A exact (hi+lo), B tf32-rounded.
template<int BN, int WARPS_M, int WARPS_N, bool CONVA>
__global__ void __launch_bounds__(256, 1)
tf32_gemm(const float* __restrict__ A, int lda, long long sAb, long long sAh,
          const float* __restrict__ Bw, int ldb, long long sBb, long long sBh,
          float* __restrict__ Cm, int ldc, long long sCb, long long sCh,
          int K, const float* __restrict__ bias, float alpha) {
    constexpr int WM_T = 128 / WARPS_M / 16;
    constexpr int WN_T = BN / WARPS_N / 8;
    constexpr int NB4 = BN / 32;
    constexpr int ES = BN + 4;

    extern __shared__ float smem[];
    float* Ash = smem;                    // [128][36]
    float* Asl = smem + 128 * 36;         // [128][36]
    float* Bsh = smem + 2 * 128 * 36;     // [BN][36]
    float* epi = smem;

    const int t = threadIdx.x, lane = t & 31, warp = t >> 5;
    const int g = lane >> 2, tig = lane & 3;
    const int warpM = warp / WARPS_N, warpN = warp % WARPS_N;
    const int wrb = warpM * WM_T * 16, wcb = warpN * WN_T * 8;

    const int n0 = blockIdx.x * BN;
    const int m0 = blockIdx.y * 128;
    const int z = blockIdx.z, zb = z >> 3, zh = z & 7;
    const float* Ab = A + (long long)zb * sAb + (CONVA ? 0 : (long long)zh * sAh);
    const int kbase = CONVA ? (int)(zh * sAh) : 0;
    const float* Bb = Bw + (long long)zb * sBb + (long long)zh * sBh;
    float* Cb = Cm + (long long)zb * sCb + (long long)zh * sCh;

    const int lr = t >> 3;
    const int lc = (t & 7) * 4;

    float acc[WM_T][WN_T][4];
#pragma unroll
    for (int i = 0; i < WM_T; i++)
#pragma unroll
        for (int j = 0; j < WN_T; j++)
#pragma unroll
            for (int q = 0; q < 4; q++) acc[i][j][q] = 0.f;

    const int nc = K >> 5;
    float4 pa[4], pb[NB4];
#pragma unroll
    for (int i = 0; i < 4; i++) {
        if (CONVA)
            pa[i] = *(const float4*)convA_addr(m0 + lr + i * 32, kbase + lc);
        else
            pa[i] = *(const float4*)(Ab + (size_t)(m0 + lr + i * 32) * lda + lc);
    }
#pragma unroll
    for (int i = 0; i < NB4; i++)
        pb[i] = *(const float4*)(Bb + (size_t)(n0 + lr + i * 32) * ldb + lc);

    for (int c = 0; c < nc; c++) {
        if (c > 0) __syncthreads();
        // split at store time
#pragma unroll
        for (int i = 0; i < 4; i++) {
            float4 h4, l4;
            tf32split(pa[i].x, h4.x, l4.x);
            tf32split(pa[i].y, h4.y, l4.y);
            tf32split(pa[i].z, h4.z, l4.z);
            tf32split(pa[i].w, h4.w, l4.w);
            *(float4*)&Ash[(lr + i * 32) * 36 + lc] = h4;
            *(float4*)&Asl[(lr + i * 32) * 36 + lc] = l4;
        }
#pragma unroll
        for (int i = 0; i < NB4; i++) {
            float4 h4;
            h4.x = tf32onef(pb[i].x); h4.y = tf32onef(pb[i].y);
            h4.z = tf32onef(pb[i].z); h4.w = tf32onef(pb[i].w);
            *(float4*)&Bsh[(lr + i * 32) * 36 + lc] = h4;
        }
        __syncthreads();
        if (c + 1 < nc) {
            int k0 = (c + 1) << 5;
#pragma unroll
            for (int i = 0; i < 4; i++) {
                if (CONVA)
                    pa[i] = *(const float4*)convA_addr(m0 + lr + i * 32, kbase + k0 + lc);
                else
                    pa[i] = *(const float4*)(Ab + (size_t)(m0 + lr + i * 32) * lda + k0 + lc);
            }
#pragma unroll
            for (int i = 0; i < NB4; i++)
                pb[i] = *(const float4*)(Bb + (size_t)(n0 + lr + i * 32) * ldb + k0 + lc);
        }
#pragma unroll
        for (int ks = 0; ks < 4; ks++) {
            const int k0 = ks * 8;
            uint32_t ah[WM_T][4], al[WM_T][4];
#pragma unroll
            for (int mt = 0; mt < WM_T; mt++) {
                int r0 = wrb + mt * 16;
                ah[mt][0] = __float_as_uint(Ash[(r0 + g) * 36 + k0 + tig]);
                ah[mt][1] = __float_as_uint(Ash[(r0 + 8 + g) * 36 + k0 + tig]);
                ah[mt][2] = __float_as_uint(Ash[(r0 + g) * 36 + k0 + tig + 4]);
                ah[mt][3] = __float_as_uint(Ash[(r0 + 8 + g) * 36 + k0 + tig + 4]);
                al[mt][0] = __float_as_uint(Asl[(r0 + g) * 36 + k0 + tig]);
                al[mt][1] = __float_as_uint(Asl[(r0 + 8 + g) * 36 + k0 + tig]);
                al[mt][2] = __float_as_uint(Asl[(r0 + g) * 36 + k0 + tig + 4]);
                al[mt][3] = __float_as_uint(Asl[(r0 + 8 + g) * 36 + k0 + tig + 4]);
            }
            uint32_t bh[WN_T][2];
#pragma unroll
            for (int nt = 0; nt < WN_T; nt++) {
                int nr = wcb + nt * 8 + g;
                bh[nt][0] = __float_as_uint(Bsh[nr * 36 + k0 + tig]);
                bh[nt][1] = __float_as_uint(Bsh[nr * 36 + k0 + tig + 4]);
            }
#pragma unroll
            for (int mt = 0; mt < WM_T; mt++)
#pragma unroll
                for (int nt = 0; nt < WN_T; nt++) {
                    mma8(acc[mt][nt], ah[mt], bh[nt]);
                    mma8(acc[mt][nt], al[mt], bh[nt]);
                }
        }
    }
    __syncthreads();
#pragma unroll
    for (int mt = 0; mt < WM_T; mt++)
#pragma unroll
        for (int nt = 0; nt < WN_T; nt++) {
            int r = wrb + mt * 16 + g;
            int cc = wcb + nt * 8 + 2 * tig;
            epi[r * ES + cc] = acc[mt][nt][0];
            epi[r * ES + cc + 1] = acc[mt][nt][1];
            epi[(r + 8) * ES + cc] = acc[mt][nt][2];
            epi[(r + 8) * ES + cc + 1] = acc[mt][nt][3];
        }
    __syncthreads();
    for (int idx = t; idx < 128 * BN; idx += 256) {
        int r = idx / BN, cc = idx % BN;
        float v = epi[r * ES + cc] * alpha;
        if (bias) v += bias[n0 + cc];
        Cb[(size_t)(m0 + r) * ldc + n0 + cc] = v;
    }
}

// ================= fused flash attention (2xTF32 S, tf32 PV) ==================
__global__ void __launch_bounds__(256, 1)
attn_fused(const float* __restrict__ conf) {
    extern __shared__ float smem[];
    float* Qh = smem;                    // [128][36]
    float* Ql = Qh + 128 * 36;           // [128][36]
    float* Ksh = Ql + 128 * 36;          // [128][36] tf32-rounded K
    float* Vs = Ksh + 128 * 36;          // [32][132]
    float* confs = Vs + 32 * 132;        // [128]

    const int t = threadIdx.x, lane = t & 31, warp = t >> 5;
    const int g = lane >> 2, tig = lane & 3;
    const int bh = blockIdx.y, b = bh >> 3, h = bh & 7;
    const int m0 = blockIdx.x << 7;
    const int wrb = warp << 4;
    const float scale = 0.17677669529663687f;

    {
        const int lr = t >> 3, lc = (t & 7) * 4;
#pragma unroll
        for (int i = 0; i < 4; i++) {
            int r = lr + i * 32;
            float4 v = *(const float4*)(g_Q + (size_t)(b * N_ + m0 + r) * C_ + h * DH_ + lc);
            float vv[4] = {v.x * scale, v.y * scale, v.z * scale, v.w * scale};
#pragma unroll
            for (int j = 0; j < 4; j++) {
                float hi, lo;
                tf32split(vv[j], hi, lo);
                Qh[r * 36 + lc + j] = hi;
                Ql[r * 36 + lc + j] = lo;
            }
        }
    }

    float Oacc[4][4];
#pragma unroll
    for (int i = 0; i < 4; i++)
#pragma unroll
        for (int j = 0; j < 4; j++) Oacc[i][j] = 0.f;
    float l0 = 0.f, l1 = 0.f;

    for (int kc = 0; kc < 8; kc++) {
        const int kb = kc << 7;
        if (kc > 0) __syncthreads();
        {
            const int lr = t >> 3, lc = (t & 7) * 4;
#pragma unroll
            for (int i = 0; i < 4; i++) {
                int r = lr + i * 32;
                float4 v = *(const float4*)(g_KV + (size_t)(b * NS_ + kb + r) * 512 + h * DH_ + lc);
                float4 h4;
                h4.x = tf32onef(v.x); h4.y = tf32onef(v.y);
                h4.z = tf32onef(v.z); h4.w = tf32onef(v.w);
                *(float4*)&Ksh[r * 36 + lc] = h4;
            }
        }
        for (int idx = t; idx < 128 * 32; idx += 256) {
            int key = idx >> 5, d = idx & 31;
            float v = g_KV[(size_t)(b * NS_ + kb + key) * 512 + 256 + h * DH_ + d];
            Vs[d * 132 + key] = __uint_as_float(tf32one(v));
        }
        if (t < 128) confs[t] = conf[b * NS_ + kb + t];
        __syncthreads();

        float Sacc[16][4];
#pragma unroll
        for (int nt = 0; nt < 16; nt++)
#pragma unroll
            for (int q = 0; q < 4; q++) Sacc[nt][q] = 0.f;

#pragma unroll
        for (int ks = 0; ks < 4; ks++) {
            const int k0 = ks * 8;
            uint32_t ah[4], al[4];
            ah[0] = __float_as_uint(Qh[(wrb + g) * 36 + k0 + tig]);
            ah[1] = __float_as_uint(Qh[(wrb + 8 + g) * 36 + k0 + tig]);
            ah[2] = __float_as_uint(Qh[(wrb + g) * 36 + k0 + tig + 4]);
            ah[3] = __float_as_uint(Qh[(wrb + 8 + g) * 36 + k0 + tig + 4]);
            al[0] = __float_as_uint(Ql[(wrb + g) * 36 + k0 + tig]);
            al[1] = __float_as_uint(Ql[(wrb + 8 + g) * 36 + k0 + tig]);
            al[2] = __float_as_uint(Ql[(wrb + g) * 36 + k0 + tig + 4]);
            al[3] = __float_as_uint(Ql[(wrb + 8 + g) * 36 + k0 + tig + 4]);
#pragma unroll
            for (int nt = 0; nt < 16; nt++) {
                int nr = nt * 8 + g;
                uint32_t bhv[2];
                bhv[0] = __float_as_uint(Ksh[nr * 36 + k0 + tig]);
                bhv[1] = __float_as_uint(Ksh[nr * 36 + k0 + tig + 4]);
                mma8(Sacc[nt], ah, bhv);
                mma8(Sacc[nt], al, bhv);
            }
        }

        const int srcA = (g << 2) + (tig >> 1);
        const int srcB = srcA + 2;
        const bool odd = (tig & 1);
#pragma unroll
        for (int nt = 0; nt < 16; nt++) {
            float ca = confs[nt * 8 + 2 * tig];
            float cb2 = confs[nt * 8 + 2 * tig + 1];
            float p0 = __expf(Sacc[nt][0] + ca);
            float p1 = __expf(Sacc[nt][1] + cb2);
            float p2 = __expf(Sacc[nt][2] + ca);
            float p3 = __expf(Sacc[nt][3] + cb2);
            l0 += p0 + p1;
            l1 += p2 + p3;

            float s0 = __shfl_sync(~0u, p0, srcA);
            float s1 = __shfl_sync(~0u, p1, srcA);
            float s2 = __shfl_sync(~0u, p2, srcA);
            float s3 = __shfl_sync(~0u, p3, srcA);
            float u0 = __shfl_sync(~0u, p0, srcB);
            float u1 = __shfl_sync(~0u, p1, srcB);
            float u2 = __shfl_sync(~0u, p2, srcB);
            float u3 = __shfl_sync(~0u, p3, srcB);

            uint32_t a[4];
            a[0] = tf32one(odd ? s1 : s0);
            a[1] = tf32one(odd ? s3 : s2);
            a[2] = tf32one(odd ? u1 : u0);
            a[3] = tf32one(odd ? u3 : u2);

#pragma unroll
            for (int dt = 0; dt < 4; dt++) {
                uint32_t bv[2];
                bv[0] = __float_as_uint(Vs[(dt * 8 + g) * 132 + nt * 8 + tig]);
                bv[1] = __float_as_uint(Vs[(dt * 8 + g) * 132 + nt * 8 + tig + 4]);
                mma8(Oacc[dt], a, bv);
            }
        }
    }

    l0 += __shfl_xor_sync(~0u, l0, 1); l0 += __shfl_xor_sync(~0u, l0, 2);
    l1 += __shfl_xor_sync(~0u, l1, 1); l1 += __shfl_xor_sync(~0u, l1, 2);
    float r0inv = 1.f / l0, r1inv = 1.f / l1;

#pragma unroll
    for (int dt = 0; dt < 4; dt++) {
        int cc = h * DH_ + dt * 8 + 2 * tig;
        size_t rowa = (size_t)(b * N_ + m0 + wrb + g) * C_;
        size_t rowb = (size_t)(b * N_ + m0 + wrb + 8 + g) * C_;
        g_AO[rowa + cc]     = Oacc[dt][0] * r0inv;
        g_AO[rowa + cc + 1] = Oacc[dt][1] * r0inv;
        g_AO[rowb + cc]     = Oacc[dt][2] * r1inv;
        g_AO[rowb + cc + 1] = Oacc[dt][3] * r1inv;
    }
}

// ================= preprocessing ==============================================
__global__ void __launch_bounds__(256) zero_kernel() {
    int i = blockIdx.x * 256 + threadIdx.x;
    float4 zf = make_float4(0.f, 0.f, 0.f, 0.f);
    ((float4*)g_Fmap)[i] = zf;
    if (i < (B_ * HW_) / 4) ((float4*)g_Cnt)[i] = zf;
}

__global__ void __launch_bounds__(256) scatter_kernel(const float* __restrict__ xs,
                                                      const float* __restrict__ loc) {
    int token = blockIdx.x;
    int b = token >> 13;
    float lx = loc[(size_t)token * 2 + 0];
    float ly = loc[(size_t)token * 2 + 1];
    lx = fminf(fmaxf(lx, 0.f), 1.f) * 127.f;
    ly = fminf(fmaxf(ly, 0.f), 1.f) * 127.f;
    int ix = (int)rintf(lx);
    int iy = (int)rintf(ly);
    int p = (b << 14) + iy * HM_ + ix;
    int c = threadIdx.x;
    atomicAdd(&g_Fmap[(size_t)p * C_ + c], xs[(size_t)token * C_ + c]);
    if (c == 0) atomicAdd(&g_Cnt[p], 1.0f);
}

// fused normalize + 3x3 gaussian reconstruct.
__global__ void __launch_bounds__(256) blur_fused_kernel() {
    __shared__ float sf[3][34][64];
    __shared__ float minv[3][34];
    __shared__ float msk[3][34];

    const int t = threadIdx.x;
    const int x0 = blockIdx.x << 5;
    const int y = blockIdx.y;
    const int b = blockIdx.z >> 2, cg = blockIdx.z & 3;
    const int cbase = cg << 6;

    if (t < 102) {
        int r = t / 34, px = t % 34;
        int gy = y + r - 1, gx = x0 + px - 1;
        float inv = 0.f, mk = 0.f;
        if (gy >= 0 && gy < HM_ && gx >= 0 && gx < HM_) {
            float cnt = g_Cnt[(b << 14) + gy * HM_ + gx];
            if (cnt > 0.f) { inv = 1.f / (cnt + 1e-6f); mk = 1.f; }
        }
        minv[r][px] = inv;
        msk[r][px] = mk;
    }
    __syncthreads();

    for (int idx = t; idx < 3 * 34 * 64; idx += 256) {
        int r = idx / (34 * 64);
        int rem = idx - r * (34 * 64);
        int px = rem >> 6, c = rem & 63;
        int gy = y + r - 1, gx = x0 + px - 1;
        float val = 0.f;
        if (gy >= 0 && gy < HM_ && gx >= 0 && gx < HM_) {
            int pix = (b << 14) + gy * HM_ + gx;
            val = g_Fmap[(size_t)pix * 256 + cbase + c] * minv[r][px];
        }
        sf[r][px][c] = val;
    }
    __syncthreads();

    const float e1 = 0.88249690258459546f;
    const float e2 = 0.77880078307140487f;
    const float nrm = 1.0f / (1.0f + 4.0f * e1 + 4.0f * e2);
    const float wc = nrm, we = e1 * nrm, wo = e2 * nrm;

    const int c = t & 63;
    const int pg = t >> 6;
#pragma unroll
    for (int i = 0; i < 8; i++) {
        int px = pg * 8 + i;
        int ps = px + 1;
        float msum =
            wo * (msk[0][ps - 1] + msk[0][ps + 1] + msk[2][ps - 1] + msk[2][ps + 1]) +
            we * (msk[0][ps] + msk[1][ps - 1] + msk[1][ps + 1] + msk[2][ps]) +
            wc * msk[1][ps];
        float fsum =
            wo * (sf[0][ps - 1][c] + sf[0][ps + 1][c] + sf[2][ps - 1][c] + sf[2][ps + 1][c]) +
            we * (sf[0][ps][c] + sf[1][ps - 1][c] + sf[1][ps + 1][c] + sf[2][ps][c]) +
            wc * sf[1][ps][c];
        float fint = (msum > 0.f) ? fsum / (msum + 1e-6f) : 0.f;
        float fc = sf[1][ps][c];
        float mc = msk[1][ps];
        int cp = (b << 14) + y * HM_ + x0 + px;
        g_Xm[(size_t)cp * 256 + cbase + c] = fc + (1.f - mc) * fint;
    }
}

__global__ void __launch_bounds__(256) wperm_kernel(const float* __restrict__ srw) {
    int idx = blockIdx.x * 256 + threadIdx.x;
    int co = idx >> 12;
    int r = idx & 4095;
    int kk = r >> 8;
    int ci = r & 255;
    g_Wc[idx] = srw[(size_t)co * 4096 + ci * 16 + kk];
}

__global__ void __launch_bounds__(256) wcat_kernel(const float* __restrict__ Wk,
                                                   const float* __restrict__ Wv) {
    int idx = blockIdx.x * 256 + threadIdx.x;
    int row = idx >> 8, c = idx & 255;
    g_Wkv[idx] = (row < 256) ? Wk[row * 256 + c] : Wv[(row - 256) * 256 + c];
}

// LN over C; input = sum of split-K conv partials + sr_b
__global__ void __launch_bounds__(256) ln_kernel(const float* __restrict__ srb,
                                                 const float* __restrict__ lnw,
                                                 const float* __restrict__ lnb) {
    __shared__ float red[8];
    int row = blockIdx.x, c = threadIdx.x;
    int lane = c & 31, wrp = c >> 5;
    float v = srb[c];
#pragma unroll
    for (int s = 0; s < KSPL_; s++)
        v += g_CPart[(size_t)s * (B_ * NS_ * C_) + (size_t)row * C_ + c];
    float s = v;
#pragma unroll
    for (int o = 16; o; o >>= 1) s += __shfl_xor_sync(~0u, s, o);
    if (lane == 0) red[wrp] = s;
    __syncthreads();
    float mu = (red[0] + red[1] + red[2] + red[3] + red[4] + red[5] + red[6] + red[7]) * (1.f / 256.f);
    float d = v - mu;
    float s2 = d * d;
#pragma unroll
    for (int o = 16; o; o >>= 1) s2 += __shfl_xor_sync(~0u, s2, o);
    __syncthreads();
    if (lane == 0) red[wrp] = s2;
    __syncthreads();
    float var = (red[0] + red[1] + red[2] + red[3] + red[4] + red[5] + red[6] + red[7]) * (1.f / 256.f);
    g_Xs[(size_t)row * C_ + c] = d * rsqrtf(var + 1e-5f) * lnw[c] + lnb[c];
}

// ================= launch =====================================================
extern "C" void kernel_launch(void* const* d_in, const int* in_sizes, int n_in,
                              void* d_out, int out_size) {
    const float* x        = (const float*)d_in[0];
    const float* x_source = (const float*)d_in[1];
    const float* loc      = (const float*)d_in[2];
    const float* conf     = (const float*)d_in[3];
    const float* Wq       = (const float*)d_in[4];
    const float* Wk       = (const float*)d_in[5];
    const float* Wv       = (const float*)d_in[6];
    const float* sr_w     = (const float*)d_in[7];
    const float* sr_b     = (const float*)d_in[8];
    const float* ln_w     = (const float*)d_in[9];
    const float* ln_b     = (const float*)d_in[10];
    const float* Wp       = (const float*)d_in[11];
    const float* bp       = (const float*)d_in[12];
    float* out = (float*)d_out;

    float *pWc, *pWkv, *pCPart, *pXs, *pQ, *pKV, *pAO;
    cudaGetSymbolAddress((void**)&pWc, g_Wc);
    cudaGetSymbolAddress((void**)&pWkv, g_Wkv);
    cudaGetSymbolAddress((void**)&pCPart, g_CPart);
    cudaGetSymbolAddress((void**)&pXs, g_Xs);
    cudaGetSymbolAddress((void**)&pQ, g_Q);
    cudaGetSymbolAddress((void**)&pKV, g_KV);
    cudaGetSymbolAddress((void**)&pAO, g_AO);

    // smem: gemm = max(3*128*36*4 = 55296, epi 128*132*4 = 67584) = 67584
    //       attn = (3*128*36 + 32*132 + 128)*4 = 72704
    const size_t SM128 = 67584;
    const size_t SMATT = (3 * 128 * 36 + 32 * 132 + 128) * 4;
    cudaFuncSetAttribute((const void*)tf32_gemm<128, 2, 4, false>,
                         cudaFuncAttributeMaxDynamicSharedMemorySize, (int)SM128);
    cudaFuncSetAttribute((const void*)tf32_gemm<128, 2, 4, true>,
                         cudaFuncAttributeMaxDynamicSharedMemorySize, (int)SM128);
    cudaFuncSetAttribute((const void*)attn_fused,
                         cudaFuncAttributeMaxDynamicSharedMemorySize, (int)SMATT);

    // token2map
    zero_kernel<<<(B_ * HW_ * C_) / 4 / 256, 256>>>();
    scatter_kernel<<<B_ * N_, 256>>>(x_source, loc);
    blur_fused_kernel<<<dim3(4, HM_, B_ * 4), 256>>>();

    // weights prep
    wperm_kernel<<<(C_ * KCOL_) / 256, 256>>>(sr_w);
    wcat_kernel<<<(2 * C_ * C_) / 256, 256>>>(Wk, Wv);

    // stride-4 conv as GEMM with implicit im2col, split-K x8
    tf32_gemm<128, 2, 4, true><<<dim3(2, 16, KSPL_), 256, SM128>>>(
        nullptr, 0, 0, KCH_, pWc, KCOL_, 0, KCH_,
        pCPart, C_, 0, (long long)B_ * NS_ * C_,
        KCH_, nullptr, 1.f);
    ln_kernel<<<B_ * NS_, 256>>>(sr_b, ln_w, ln_b);

    // q projection
    tf32_gemm<128, 2, 4, false><<<dim3(2, 128, 1), 256, SM128>>>(
        x, C_, 0, 0, Wq, C_, 0, 0, pQ, C_, 0, 0, C_, nullptr, 1.f);
    // fused k+v projection -> interleaved KV
    tf32_gemm<128, 2, 4, false><<<dim3(4, 16, 1), 256, SM128>>>(
        pXs, C_, 0, 0, pWkv, C_, 0, 0, pKV, 2 * C_, 0, 0, C_, nullptr, 1.f);

    // fused attention
    attn_fused<<<dim3(N_ / 128, B_ * HEADS_), 256, SMATT>>>(conf);

    // output projection (+bias)
    tf32_gemm<128, 2, 4, false><<<dim3(2, 128, 1), 256, SM128>>>(
        pAO, C_, 0, 0, Wp, C_, 0, 0, out, C_, 0, 0, C_, bp, 1.f);
}

// round 7
// speedup vs baseline: 4.3662x; 1.5357x over previous
#include <cuda_runtime.h>
#include <cuda_fp16.h>
#include <cstdint>
#include <math.h>

// Problem constants
#define B_    2
#define N_    8192
#define C_    256
#define HEADS_ 8
#define DH_   32
#define HM_   128
#define HW_   (HM_*HM_)
#define NS_   1024
#define KCOL_ 4096
#define KSPL_ 8
#define KCH_  (KCOL_/KSPL_)   // 512

// ---------------- scratch (device globals) ------------------------------------
__device__ float g_Fmap[B_ * HW_ * C_];
__device__ float g_Cnt [B_ * HW_];
__device__ float g_Xm  [B_ * HW_ * C_];
__device__ float g_Wc  [C_ * KCOL_];              // permuted conv weights
__device__ float g_Wkv [2 * C_ * C_];             // [Wk;Wv]
__device__ float g_CPart[KSPL_ * B_ * NS_ * C_];  // conv split-K partials
__device__ float g_Xs  [B_ * NS_ * C_];
__device__ float g_Q   [B_ * N_ * C_];
__device__ float g_KV  [B_ * NS_ * 2 * C_];       // [row][0:256]=K, [256:512]=V
__device__ float g_AO  [B_ * N_ * C_];

// ================= fp16 mma helpers ===========================================
__device__ __forceinline__ uint32_t pkh2(float a, float b) {   // a -> low (k even), b -> high
    __half2 h = __floats2half2_rn(a, b);
    return *(uint32_t*)&h;
}
__device__ __forceinline__ void f16split(float x, float& hi, float& lo) {
    float h = __half2float(__float2half_rn(x));
    hi = h; lo = x - h;
}
__device__ __forceinline__ void mma16(float* c, const uint32_t* a, const uint32_t* b) {
    asm volatile(
        "mma.sync.aligned.m16n8k16.row.col.f32.f16.f16.f32 "
        "{%0,%1,%2,%3}, {%4,%5,%6,%7}, {%8,%9}, {%0,%1,%2,%3};"
        : "+f"(c[0]), "+f"(c[1]), "+f"(c[2]), "+f"(c[3])
        : "r"(a[0]), "r"(a[1]), "r"(a[2]), "r"(a[3]), "r"(b[0]), "r"(b[1]));
}

// implicit-im2col address for conv A: A[m][k] = g_Xm[pixel(m, k>>8)*256 + (k&255)]
__device__ __forceinline__ const float* convA_addr(int m, int k) {
    int b = m >> 10, rr = m & 1023;
    int oy = rr >> 5, ox = rr & 31;
    int kk = k >> 8, ci = k & 255;
    int ky = kk >> 2, kx = kk & 3;
    int pix = (b << 14) + (oy * 4 + ky) * HM_ + ox * 4 + kx;
    return g_Xm + (size_t)pix * 256 + ci;
}

// ================= asymmetric fp16 GEMM =======================================
// C[z] = alpha * A[z][M,K] @ B[z][N,K]^T (+bias).  A exact (f16 hi+lo), B f16.
// BM=128, BK=32 (2 k16 steps), 8 warps.  Smem word-stride 20 -> conflict-free.
template<int BN, int WARPS_M, int WARPS_N, bool CONVA>
__global__ void __launch_bounds__(256, 1)
f16_gemm(const float* __restrict__ A, int lda, long long sAb, long long sAh,
         const float* __restrict__ Bw, int ldb, long long sBb, long long sBh,
         float* __restrict__ Cm, int ldc, long long sCb, long long sCh,
         int K, const float* __restrict__ bias, float alpha) {
    constexpr int WM_T = 128 / WARPS_M / 16;
    constexpr int WN_T = BN / WARPS_N / 8;
    constexpr int NB4 = BN / 32;
    constexpr int ES = BN + 4;

    extern __shared__ float smem[];
    uint32_t* AshW = (uint32_t*)smem;                // [128][20]
    uint32_t* AslW = AshW + 128 * 20;                // [128][20]
    uint32_t* BshW = AslW + 128 * 20;                // [BN][20]
    float* epi = smem;

    const int t = threadIdx.x, lane = t & 31, warp = t >> 5;
    const int g = lane >> 2, tig = lane & 3;
    const int warpM = warp / WARPS_N, warpN = warp % WARPS_N;
    const int wrb = warpM * WM_T * 16, wcb = warpN * WN_T * 8;

    const int n0 = blockIdx.x * BN;
    const int m0 = blockIdx.y * 128;
    const int z = blockIdx.z, zb = z >> 3, zh = z & 7;
    const float* Ab = A + (long long)zb * sAb + (CONVA ? 0 : (long long)zh * sAh);
    const int kbase = CONVA ? (int)(zh * sAh) : 0;
    const float* Bb = Bw + (long long)zb * sBb + (long long)zh * sBh;
    float* Cb = Cm + (long long)zb * sCb + (long long)zh * sCh;

    const int lr = t >> 3;
    const int lc = (t & 7) * 4;

    float acc[WM_T][WN_T][4];
#pragma unroll
    for (int i = 0; i < WM_T; i++)
#pragma unroll
        for (int j = 0; j < WN_T; j++)
#pragma unroll
            for (int q = 0; q < 4; q++) acc[i][j][q] = 0.f;

    const int nc = K >> 5;
    float4 pa[4], pb[NB4];
#pragma unroll
    for (int i = 0; i < 4; i++) {
        if (CONVA)
            pa[i] = *(const float4*)convA_addr(m0 + lr + i * 32, kbase + lc);
        else
            pa[i] = *(const float4*)(Ab + (size_t)(m0 + lr + i * 32) * lda + lc);
    }
#pragma unroll
    for (int i = 0; i < NB4; i++)
        pb[i] = *(const float4*)(Bb + (size_t)(n0 + lr + i * 32) * ldb + lc);

    for (int c = 0; c < nc; c++) {
        if (c > 0) __syncthreads();
#pragma unroll
        for (int i = 0; i < 4; i++) {
            float h0, l0, h1, l1, h2, l2, h3, l3;
            f16split(pa[i].x, h0, l0); f16split(pa[i].y, h1, l1);
            f16split(pa[i].z, h2, l2); f16split(pa[i].w, h3, l3);
            uint2 hw = make_uint2(pkh2(h0, h1), pkh2(h2, h3));
            uint2 lw = make_uint2(pkh2(l0, l1), pkh2(l2, l3));
            *(uint2*)&AshW[(lr + i * 32) * 20 + (lc >> 1)] = hw;
            *(uint2*)&AslW[(lr + i * 32) * 20 + (lc >> 1)] = lw;
        }
#pragma unroll
        for (int i = 0; i < NB4; i++) {
            uint2 hw = make_uint2(pkh2(pb[i].x, pb[i].y), pkh2(pb[i].z, pb[i].w));
            *(uint2*)&BshW[(lr + i * 32) * 20 + (lc >> 1)] = hw;
        }
        __syncthreads();
        if (c + 1 < nc) {
            int k0 = (c + 1) << 5;
#pragma unroll
            for (int i = 0; i < 4; i++) {
                if (CONVA)
                    pa[i] = *(const float4*)convA_addr(m0 + lr + i * 32, kbase + k0 + lc);
                else
                    pa[i] = *(const float4*)(Ab + (size_t)(m0 + lr + i * 32) * lda + k0 + lc);
            }
#pragma unroll
            for (int i = 0; i < NB4; i++)
                pb[i] = *(const float4*)(Bb + (size_t)(n0 + lr + i * 32) * ldb + k0 + lc);
        }
#pragma unroll
        for (int ks = 0; ks < 2; ks++) {
            const int w0 = ks * 8;
            uint32_t ah[WM_T][4], al[WM_T][4];
#pragma unroll
            for (int mt = 0; mt < WM_T; mt++) {
                int r0 = wrb + mt * 16;
                ah[mt][0] = AshW[(r0 + g) * 20 + w0 + tig];
                ah[mt][1] = AshW[(r0 + 8 + g) * 20 + w0 + tig];
                ah[mt][2] = AshW[(r0 + g) * 20 + w0 + 4 + tig];
                ah[mt][3] = AshW[(r0 + 8 + g) * 20 + w0 + 4 + tig];
                al[mt][0] = AslW[(r0 + g) * 20 + w0 + tig];
                al[mt][1] = AslW[(r0 + 8 + g) * 20 + w0 + tig];
                al[mt][2] = AslW[(r0 + g) * 20 + w0 + 4 + tig];
                al[mt][3] = AslW[(r0 + 8 + g) * 20 + w0 + 4 + tig];
            }
            uint32_t bh[WN_T][2];
#pragma unroll
            for (int nt = 0; nt < WN_T; nt++) {
                int nr = wcb + nt * 8 + g;
                bh[nt][0] = BshW[nr * 20 + w0 + tig];
                bh[nt][1] = BshW[nr * 20 + w0 + 4 + tig];
            }
#pragma unroll
            for (int mt = 0; mt < WM_T; mt++)
#pragma unroll
                for (int nt = 0; nt < WN_T; nt++) {
                    mma16(acc[mt][nt], ah[mt], bh[nt]);
                    mma16(acc[mt][nt], al[mt], bh[nt]);
                }
        }
    }
    __syncthreads();
#pragma unroll
    for (int mt = 0; mt < WM_T; mt++)
#pragma unroll
        for (int nt = 0; nt < WN_T; nt++) {
            int r = wrb + mt * 16 + g;
            int cc = wcb + nt * 8 + 2 * tig;
            epi[r * ES + cc] = acc[mt][nt][0];
            epi[r * ES + cc + 1] = acc[mt][nt][1];
            epi[(r + 8) * ES + cc] = acc[mt][nt][2];
            epi[(r + 8) * ES + cc + 1] = acc[mt][nt][3];
        }
    __syncthreads();
    for (int idx = t; idx < 128 * BN; idx += 256) {
        int r = idx / BN, cc = idx % BN;
        float v = epi[r * ES + cc] * alpha;
        if (bias) v += bias[n0 + cc];
        Cb[(size_t)(m0 + r) * ldc + n0 + cc] = v;
    }
}

// ================= fused flash attention (fp16 mma) ===========================
// grid (64, 16), block 256. 128 queries x one (b,h), 8 key chunks of 128.
__global__ void __launch_bounds__(256, 1)
attn_fused(const float* __restrict__ conf) {
    extern __shared__ float smem[];
    uint32_t* QhW = (uint32_t*)smem;           // [128][20]
    uint32_t* QlW = QhW + 128 * 20;            // [128][20]
    uint32_t* KsW = QlW + 128 * 20;            // [128][20]
    uint32_t* VsW = KsW + 128 * 20;            // [32 d][68] keys packed x2
    float* confs = (float*)(VsW + 32 * 68);    // [128]

    const int t = threadIdx.x, lane = t & 31, warp = t >> 5;
    const int g = lane >> 2, tig = lane & 3;
    const int bh = blockIdx.y, b = bh >> 3, h = bh & 7;
    const int m0 = blockIdx.x << 7;
    const int wrb = warp << 4;
    const float scale = 0.17677669529663687f;

    // Q tile (x scale) -> fp16 hi/lo packed
    {
        const int lr = t >> 3, lc = (t & 7) * 4;
#pragma unroll
        for (int i = 0; i < 4; i++) {
            int r = lr + i * 32;
            float4 v = *(const float4*)(g_Q + (size_t)(b * N_ + m0 + r) * C_ + h * DH_ + lc);
            float h0, l0, h1, l1, h2, l2, h3, l3;
            f16split(v.x * scale, h0, l0); f16split(v.y * scale, h1, l1);
            f16split(v.z * scale, h2, l2); f16split(v.w * scale, h3, l3);
            *(uint2*)&QhW[r * 20 + (lc >> 1)] = make_uint2(pkh2(h0, h1), pkh2(h2, h3));
            *(uint2*)&QlW[r * 20 + (lc >> 1)] = make_uint2(pkh2(l0, l1), pkh2(l2, l3));
        }
    }

    float Oacc[4][4];
#pragma unroll
    for (int i = 0; i < 4; i++)
#pragma unroll
        for (int j = 0; j < 4; j++) Oacc[i][j] = 0.f;
    float l0s = 0.f, l1s = 0.f;

    for (int kc = 0; kc < 8; kc++) {
        const int kb = kc << 7;
        if (kc > 0) __syncthreads();
        // K chunk -> fp16 packed
        {
            const int lr = t >> 3, lc = (t & 7) * 4;
#pragma unroll
            for (int i = 0; i < 4; i++) {
                int r = lr + i * 32;
                float4 v = *(const float4*)(g_KV + (size_t)(b * NS_ + kb + r) * 512 + h * DH_ + lc);
                *(uint2*)&KsW[r * 20 + (lc >> 1)] = make_uint2(pkh2(v.x, v.y), pkh2(v.z, v.w));
            }
        }
        // V chunk transposed: VsW[d][w] = f16x2(V[2w][d], V[2w+1][d])
#pragma unroll
        for (int i = 0; i < 8; i++) {
            int idx = t + i * 256;
            int d = idx & 31, w = idx >> 5;
            float va = g_KV[(size_t)(b * NS_ + kb + 2 * w) * 512 + 256 + h * DH_ + d];
            float vb = g_KV[(size_t)(b * NS_ + kb + 2 * w + 1) * 512 + 256 + h * DH_ + d];
            VsW[d * 68 + w] = pkh2(va, vb);
        }
        if (t < 128) confs[t] = conf[b * NS_ + kb + t];
        __syncthreads();

        // S = Q K^T  (A = f16 hi+lo, B = f16)
        float Sacc[16][4];
#pragma unroll
        for (int nt = 0; nt < 16; nt++)
#pragma unroll
            for (int q = 0; q < 4; q++) Sacc[nt][q] = 0.f;

#pragma unroll
        for (int ks = 0; ks < 2; ks++) {
            const int w0 = ks * 8;
            uint32_t ah[4], al[4];
            ah[0] = QhW[(wrb + g) * 20 + w0 + tig];
            ah[1] = QhW[(wrb + 8 + g) * 20 + w0 + tig];
            ah[2] = QhW[(wrb + g) * 20 + w0 + 4 + tig];
            ah[3] = QhW[(wrb + 8 + g) * 20 + w0 + 4 + tig];
            al[0] = QlW[(wrb + g) * 20 + w0 + tig];
            al[1] = QlW[(wrb + 8 + g) * 20 + w0 + tig];
            al[2] = QlW[(wrb + g) * 20 + w0 + 4 + tig];
            al[3] = QlW[(wrb + 8 + g) * 20 + w0 + 4 + tig];
#pragma unroll
            for (int nt = 0; nt < 16; nt++) {
                int nr = nt * 8 + g;
                uint32_t bv[2];
                bv[0] = KsW[nr * 20 + w0 + tig];
                bv[1] = KsW[nr * 20 + w0 + 4 + tig];
                mma16(Sacc[nt], ah, bv);
                mma16(Sacc[nt], al, bv);
            }
        }

        // exp + row sums + PV.  c-frag pairs ARE the fp16 A-frag -> no shuffles.
#pragma unroll
        for (int j = 0; j < 8; j++) {
            const int nt0 = 2 * j, nt1 = 2 * j + 1;
            float ca0 = confs[nt0 * 8 + 2 * tig],  cb0 = confs[nt0 * 8 + 2 * tig + 1];
            float ca1 = confs[nt1 * 8 + 2 * tig],  cb1 = confs[nt1 * 8 + 2 * tig + 1];
            float p00 = __expf(Sacc[nt0][0] + ca0);
            float p01 = __expf(Sacc[nt0][1] + cb0);
            float p02 = __expf(Sacc[nt0][2] + ca0);
            float p03 = __expf(Sacc[nt0][3] + cb0);
            float p10 = __expf(Sacc[nt1][0] + ca1);
            float p11 = __expf(Sacc[nt1][1] + cb1);
            float p12 = __expf(Sacc[nt1][2] + ca1);
            float p13 = __expf(Sacc[nt1][3] + cb1);
            l0s += p00 + p01 + p10 + p11;
            l1s += p02 + p03 + p12 + p13;

            uint32_t a[4];
            a[0] = pkh2(p00, p01);   // row g,   keys 16j+2tig..+1
            a[1] = pkh2(p02, p03);   // row g+8
            a[2] = pkh2(p10, p11);   // row g,   keys 16j+8+2tig..+1
            a[3] = pkh2(p12, p13);   // row g+8
#pragma unroll
            for (int dt = 0; dt < 4; dt++) {
                uint32_t bv[2];
                bv[0] = VsW[(dt * 8 + g) * 68 + 8 * j + tig];
                bv[1] = VsW[(dt * 8 + g) * 68 + 8 * j + 4 + tig];
                mma16(Oacc[dt], a, bv);
            }
        }
    }

    l0s += __shfl_xor_sync(~0u, l0s, 1); l0s += __shfl_xor_sync(~0u, l0s, 2);
    l1s += __shfl_xor_sync(~0u, l1s, 1); l1s += __shfl_xor_sync(~0u, l1s, 2);
    float r0inv = 1.f / l0s, r1inv = 1.f / l1s;

#pragma unroll
    for (int dt = 0; dt < 4; dt++) {
        int cc = h * DH_ + dt * 8 + 2 * tig;
        size_t rowa = (size_t)(b * N_ + m0 + wrb + g) * C_;
        size_t rowb = (size_t)(b * N_ + m0 + wrb + 8 + g) * C_;
        g_AO[rowa + cc]     = Oacc[dt][0] * r0inv;
        g_AO[rowa + cc + 1] = Oacc[dt][1] * r0inv;
        g_AO[rowb + cc]     = Oacc[dt][2] * r1inv;
        g_AO[rowb + cc + 1] = Oacc[dt][3] * r1inv;
    }
}

// ================= preprocessing ==============================================
__global__ void __launch_bounds__(256) zero_kernel() {
    int i = blockIdx.x * 256 + threadIdx.x;
    float4 zf = make_float4(0.f, 0.f, 0.f, 0.f);
    ((float4*)g_Fmap)[i] = zf;
    if (i < (B_ * HW_) / 4) ((float4*)g_Cnt)[i] = zf;
}

__global__ void __launch_bounds__(256) scatter_kernel(const float* __restrict__ xs,
                                                      const float* __restrict__ loc) {
    int token = blockIdx.x;
    int b = token >> 13;
    float lx = loc[(size_t)token * 2 + 0];
    float ly = loc[(size_t)token * 2 + 1];
    lx = fminf(fmaxf(lx, 0.f), 1.f) * 127.f;
    ly = fminf(fmaxf(ly, 0.f), 1.f) * 127.f;
    int ix = (int)rintf(lx);
    int iy = (int)rintf(ly);
    int p = (b << 14) + iy * HM_ + ix;
    int c = threadIdx.x;
    atomicAdd(&g_Fmap[(size_t)p * C_ + c], xs[(size_t)token * C_ + c]);
    if (c == 0) atomicAdd(&g_Cnt[p], 1.0f);
}

// fused normalize + 3x3 gaussian reconstruct
__global__ void __launch_bounds__(256) blur_fused_kernel() {
    __shared__ float sf[3][34][64];
    __shared__ float minv[3][34];
    __shared__ float msk[3][34];

    const int t = threadIdx.x;
    const int x0 = blockIdx.x << 5;
    const int y = blockIdx.y;
    const int b = blockIdx.z >> 2, cg = blockIdx.z & 3;
    const int cbase = cg << 6;

    if (t < 102) {
        int r = t / 34, px = t % 34;
        int gy = y + r - 1, gx = x0 + px - 1;
        float inv = 0.f, mk = 0.f;
        if (gy >= 0 && gy < HM_ && gx >= 0 && gx < HM_) {
            float cnt = g_Cnt[(b << 14) + gy * HM_ + gx];
            if (cnt > 0.f) { inv = 1.f / (cnt + 1e-6f); mk = 1.f; }
        }
        minv[r][px] = inv;
        msk[r][px] = mk;
    }
    __syncthreads();

    for (int idx = t; idx < 3 * 34 * 64; idx += 256) {
        int r = idx / (34 * 64);
        int rem = idx - r * (34 * 64);
        int px = rem >> 6, c = rem & 63;
        int gy = y + r - 1, gx = x0 + px - 1;
        float val = 0.f;
        if (gy >= 0 && gy < HM_ && gx >= 0 && gx < HM_) {
            int pix = (b << 14) + gy * HM_ + gx;
            val = g_Fmap[(size_t)pix * 256 + cbase + c] * minv[r][px];
        }
        sf[r][px][c] = val;
    }
    __syncthreads();

    const float e1 = 0.88249690258459546f;
    const float e2 = 0.77880078307140487f;
    const float nrm = 1.0f / (1.0f + 4.0f * e1 + 4.0f * e2);
    const float wc = nrm, we = e1 * nrm, wo = e2 * nrm;

    const int c = t & 63;
    const int pg = t >> 6;
#pragma unroll
    for (int i = 0; i < 8; i++) {
        int px = pg * 8 + i;
        int ps = px + 1;
        float msum =
            wo * (msk[0][ps - 1] + msk[0][ps + 1] + msk[2][ps - 1] + msk[2][ps + 1]) +
            we * (msk[0][ps] + msk[1][ps - 1] + msk[1][ps + 1] + msk[2][ps]) +
            wc * msk[1][ps];
        float fsum =
            wo * (sf[0][ps - 1][c] + sf[0][ps + 1][c] + sf[2][ps - 1][c] + sf[2][ps + 1][c]) +
            we * (sf[0][ps][c] + sf[1][ps - 1][c] + sf[1][ps + 1][c] + sf[2][ps][c]) +
            wc * sf[1][ps][c];
        float fint = (msum > 0.f) ? fsum / (msum + 1e-6f) : 0.f;
        float fc = sf[1][ps][c];
        float mc = msk[1][ps];
        int cp = (b << 14) + y * HM_ + x0 + px;
        g_Xm[(size_t)cp * 256 + cbase + c] = fc + (1.f - mc) * fint;
    }
}

__global__ void __launch_bounds__(256) wperm_kernel(const float* __restrict__ srw) {
    int idx = blockIdx.x * 256 + threadIdx.x;
    int co = idx >> 12;
    int r = idx & 4095;
    int kk = r >> 8;
    int ci = r & 255;
    g_Wc[idx] = srw[(size_t)co * 4096 + ci * 16 + kk];
}

__global__ void __launch_bounds__(256) wcat_kernel(const float* __restrict__ Wk,
                                                   const float* __restrict__ Wv) {
    int idx = blockIdx.x * 256 + threadIdx.x;
    int row = idx >> 8, c = idx & 255;
    g_Wkv[idx] = (row < 256) ? Wk[row * 256 + c] : Wv[(row - 256) * 256 + c];
}

// LN over C; input = sum of split-K conv partials + sr_b
__global__ void __launch_bounds__(256) ln_kernel(const float* __restrict__ srb,
                                                 const float* __restrict__ lnw,
                                                 const float* __restrict__ lnb) {
    __shared__ float red[8];
    int row = blockIdx.x, c = threadIdx.x;
    int lane = c & 31, wrp = c >> 5;
    float v = srb[c];
#pragma unroll
    for (int s = 0; s < KSPL_; s++)
        v += g_CPart[(size_t)s * (B_ * NS_ * C_) + (size_t)row * C_ + c];
    float s = v;
#pragma unroll
    for (int o = 16; o; o >>= 1) s += __shfl_xor_sync(~0u, s, o);
    if (lane == 0) red[wrp] = s;
    __syncthreads();
    float mu = (red[0] + red[1] + red[2] + red[3] + red[4] + red[5] + red[6] + red[7]) * (1.f / 256.f);
    float d = v - mu;
    float s2 = d * d;
#pragma unroll
    for (int o = 16; o; o >>= 1) s2 += __shfl_xor_sync(~0u, s2, o);
    __syncthreads();
    if (lane == 0) red[wrp] = s2;
    __syncthreads();
    float var = (red[0] + red[1] + red[2] + red[3] + red[4] + red[5] + red[6] + red[7]) * (1.f / 256.f);
    g_Xs[(size_t)row * C_ + c] = d * rsqrtf(var + 1e-5f) * lnw[c] + lnb[c];
}

// ================= launch =====================================================
extern "C" void kernel_launch(void* const* d_in, const int* in_sizes, int n_in,
                              void* d_out, int out_size) {
    const float* x        = (const float*)d_in[0];
    const float* x_source = (const float*)d_in[1];
    const float* loc      = (const float*)d_in[2];
    const float* conf     = (const float*)d_in[3];
    const float* Wq       = (const float*)d_in[4];
    const float* Wk       = (const float*)d_in[5];
    const float* Wv       = (const float*)d_in[6];
    const float* sr_w     = (const float*)d_in[7];
    const float* sr_b     = (const float*)d_in[8];
    const float* ln_w     = (const float*)d_in[9];
    const float* ln_b     = (const float*)d_in[10];
    const float* Wp       = (const float*)d_in[11];
    const float* bp       = (const float*)d_in[12];
    float* out = (float*)d_out;

    float *pWc, *pWkv, *pCPart, *pXs, *pQ, *pKV, *pAO;
    cudaGetSymbolAddress((void**)&pWc, g_Wc);
    cudaGetSymbolAddress((void**)&pWkv, g_Wkv);
    cudaGetSymbolAddress((void**)&pCPart, g_CPart);
    cudaGetSymbolAddress((void**)&pXs, g_Xs);
    cudaGetSymbolAddress((void**)&pQ, g_Q);
    cudaGetSymbolAddress((void**)&pKV, g_KV);
    cudaGetSymbolAddress((void**)&pAO, g_AO);

    // smem: gemm = max(3*128*20*4 = 30720, epi 128*132*4 = 67584) = 67584
    //       attn = (3*128*20 + 32*68)*4 + 512 = 39936
    const size_t SM128 = 67584;
    const size_t SMATT = (3 * 128 * 20 + 32 * 68) * 4 + 512;
    cudaFuncSetAttribute((const void*)f16_gemm<128, 2, 4, false>,
                         cudaFuncAttributeMaxDynamicSharedMemorySize, (int)SM128);
    cudaFuncSetAttribute((const void*)f16_gemm<128, 2, 4, true>,
                         cudaFuncAttributeMaxDynamicSharedMemorySize, (int)SM128);
    cudaFuncSetAttribute((const void*)attn_fused,
                         cudaFuncAttributeMaxDynamicSharedMemorySize, (int)SMATT);

    // token2map
    zero_kernel<<<(B_ * HW_ * C_) / 4 / 256, 256>>>();
    scatter_kernel<<<B_ * N_, 256>>>(x_source, loc);
    blur_fused_kernel<<<dim3(4, HM_, B_ * 4), 256>>>();

    // weights prep
    wperm_kernel<<<(C_ * KCOL_) / 256, 256>>>(sr_w);
    wcat_kernel<<<(2 * C_ * C_) / 256, 256>>>(Wk, Wv);

    // stride-4 conv as GEMM with implicit im2col, split-K x8
    f16_gemm<128, 2, 4, true><<<dim3(2, 16, KSPL_), 256, SM128>>>(
        nullptr, 0, 0, KCH_, pWc, KCOL_, 0, KCH_,
        pCPart, C_, 0, (long long)B_ * NS_ * C_,
        KCH_, nullptr, 1.f);
    ln_kernel<<<B_ * NS_, 256>>>(sr_b, ln_w, ln_b);

    // q projection
    f16_gemm<128, 2, 4, false><<<dim3(2, 128, 1), 256, SM128>>>(
        x, C_, 0, 0, Wq, C_, 0, 0, pQ, C_, 0, 0, C_, nullptr, 1.f);
    // fused k+v projection -> interleaved KV
    f16_gemm<128, 2, 4, false><<<dim3(4, 16, 1), 256, SM128>>>(
        pXs, C_, 0, 0, pWkv, C_, 0, 0, pKV, 2 * C_, 0, 0, C_, nullptr, 1.f);

    // fused attention
    attn_fused<<<dim3(N_ / 128, B_ * HEADS_), 256, SMATT>>>(conf);

    // output projection (+bias)
    f16_gemm<128, 2, 4, false><<<dim3(2, 128, 1), 256, SM128>>>(
        pAO, C_, 0, 0, Wp, C_, 0, 0, out, C_, 0, 0, C_, bp, 1.f);
}

// round 8
// speedup vs baseline: 4.5741x; 1.0476x over previous
#include <cuda_runtime.h>
#include <cuda_fp16.h>
#include <cstdint>
#include <math.h>

// Problem constants
#define B_    2
#define N_    8192
#define C_    256
#define HEADS_ 8
#define DH_   32
#define HM_   128
#define HW_   (HM_*HM_)
#define NS_   1024
#define KCOL_ 4096
#define KSPL_ 8
#define KCH_  (KCOL_/KSPL_)   // 512

// ---------------- scratch (device globals) ------------------------------------
__device__ float g_Fmap[B_ * HW_ * C_];
__device__ float g_Cnt [B_ * HW_];
__device__ float g_Xm  [B_ * HW_ * C_];
__device__ float g_Wc  [C_ * KCOL_];              // permuted conv weights
__device__ float g_Wkv [2 * C_ * C_];             // [Wk;Wv]
__device__ float g_CPart[KSPL_ * B_ * NS_ * C_];  // conv split-K partials
__device__ float g_Xs  [B_ * NS_ * C_];
__device__ float g_Q   [B_ * N_ * C_];
__device__ float g_KV  [B_ * NS_ * 2 * C_];       // [row][0:256]=K, [256:512]=V
__device__ uint32_t g_KhW[16 * NS_ * 16];         // [bh][key][16 f16x2 words]
__device__ uint32_t g_VtW[16 * 32 * 512];         // [bh][d][512 words]: w=pack(V[2w][d],V[2w+1][d])
__device__ float g_AO  [B_ * N_ * C_];

// ================= fp16 mma helpers ===========================================
__device__ __forceinline__ uint32_t pkh2(float a, float b) {   // a -> low, b -> high
    __half2 h = __floats2half2_rn(a, b);
    return *(uint32_t*)&h;
}
__device__ __forceinline__ void f16split(float x, float& hi, float& lo) {
    float h = __half2float(__float2half_rn(x));
    hi = h; lo = x - h;
}
__device__ __forceinline__ void mma16(float* c, const uint32_t* a, const uint32_t* b) {
    asm volatile(
        "mma.sync.aligned.m16n8k16.row.col.f32.f16.f16.f32 "
        "{%0,%1,%2,%3}, {%4,%5,%6,%7}, {%8,%9}, {%0,%1,%2,%3};"
        : "+f"(c[0]), "+f"(c[1]), "+f"(c[2]), "+f"(c[3])
        : "r"(a[0]), "r"(a[1]), "r"(a[2]), "r"(a[3]), "r"(b[0]), "r"(b[1]));
}

// implicit-im2col address for conv A
__device__ __forceinline__ const float* convA_addr(int m, int k) {
    int b = m >> 10, rr = m & 1023;
    int oy = rr >> 5, ox = rr & 31;
    int kk = k >> 8, ci = k & 255;
    int ky = kk >> 2, kx = kk & 3;
    int pix = (b << 14) + (oy * 4 + ky) * HM_ + ox * 4 + kx;
    return g_Xm + (size_t)pix * 256 + ci;
}

// ================= asymmetric fp16 GEMM body ==================================
// C[m0.., n0..] += A[M,K] @ B[N,K]^T (+bias). A exact (f16 hi+lo), B f16.
template<int BN, int WARPS_M, int WARPS_N, bool CONVA>
__device__ __forceinline__ void gemm_body(
        const float* __restrict__ A, int lda, int kbase,
        const float* __restrict__ Bw, int ldb,
        float* __restrict__ Cb, int ldc,
        int K, const float* __restrict__ bias, int n0, int m0) {
    constexpr int WM_T = 128 / WARPS_M / 16;
    constexpr int WN_T = BN / WARPS_N / 8;
    constexpr int NB4 = BN / 32;
    constexpr int ES = BN + 4;

    extern __shared__ float smem[];
    uint32_t* AshW = (uint32_t*)smem;                // [128][20]
    uint32_t* AslW = AshW + 128 * 20;
    uint32_t* BshW = AslW + 128 * 20;                // [BN][20]
    float* epi = smem;

    const int t = threadIdx.x, lane = t & 31, warp = t >> 5;
    const int g = lane >> 2, tig = lane & 3;
    const int warpM = warp / WARPS_N, warpN = warp % WARPS_N;
    const int wrb = warpM * WM_T * 16, wcb = warpN * WN_T * 8;

    const int lr = t >> 3;
    const int lc = (t & 7) * 4;

    float acc[WM_T][WN_T][4];
#pragma unroll
    for (int i = 0; i < WM_T; i++)
#pragma unroll
        for (int j = 0; j < WN_T; j++)
#pragma unroll
            for (int q = 0; q < 4; q++) acc[i][j][q] = 0.f;

    const int nc = K >> 5;
    float4 pa[4], pb[NB4];
#pragma unroll
    for (int i = 0; i < 4; i++) {
        if (CONVA)
            pa[i] = *(const float4*)convA_addr(m0 + lr + i * 32, kbase + lc);
        else
            pa[i] = *(const float4*)(A + (size_t)(m0 + lr + i * 32) * lda + lc);
    }
#pragma unroll
    for (int i = 0; i < NB4; i++)
        pb[i] = *(const float4*)(Bw + (size_t)(n0 + lr + i * 32) * ldb + kbase + lc);

    for (int c = 0; c < nc; c++) {
        if (c > 0) __syncthreads();
#pragma unroll
        for (int i = 0; i < 4; i++) {
            float h0, l0, h1, l1, h2, l2, h3, l3;
            f16split(pa[i].x, h0, l0); f16split(pa[i].y, h1, l1);
            f16split(pa[i].z, h2, l2); f16split(pa[i].w, h3, l3);
            *(uint2*)&AshW[(lr + i * 32) * 20 + (lc >> 1)] = make_uint2(pkh2(h0, h1), pkh2(h2, h3));
            *(uint2*)&AslW[(lr + i * 32) * 20 + (lc >> 1)] = make_uint2(pkh2(l0, l1), pkh2(l2, l3));
        }
#pragma unroll
        for (int i = 0; i < NB4; i++)
            *(uint2*)&BshW[(lr + i * 32) * 20 + (lc >> 1)] =
                make_uint2(pkh2(pb[i].x, pb[i].y), pkh2(pb[i].z, pb[i].w));
        __syncthreads();
        if (c + 1 < nc) {
            int k0 = (c + 1) << 5;
#pragma unroll
            for (int i = 0; i < 4; i++) {
                if (CONVA)
                    pa[i] = *(const float4*)convA_addr(m0 + lr + i * 32, kbase + k0 + lc);
                else
                    pa[i] = *(const float4*)(A + (size_t)(m0 + lr + i * 32) * lda + k0 + lc);
            }
#pragma unroll
            for (int i = 0; i < NB4; i++)
                pb[i] = *(const float4*)(Bw + (size_t)(n0 + lr + i * 32) * ldb + kbase + k0 + lc);
        }
#pragma unroll
        for (int ks = 0; ks < 2; ks++) {
            const int w0 = ks * 8;
            uint32_t ah[WM_T][4], al[WM_T][4];
#pragma unroll
            for (int mt = 0; mt < WM_T; mt++) {
                int r0 = wrb + mt * 16;
                ah[mt][0] = AshW[(r0 + g) * 20 + w0 + tig];
                ah[mt][1] = AshW[(r0 + 8 + g) * 20 + w0 + tig];
                ah[mt][2] = AshW[(r0 + g) * 20 + w0 + 4 + tig];
                ah[mt][3] = AshW[(r0 + 8 + g) * 20 + w0 + 4 + tig];
                al[mt][0] = AslW[(r0 + g) * 20 + w0 + tig];
                al[mt][1] = AslW[(r0 + 8 + g) * 20 + w0 + tig];
                al[mt][2] = AslW[(r0 + g) * 20 + w0 + 4 + tig];
                al[mt][3] = AslW[(r0 + 8 + g) * 20 + w0 + 4 + tig];
            }
            uint32_t bh[WN_T][2];
#pragma unroll
            for (int nt = 0; nt < WN_T; nt++) {
                int nr = wcb + nt * 8 + g;
                bh[nt][0] = BshW[nr * 20 + w0 + tig];
                bh[nt][1] = BshW[nr * 20 + w0 + 4 + tig];
            }
#pragma unroll
            for (int mt = 0; mt < WM_T; mt++)
#pragma unroll
                for (int nt = 0; nt < WN_T; nt++) {
                    mma16(acc[mt][nt], ah[mt], bh[nt]);
                    mma16(acc[mt][nt], al[mt], bh[nt]);
                }
        }
    }
    __syncthreads();
#pragma unroll
    for (int mt = 0; mt < WM_T; mt++)
#pragma unroll
        for (int nt = 0; nt < WN_T; nt++) {
            int r = wrb + mt * 16 + g;
            int cc = wcb + nt * 8 + 2 * tig;
            epi[r * ES + cc] = acc[mt][nt][0];
            epi[r * ES + cc + 1] = acc[mt][nt][1];
            epi[(r + 8) * ES + cc] = acc[mt][nt][2];
            epi[(r + 8) * ES + cc + 1] = acc[mt][nt][3];
        }
    __syncthreads();
    for (int idx = t; idx < 128 * BN; idx += 256) {
        int r = idx / BN, cc = idx % BN;
        float v = epi[r * ES + cc];
        if (bias) v += bias[n0 + cc];
        Cb[(size_t)(m0 + r) * ldc + n0 + cc] = v;
    }
}

// ---- merged conv(split-K x8) + q-projection launch ----------------------------
// grid (2, 144, 8): y<16 -> conv m-tile y, split z; y>=16 -> qproj m-tile y-16 (z==0 only)
__global__ void __launch_bounds__(256, 1)
conv_q_kernel(const float* __restrict__ x, const float* __restrict__ Wq) {
    if (blockIdx.y < 16) {
        int zh = blockIdx.z;
        gemm_body<128, 2, 4, true>(
            nullptr, 0, zh * KCH_, g_Wc, KCOL_,
            g_CPart + (size_t)zh * (B_ * NS_ * C_), C_,
            KCH_, nullptr, blockIdx.x * 128, blockIdx.y * 128);
    } else {
        if (blockIdx.z) return;
        gemm_body<128, 2, 4, false>(
            x, C_, 0, Wq, C_, g_Q, C_,
            C_, nullptr, blockIdx.x * 128, (blockIdx.y - 16) * 128);
    }
}

// ---- plain GEMM launches ------------------------------------------------------
__global__ void __launch_bounds__(256, 1)
gemm_kernel(const float* __restrict__ A, int lda,
            const float* __restrict__ Bw, int ldb,
            float* __restrict__ Cm, int ldc,
            int K, const float* __restrict__ bias) {
    gemm_body<128, 2, 4, false>(A, lda, 0, Bw, ldb, Cm, ldc, K, bias,
                                blockIdx.x * 128, blockIdx.y * 128);
}

// ---- pack K (fragment words) and V^T once per (b,h) ---------------------------
// grid (16 bh, 16 key-groups of 64), block 256
__global__ void __launch_bounds__(256) kvpack_kernel() {
    __shared__ float vsm[64][33];
    const int bh = blockIdx.x, b = bh >> 3, h = bh & 7;
    const int key0 = blockIdx.y << 6;
    const int t = threadIdx.x;
    // K: pack pairs of d into f16x2 words
#pragma unroll
    for (int u = t; u < 1024; u += 256) {
        int key = u >> 4, w = u & 15;
        const float* src = g_KV + (size_t)(b * NS_ + key0 + key) * 512 + h * 32 + 2 * w;
        g_KhW[(size_t)(bh * NS_ + key0 + key) * 16 + w] = pkh2(src[0], src[1]);
    }
    // V rows to smem
#pragma unroll
    for (int u = t; u < 2048; u += 256) {
        int key = u >> 5, d = u & 31;
        vsm[key][d] = g_KV[(size_t)(b * NS_ + key0 + key) * 512 + 256 + h * 32 + d];
    }
    __syncthreads();
    // V^T words: w = pack(V[2w][d], V[2w+1][d])
#pragma unroll
    for (int u = t; u < 1024; u += 256) {
        int d = u >> 5, wl = u & 31;
        g_VtW[(size_t)(bh * 32 + d) * 512 + blockIdx.y * 32 + wl] =
            pkh2(vsm[2 * wl][d], vsm[2 * wl + 1][d]);
    }
}

// ================= fused flash attention (fp16 mma, packed KV) ================
__global__ void __launch_bounds__(256, 1)
attn_fused(const float* __restrict__ conf) {
    extern __shared__ float smem[];
    uint32_t* QhW = (uint32_t*)smem;           // [128][20]
    uint32_t* QlW = QhW + 128 * 20;
    uint32_t* KsW = QlW + 128 * 20;            // [128][20]
    uint32_t* VsW = KsW + 128 * 20;            // [32][68]
    float* confs = (float*)(VsW + 32 * 68);    // [128]

    const int t = threadIdx.x, lane = t & 31, warp = t >> 5;
    const int g = lane >> 2, tig = lane & 3;
    const int bh = blockIdx.y, b = bh >> 3, h = bh & 7;
    const int m0 = blockIdx.x << 7;
    const int wrb = warp << 4;
    const float scale = 0.17677669529663687f;

    // Q tile (x scale) -> fp16 hi/lo packed
    {
        const int lr = t >> 3, lc = (t & 7) * 4;
#pragma unroll
        for (int i = 0; i < 4; i++) {
            int r = lr + i * 32;
            float4 v = *(const float4*)(g_Q + (size_t)(b * N_ + m0 + r) * C_ + h * DH_ + lc);
            float h0, l0, h1, l1, h2, l2, h3, l3;
            f16split(v.x * scale, h0, l0); f16split(v.y * scale, h1, l1);
            f16split(v.z * scale, h2, l2); f16split(v.w * scale, h3, l3);
            *(uint2*)&QhW[r * 20 + (lc >> 1)] = make_uint2(pkh2(h0, h1), pkh2(h2, h3));
            *(uint2*)&QlW[r * 20 + (lc >> 1)] = make_uint2(pkh2(l0, l1), pkh2(l2, l3));
        }
    }

    float Oacc[4][4];
#pragma unroll
    for (int i = 0; i < 4; i++)
#pragma unroll
        for (int j = 0; j < 4; j++) Oacc[i][j] = 0.f;
    float l0s = 0.f, l1s = 0.f;

    const uint4* KhG = (const uint4*)g_KhW;
    const uint4* VtG = (const uint4*)g_VtW;

    for (int kc = 0; kc < 8; kc++) {
        const int kb = kc << 7;
        if (kc > 0) __syncthreads();
        // K fragments: 128 keys x 4 uint4
#pragma unroll
        for (int i = 0; i < 2; i++) {
            int u = t + i * 256;
            int r = u >> 2, j = u & 3;
            *(uint4*)&KsW[r * 20 + 4 * j] = KhG[(size_t)(bh * NS_ + kb + r) * 4 + j];
        }
        // V^T chunk: 32 d x 16 uint4
#pragma unroll
        for (int i = 0; i < 2; i++) {
            int u = t + i * 256;
            int d = u >> 4, j = u & 15;
            *(uint4*)&VsW[d * 68 + 4 * j] = VtG[(size_t)(bh * 32 + d) * 128 + kc * 16 + j];
        }
        if (t < 128) confs[t] = conf[b * NS_ + kb + t];
        __syncthreads();

        // S = Q K^T  (A = f16 hi+lo, B = f16)
        float Sacc[16][4];
#pragma unroll
        for (int nt = 0; nt < 16; nt++)
#pragma unroll
            for (int q = 0; q < 4; q++) Sacc[nt][q] = 0.f;

#pragma unroll
        for (int ks = 0; ks < 2; ks++) {
            const int w0 = ks * 8;
            uint32_t ah[4], al[4];
            ah[0] = QhW[(wrb + g) * 20 + w0 + tig];
            ah[1] = QhW[(wrb + 8 + g) * 20 + w0 + tig];
            ah[2] = QhW[(wrb + g) * 20 + w0 + 4 + tig];
            ah[3] = QhW[(wrb + 8 + g) * 20 + w0 + 4 + tig];
            al[0] = QlW[(wrb + g) * 20 + w0 + tig];
            al[1] = QlW[(wrb + 8 + g) * 20 + w0 + tig];
            al[2] = QlW[(wrb + g) * 20 + w0 + 4 + tig];
            al[3] = QlW[(wrb + 8 + g) * 20 + w0 + 4 + tig];
#pragma unroll
            for (int nt = 0; nt < 16; nt++) {
                int nr = nt * 8 + g;
                uint32_t bv[2];
                bv[0] = KsW[nr * 20 + w0 + tig];
                bv[1] = KsW[nr * 20 + w0 + 4 + tig];
                mma16(Sacc[nt], ah, bv);
                mma16(Sacc[nt], al, bv);
            }
        }

        // exp + row sums + PV (c-frag pairs are the fp16 A-frag)
#pragma unroll
        for (int j = 0; j < 8; j++) {
            const int nt0 = 2 * j, nt1 = 2 * j + 1;
            float ca0 = confs[nt0 * 8 + 2 * tig],  cb0 = confs[nt0 * 8 + 2 * tig + 1];
            float ca1 = confs[nt1 * 8 + 2 * tig],  cb1 = confs[nt1 * 8 + 2 * tig + 1];
            float p00 = __expf(Sacc[nt0][0] + ca0);
            float p01 = __expf(Sacc[nt0][1] + cb0);
            float p02 = __expf(Sacc[nt0][2] + ca0);
            float p03 = __expf(Sacc[nt0][3] + cb0);
            float p10 = __expf(Sacc[nt1][0] + ca1);
            float p11 = __expf(Sacc[nt1][1] + cb1);
            float p12 = __expf(Sacc[nt1][2] + ca1);
            float p13 = __expf(Sacc[nt1][3] + cb1);
            l0s += p00 + p01 + p10 + p11;
            l1s += p02 + p03 + p12 + p13;

            uint32_t a[4];
            a[0] = pkh2(p00, p01);
            a[1] = pkh2(p02, p03);
            a[2] = pkh2(p10, p11);
            a[3] = pkh2(p12, p13);
#pragma unroll
            for (int dt = 0; dt < 4; dt++) {
                uint32_t bv[2];
                bv[0] = VsW[(dt * 8 + g) * 68 + 8 * j + tig];
                bv[1] = VsW[(dt * 8 + g) * 68 + 8 * j + 4 + tig];
                mma16(Oacc[dt], a, bv);
            }
        }
    }

    l0s += __shfl_xor_sync(~0u, l0s, 1); l0s += __shfl_xor_sync(~0u, l0s, 2);
    l1s += __shfl_xor_sync(~0u, l1s, 1); l1s += __shfl_xor_sync(~0u, l1s, 2);
    float r0inv = 1.f / l0s, r1inv = 1.f / l1s;

#pragma unroll
    for (int dt = 0; dt < 4; dt++) {
        int cc = h * DH_ + dt * 8 + 2 * tig;
        size_t rowa = (size_t)(b * N_ + m0 + wrb + g) * C_;
        size_t rowb = (size_t)(b * N_ + m0 + wrb + 8 + g) * C_;
        g_AO[rowa + cc]     = Oacc[dt][0] * r0inv;
        g_AO[rowa + cc + 1] = Oacc[dt][1] * r0inv;
        g_AO[rowb + cc]     = Oacc[dt][2] * r1inv;
        g_AO[rowb + cc + 1] = Oacc[dt][3] * r1inv;
    }
}

// ================= preprocessing ==============================================
// 8 tokens per block
__global__ void __launch_bounds__(256) scatter_kernel(const float* __restrict__ xs,
                                                      const float* __restrict__ loc) {
    const int tok0 = blockIdx.x << 3;
    const int c = threadIdx.x;
    int p[8];
#pragma unroll
    for (int i = 0; i < 8; i++) {
        int token = tok0 + i;
        int b = token >> 13;
        float lx = loc[(size_t)token * 2 + 0];
        float ly = loc[(size_t)token * 2 + 1];
        lx = fminf(fmaxf(lx, 0.f), 1.f) * 127.f;
        ly = fminf(fmaxf(ly, 0.f), 1.f) * 127.f;
        p[i] = (b << 14) + (int)rintf(ly) * HM_ + (int)rintf(lx);
    }
#pragma unroll
    for (int i = 0; i < 8; i++) {
        atomicAdd(&g_Fmap[(size_t)p[i] * C_ + c], xs[(size_t)(tok0 + i) * C_ + c]);
        if (c == 0) atomicAdd(&g_Cnt[p[i]], 1.0f);
    }
}

// fused normalize + 3x3 gaussian reconstruct
__global__ void __launch_bounds__(256) blur_fused_kernel() {
    __shared__ float sf[3][34][64];
    __shared__ float minv[3][34];
    __shared__ float msk[3][34];

    const int t = threadIdx.x;
    const int x0 = blockIdx.x << 5;
    const int y = blockIdx.y;
    const int b = blockIdx.z >> 2, cg = blockIdx.z & 3;
    const int cbase = cg << 6;

    if (t < 102) {
        int r = t / 34, px = t % 34;
        int gy = y + r - 1, gx = x0 + px - 1;
        float inv = 0.f, mk = 0.f;
        if (gy >= 0 && gy < HM_ && gx >= 0 && gx < HM_) {
            float cnt = g_Cnt[(b << 14) + gy * HM_ + gx];
            if (cnt > 0.f) { inv = 1.f / (cnt + 1e-6f); mk = 1.f; }
        }
        minv[r][px] = inv;
        msk[r][px] = mk;
    }
    __syncthreads();

    for (int idx = t; idx < 3 * 34 * 64; idx += 256) {
        int r = idx / (34 * 64);
        int rem = idx - r * (34 * 64);
        int px = rem >> 6, c = rem & 63;
        int gy = y + r - 1, gx = x0 + px - 1;
        float val = 0.f;
        if (gy >= 0 && gy < HM_ && gx >= 0 && gx < HM_) {
            int pix = (b << 14) + gy * HM_ + gx;
            val = g_Fmap[(size_t)pix * 256 + cbase + c] * minv[r][px];
        }
        sf[r][px][c] = val;
    }
    __syncthreads();

    const float e1 = 0.88249690258459546f;
    const float e2 = 0.77880078307140487f;
    const float nrm = 1.0f / (1.0f + 4.0f * e1 + 4.0f * e2);
    const float wc = nrm, we = e1 * nrm, wo = e2 * nrm;

    const int c = t & 63;
    const int pg = t >> 6;
#pragma unroll
    for (int i = 0; i < 8; i++) {
        int px = pg * 8 + i;
        int ps = px + 1;
        float msum =
            wo * (msk[0][ps - 1] + msk[0][ps + 1] + msk[2][ps - 1] + msk[2][ps + 1]) +
            we * (msk[0][ps] + msk[1][ps - 1] + msk[1][ps + 1] + msk[2][ps]) +
            wc * msk[1][ps];
        float fsum =
            wo * (sf[0][ps - 1][c] + sf[0][ps + 1][c] + sf[2][ps - 1][c] + sf[2][ps + 1][c]) +
            we * (sf[0][ps][c] + sf[1][ps - 1][c] + sf[1][ps + 1][c] + sf[2][ps][c]) +
            wc * sf[1][ps][c];
        float fint = (msum > 0.f) ? fsum / (msum + 1e-6f) : 0.f;
        float fc = sf[1][ps][c];
        float mc = msk[1][ps];
        int cp = (b << 14) + y * HM_ + x0 + px;
        g_Xm[(size_t)cp * 256 + cbase + c] = fc + (1.f - mc) * fint;
    }
}

// merged weight prep: blocks [0,4096) wperm, [4096,4608) wcat
__global__ void __launch_bounds__(256) wprep_kernel(const float* __restrict__ srw,
                                                    const float* __restrict__ Wk,
                                                    const float* __restrict__ Wv) {
    int blk = blockIdx.x;
    if (blk < 4096) {
        int idx = blk * 256 + threadIdx.x;
        int co = idx >> 12;
        int r = idx & 4095;
        int kk = r >> 8;
        int ci = r & 255;
        g_Wc[idx] = srw[(size_t)co * 4096 + ci * 16 + kk];
    } else {
        int idx = (blk - 4096) * 256 + threadIdx.x;
        int row = idx >> 8, c = idx & 255;
        g_Wkv[idx] = (row < 256) ? Wk[row * 256 + c] : Wv[(row - 256) * 256 + c];
    }
}

// LN over C; input = sum of split-K conv partials + sr_b
__global__ void __launch_bounds__(256) ln_kernel(const float* __restrict__ srb,
                                                 const float* __restrict__ lnw,
                                                 const float* __restrict__ lnb) {
    __shared__ float red[8];
    int row = blockIdx.x, c = threadIdx.x;
    int lane = c & 31, wrp = c >> 5;
    float v = srb[c];
#pragma unroll
    for (int s = 0; s < KSPL_; s++)
        v += g_CPart[(size_t)s * (B_ * NS_ * C_) + (size_t)row * C_ + c];
    float s = v;
#pragma unroll
    for (int o = 16; o; o >>= 1) s += __shfl_xor_sync(~0u, s, o);
    if (lane == 0) red[wrp] = s;
    __syncthreads();
    float mu = (red[0] + red[1] + red[2] + red[3] + red[4] + red[5] + red[6] + red[7]) * (1.f / 256.f);
    float d = v - mu;
    float s2 = d * d;
#pragma unroll
    for (int o = 16; o; o >>= 1) s2 += __shfl_xor_sync(~0u, s2, o);
    __syncthreads();
    if (lane == 0) red[wrp] = s2;
    __syncthreads();
    float var = (red[0] + red[1] + red[2] + red[3] + red[4] + red[5] + red[6] + red[7]) * (1.f / 256.f);
    g_Xs[(size_t)row * C_ + c] = d * rsqrtf(var + 1e-5f) * lnw[c] + lnb[c];
}

// ================= launch =====================================================
extern "C" void kernel_launch(void* const* d_in, const int* in_sizes, int n_in,
                              void* d_out, int out_size) {
    const float* x        = (const float*)d_in[0];
    const float* x_source = (const float*)d_in[1];
    const float* loc      = (const float*)d_in[2];
    const float* conf     = (const float*)d_in[3];
    const float* Wq       = (const float*)d_in[4];
    const float* Wk       = (const float*)d_in[5];
    const float* Wv       = (const float*)d_in[6];
    const float* sr_w     = (const float*)d_in[7];
    const float* sr_b     = (const float*)d_in[8];
    const float* ln_w     = (const float*)d_in[9];
    const float* ln_b     = (const float*)d_in[10];
    const float* Wp       = (const float*)d_in[11];
    const float* bp       = (const float*)d_in[12];
    float* out = (float*)d_out;

    float *pFmap, *pCnt, *pWkv, *pXs, *pAO;
    cudaGetSymbolAddress((void**)&pFmap, g_Fmap);
    cudaGetSymbolAddress((void**)&pCnt, g_Cnt);
    cudaGetSymbolAddress((void**)&pWkv, g_Wkv);
    cudaGetSymbolAddress((void**)&pXs, g_Xs);
    cudaGetSymbolAddress((void**)&pAO, g_AO);
    float *pKV; cudaGetSymbolAddress((void**)&pKV, g_KV);

    const size_t SM128 = 67584;
    const size_t SMATT = (3 * 128 * 20 + 32 * 68) * 4 + 512;
    cudaFuncSetAttribute((const void*)conv_q_kernel,
                         cudaFuncAttributeMaxDynamicSharedMemorySize, (int)SM128);
    cudaFuncSetAttribute((const void*)gemm_kernel,
                         cudaFuncAttributeMaxDynamicSharedMemorySize, (int)SM128);
    cudaFuncSetAttribute((const void*)attn_fused,
                         cudaFuncAttributeMaxDynamicSharedMemorySize, (int)SMATT);

    // token2map
    cudaMemsetAsync(pFmap, 0, (size_t)B_ * HW_ * C_ * sizeof(float));
    cudaMemsetAsync(pCnt, 0, (size_t)B_ * HW_ * sizeof(float));
    scatter_kernel<<<(B_ * N_) / 8, 256>>>(x_source, loc);
    blur_fused_kernel<<<dim3(4, HM_, B_ * 4), 256>>>();

    // weight prep
    wprep_kernel<<<4096 + 512, 256>>>(sr_w, Wk, Wv);

    // conv (split-K x8, implicit im2col) + q projection, one launch
    conv_q_kernel<<<dim3(2, 144, 8), 256, SM128>>>(x, Wq);
    ln_kernel<<<B_ * NS_, 256>>>(sr_b, ln_w, ln_b);

    // fused k+v projection -> interleaved KV
    gemm_kernel<<<dim3(4, 16), 256, SM128>>>(pXs, C_, pWkv, C_, pKV, 2 * C_, C_, nullptr);
    // pack K fragments + V^T once
    kvpack_kernel<<<dim3(16, 16), 256>>>();

    // fused attention
    attn_fused<<<dim3(N_ / 128, B_ * HEADS_), 256, SMATT>>>(conf);

    // output projection (+bias)
    gemm_kernel<<<dim3(2, 128), 256, SM128>>>(pAO, C_, Wp, C_, out, C_, C_, bp);
}

// round 9
// speedup vs baseline: 5.1142x; 1.1181x over previous
#include <cuda_runtime.h>
#include <cuda_fp16.h>
#include <cstdint>
#include <math.h>

// Problem constants
#define B_    2
#define N_    8192
#define C_    256
#define HEADS_ 8
#define DH_   32
#define HM_   128
#define HW_   (HM_*HM_)
#define NS_   1024
#define KCOL_ 4096
#define KSPL_ 8
#define KCH_  (KCOL_/KSPL_)   // 512

// ---------------- scratch (device globals) ------------------------------------
__device__ float g_Fmap[B_ * HW_ * C_];
__device__ float g_Cnt [B_ * HW_];
__device__ float g_Xm  [B_ * HW_ * C_];
__device__ float g_Wc  [C_ * KCOL_];              // permuted conv weights
__device__ float g_Wkv [2 * C_ * C_];             // [Wk;Wv]
__device__ float g_CPart[KSPL_ * B_ * NS_ * C_];  // conv split-K partials
__device__ float g_Xs  [B_ * NS_ * C_];
__device__ float g_Q   [B_ * N_ * C_];
__device__ uint32_t g_KhW[16 * NS_ * 16];         // [bh][key][16 f16x2 words]
__device__ uint32_t g_VtW[16 * 32 * 512];         // [bh][d][512 words]
__device__ float g_AO  [B_ * N_ * C_];

// ================= fp16 mma helpers ===========================================
__device__ __forceinline__ uint32_t pkh2(float a, float b) {
    __half2 h = __floats2half2_rn(a, b);
    return *(uint32_t*)&h;
}
__device__ __forceinline__ void f16split(float x, float& hi, float& lo) {
    float h = __half2float(__float2half_rn(x));
    hi = h; lo = x - h;
}
__device__ __forceinline__ void mma16(float* c, const uint32_t* a, const uint32_t* b) {
    asm volatile(
        "mma.sync.aligned.m16n8k16.row.col.f32.f16.f16.f32 "
        "{%0,%1,%2,%3}, {%4,%5,%6,%7}, {%8,%9}, {%0,%1,%2,%3};"
        : "+f"(c[0]), "+f"(c[1]), "+f"(c[2]), "+f"(c[3])
        : "r"(a[0]), "r"(a[1]), "r"(a[2]), "r"(a[3]), "r"(b[0]), "r"(b[1]));
}

// implicit-im2col address for conv A
__device__ __forceinline__ const float* convA_addr(int m, int k) {
    int b = m >> 10, rr = m & 1023;
    int oy = rr >> 5, ox = rr & 31;
    int kk = k >> 8, ci = k & 255;
    int ky = kk >> 2, kx = kk & 3;
    int pix = (b << 14) + (oy * 4 + ky) * HM_ + ox * 4 + kx;
    return g_Xm + (size_t)pix * 256 + ci;
}

// ================= asymmetric fp16 GEMM body (double-buffered) ================
// EPI 0: C = A@B^T (+bias).  EPI 2: kv-pack epilogue (write KhW/VtW directly).
template<int BN, int WARPS_M, int WARPS_N, bool CONVA, int EPI>
__device__ __forceinline__ void gemm_body(
        const float* __restrict__ A, int lda, int kbase,
        const float* __restrict__ Bw, int ldb,
        float* __restrict__ Cb, int ldc,
        int K, const float* __restrict__ bias, int n0, int m0) {
    constexpr int WM_T = 128 / WARPS_M / 16;
    constexpr int WN_T = BN / WARPS_N / 8;
    constexpr int NB4 = BN / 32;
    constexpr int ES = BN + 4;
    constexpr int STW = 128 * 20 * 2 + BN * 20;   // words per stage

    extern __shared__ float smem[];
    uint32_t* stage0 = (uint32_t*)smem;
    float* epi = smem;

    const int t = threadIdx.x, lane = t & 31, warp = t >> 5;
    const int g = lane >> 2, tig = lane & 3;
    const int warpM = warp / WARPS_N, warpN = warp % WARPS_N;
    const int wrb = warpM * WM_T * 16, wcb = warpN * WN_T * 8;

    const int lr = t >> 3;
    const int lc = (t & 7) * 4;

    float acc[WM_T][WN_T][4];
#pragma unroll
    for (int i = 0; i < WM_T; i++)
#pragma unroll
        for (int j = 0; j < WN_T; j++)
#pragma unroll
            for (int q = 0; q < 4; q++) acc[i][j][q] = 0.f;

    const int nc = K >> 5;
    float4 pa[4], pb[NB4];

#define GB_LOAD(cc_)                                                              \
    {                                                                             \
        int k0_ = (cc_) << 5;                                                     \
        _Pragma("unroll")                                                         \
        for (int i = 0; i < 4; i++) {                                             \
            if (CONVA)                                                            \
                pa[i] = *(const float4*)convA_addr(m0 + lr + i * 32, kbase + k0_ + lc); \
            else                                                                  \
                pa[i] = *(const float4*)(A + (size_t)(m0 + lr + i * 32) * lda + k0_ + lc); \
        }                                                                         \
        _Pragma("unroll")                                                         \
        for (int i = 0; i < NB4; i++)                                             \
            pb[i] = *(const float4*)(Bw + (size_t)(n0 + lr + i * 32) * ldb + kbase + k0_ + lc); \
    }

#define GB_STORE(st_)                                                             \
    {                                                                             \
        uint32_t* AshW_ = stage0 + (st_) * STW;                                   \
        uint32_t* AslW_ = AshW_ + 128 * 20;                                       \
        uint32_t* BshW_ = AslW_ + 128 * 20;                                       \
        _Pragma("unroll")                                                         \
        for (int i = 0; i < 4; i++) {                                             \
            float h0, l0, h1, l1, h2, l2, h3, l3;                                 \
            f16split(pa[i].x, h0, l0); f16split(pa[i].y, h1, l1);                 \
            f16split(pa[i].z, h2, l2); f16split(pa[i].w, h3, l3);                 \
            *(uint2*)&AshW_[(lr + i * 32) * 20 + (lc >> 1)] = make_uint2(pkh2(h0, h1), pkh2(h2, h3)); \
            *(uint2*)&AslW_[(lr + i * 32) * 20 + (lc >> 1)] = make_uint2(pkh2(l0, l1), pkh2(l2, l3)); \
        }                                                                         \
        _Pragma("unroll")                                                         \
        for (int i = 0; i < NB4; i++)                                             \
            *(uint2*)&BshW_[(lr + i * 32) * 20 + (lc >> 1)] =                     \
                make_uint2(pkh2(pb[i].x, pb[i].y), pkh2(pb[i].z, pb[i].w));       \
    }

    GB_LOAD(0);
    GB_STORE(0);
    __syncthreads();
    if (nc > 1) GB_LOAD(1);

    for (int c = 0; c < nc; c++) {
        const int st = c & 1;
        const uint32_t* AshW = stage0 + st * STW;
        const uint32_t* AslW = AshW + 128 * 20;
        const uint32_t* BshW = AslW + 128 * 20;
#pragma unroll
        for (int ks = 0; ks < 2; ks++) {
            const int w0 = ks * 8;
            uint32_t ah[WM_T][4], al[WM_T][4];
#pragma unroll
            for (int mt = 0; mt < WM_T; mt++) {
                int r0 = wrb + mt * 16;
                ah[mt][0] = AshW[(r0 + g) * 20 + w0 + tig];
                ah[mt][1] = AshW[(r0 + 8 + g) * 20 + w0 + tig];
                ah[mt][2] = AshW[(r0 + g) * 20 + w0 + 4 + tig];
                ah[mt][3] = AshW[(r0 + 8 + g) * 20 + w0 + 4 + tig];
                al[mt][0] = AslW[(r0 + g) * 20 + w0 + tig];
                al[mt][1] = AslW[(r0 + 8 + g) * 20 + w0 + tig];
                al[mt][2] = AslW[(r0 + g) * 20 + w0 + 4 + tig];
                al[mt][3] = AslW[(r0 + 8 + g) * 20 + w0 + 4 + tig];
            }
            uint32_t bh[WN_T][2];
#pragma unroll
            for (int nt = 0; nt < WN_T; nt++) {
                int nr = wcb + nt * 8 + g;
                bh[nt][0] = BshW[nr * 20 + w0 + tig];
                bh[nt][1] = BshW[nr * 20 + w0 + 4 + tig];
            }
#pragma unroll
            for (int mt = 0; mt < WM_T; mt++)
#pragma unroll
                for (int nt = 0; nt < WN_T; nt++) {
                    mma16(acc[mt][nt], ah[mt], bh[nt]);
                    mma16(acc[mt][nt], al[mt], bh[nt]);
                }
        }
        if (c + 1 < nc) {
            GB_STORE(st ^ 1);
            __syncthreads();
            if (c + 2 < nc) GB_LOAD(c + 2);
        }
    }
    __syncthreads();
#pragma unroll
    for (int mt = 0; mt < WM_T; mt++)
#pragma unroll
        for (int nt = 0; nt < WN_T; nt++) {
            int r = wrb + mt * 16 + g;
            int cc = wcb + nt * 8 + 2 * tig;
            epi[r * ES + cc] = acc[mt][nt][0];
            epi[r * ES + cc + 1] = acc[mt][nt][1];
            epi[(r + 8) * ES + cc] = acc[mt][nt][2];
            epi[(r + 8) * ES + cc + 1] = acc[mt][nt][3];
        }
    __syncthreads();

    if (EPI == 0) {
        for (int idx = t; idx < 128 * BN; idx += 256) {
            int r = idx / BN, cc = idx % BN;
            float v = epi[r * ES + cc];
            if (bias) v += bias[n0 + cc];
            Cb[(size_t)(m0 + r) * ldc + n0 + cc] = v;
        }
    } else {
        // kv-pack: n0<256 -> K dims; else V dims (transposed pack)
        if (n0 < 256) {
            for (int u = t; u < 128 * 64; u += 256) {
                int r = u >> 6, wp = u & 63;
                int cc = 2 * wp;
                int dim = n0 + cc;
                int h = dim >> 5, w2 = (dim & 31) >> 1;
                int m = m0 + r;
                int b = m >> 10, key = m & 1023;
                g_KhW[((size_t)((b * 8 + h) * NS_ + key)) * 16 + w2] =
                    pkh2(epi[r * ES + cc], epi[r * ES + cc + 1]);
            }
        } else {
            for (int u = t; u < 64 * 128; u += 256) {
                int wl = u >> 7, cc = u & 127;
                int dim = n0 - 256 + cc;
                int h = dim >> 5, d = dim & 31;
                int m = m0 + 2 * wl;
                int b = m >> 10, keyloc = m & 1023;
                g_VtW[((size_t)((b * 8 + h) * 32 + d)) * 512 + (keyloc >> 1)] =
                    pkh2(epi[(2 * wl) * ES + cc], epi[(2 * wl + 1) * ES + cc]);
            }
        }
    }
#undef GB_LOAD
#undef GB_STORE
}

// ---- merged conv(split-K x8) + q-projection launch ----------------------------
__global__ void __launch_bounds__(256, 1)
conv_q_kernel(const float* __restrict__ x, const float* __restrict__ Wq) {
    if (blockIdx.y < 16) {
        int zh = blockIdx.z;
        gemm_body<128, 2, 4, true, 0>(
            nullptr, 0, zh * KCH_, g_Wc, KCOL_,
            g_CPart + (size_t)zh * (B_ * NS_ * C_), C_,
            KCH_, nullptr, blockIdx.x * 128, blockIdx.y * 128);
    } else {
        if (blockIdx.z) return;
        gemm_body<128, 2, 4, false, 0>(
            x, C_, 0, Wq, C_, g_Q, C_,
            C_, nullptr, blockIdx.x * 128, (blockIdx.y - 16) * 128);
    }
}

__global__ void __launch_bounds__(256, 1)
gemm_kernel(const float* __restrict__ A, int lda,
            const float* __restrict__ Bw, int ldb,
            float* __restrict__ Cm, int ldc,
            int K, const float* __restrict__ bias) {
    gemm_body<128, 2, 4, false, 0>(A, lda, 0, Bw, ldb, Cm, ldc, K, bias,
                                   blockIdx.x * 128, blockIdx.y * 128);
}

// KV projection with packing epilogue (writes g_KhW / g_VtW directly)
__global__ void __launch_bounds__(256, 1)
kv_gemm_kernel(const float* __restrict__ A, const float* __restrict__ Bw) {
    gemm_body<128, 2, 4, false, 2>(A, C_, 0, Bw, C_, nullptr, 0, C_, nullptr,
                                   blockIdx.x * 128, blockIdx.y * 128);
}

// ================= fused flash attention (double-buffered KV) =================
__global__ void __launch_bounds__(256, 1)
attn_fused(const float* __restrict__ conf) {
    extern __shared__ float smem[];
    uint32_t* QhW = (uint32_t*)smem;            // [128][20]
    uint32_t* QlW = QhW + 128 * 20;
    uint32_t* stg = QlW + 128 * 20;             // 2 stages: [128*20 K][32*68 V][128 conf]
    const int STW = 128 * 20 + 32 * 68 + 128;

    const int t = threadIdx.x, lane = t & 31, warp = t >> 5;
    const int g = lane >> 2, tig = lane & 3;
    const int bh = blockIdx.y, b = bh >> 3, h = bh & 7;
    const int m0 = blockIdx.x << 7;
    const int wrb = warp << 4;
    const float scale = 0.17677669529663687f;

    // Q tile (x scale) -> fp16 hi/lo packed
    {
        const int lr = t >> 3, lc = (t & 7) * 4;
#pragma unroll
        for (int i = 0; i < 4; i++) {
            int r = lr + i * 32;
            float4 v = *(const float4*)(g_Q + (size_t)(b * N_ + m0 + r) * C_ + h * DH_ + lc);
            float h0, l0, h1, l1, h2, l2, h3, l3;
            f16split(v.x * scale, h0, l0); f16split(v.y * scale, h1, l1);
            f16split(v.z * scale, h2, l2); f16split(v.w * scale, h3, l3);
            *(uint2*)&QhW[r * 20 + (lc >> 1)] = make_uint2(pkh2(h0, h1), pkh2(h2, h3));
            *(uint2*)&QlW[r * 20 + (lc >> 1)] = make_uint2(pkh2(l0, l1), pkh2(l2, l3));
        }
    }

    float Oacc[4][4];
#pragma unroll
    for (int i = 0; i < 4; i++)
#pragma unroll
        for (int j = 0; j < 4; j++) Oacc[i][j] = 0.f;
    float l0s = 0.f, l1s = 0.f;

    const uint4* KhG = (const uint4*)g_KhW;
    const uint4* VtG = (const uint4*)g_VtW;
    uint4 kr[2], vr[2];
    float cf;

#define AT_LOAD(kc_)                                                              \
    {                                                                             \
        int kb_ = (kc_) << 7;                                                     \
        _Pragma("unroll")                                                         \
        for (int i = 0; i < 2; i++) {                                             \
            int u = t + i * 256;                                                  \
            kr[i] = KhG[(size_t)(bh * NS_ + kb_ + (u >> 2)) * 4 + (u & 3)];       \
            vr[i] = VtG[(size_t)(bh * 32 + (u >> 4)) * 128 + (kc_) * 16 + (u & 15)]; \
        }                                                                         \
        if (t < 128) cf = conf[b * NS_ + kb_ + t];                                \
    }

#define AT_STORE(st_)                                                             \
    {                                                                             \
        uint32_t* KsW_ = stg + (st_) * STW;                                       \
        uint32_t* VsW_ = KsW_ + 128 * 20;                                         \
        float* cf_ = (float*)(VsW_ + 32 * 68);                                    \
        _Pragma("unroll")                                                         \
        for (int i = 0; i < 2; i++) {                                             \
            int u = t + i * 256;                                                  \
            *(uint4*)&KsW_[(u >> 2) * 20 + 4 * (u & 3)] = kr[i];                  \
            *(uint4*)&VsW_[(u >> 4) * 68 + 4 * (u & 15)] = vr[i];                 \
        }                                                                         \
        if (t < 128) cf_[t] = cf;                                                 \
    }

    AT_LOAD(0);
    AT_STORE(0);
    __syncthreads();
    AT_LOAD(1);

    for (int kc = 0; kc < 8; kc++) {
        const int st = kc & 1;
        const uint32_t* KsW = stg + st * STW;
        const uint32_t* VsW = KsW + 128 * 20;
        const float* confs = (const float*)(VsW + 32 * 68);

        float Sacc[16][4];
#pragma unroll
        for (int nt = 0; nt < 16; nt++)
#pragma unroll
            for (int q = 0; q < 4; q++) Sacc[nt][q] = 0.f;

#pragma unroll
        for (int ks = 0; ks < 2; ks++) {
            const int w0 = ks * 8;
            uint32_t ah[4], al[4];
            ah[0] = QhW[(wrb + g) * 20 + w0 + tig];
            ah[1] = QhW[(wrb + 8 + g) * 20 + w0 + tig];
            ah[2] = QhW[(wrb + g) * 20 + w0 + 4 + tig];
            ah[3] = QhW[(wrb + 8 + g) * 20 + w0 + 4 + tig];
            al[0] = QlW[(wrb + g) * 20 + w0 + tig];
            al[1] = QlW[(wrb + 8 + g) * 20 + w0 + tig];
            al[2] = QlW[(wrb + g) * 20 + w0 + 4 + tig];
            al[3] = QlW[(wrb + 8 + g) * 20 + w0 + 4 + tig];
#pragma unroll
            for (int nt = 0; nt < 16; nt++) {
                int nr = nt * 8 + g;
                uint32_t bv[2];
                bv[0] = KsW[nr * 20 + w0 + tig];
                bv[1] = KsW[nr * 20 + w0 + 4 + tig];
                mma16(Sacc[nt], ah, bv);
                mma16(Sacc[nt], al, bv);
            }
        }

#pragma unroll
        for (int j = 0; j < 8; j++) {
            const int nt0 = 2 * j, nt1 = 2 * j + 1;
            float ca0 = confs[nt0 * 8 + 2 * tig],  cb0 = confs[nt0 * 8 + 2 * tig + 1];
            float ca1 = confs[nt1 * 8 + 2 * tig],  cb1 = confs[nt1 * 8 + 2 * tig + 1];
            float p00 = __expf(Sacc[nt0][0] + ca0);
            float p01 = __expf(Sacc[nt0][1] + cb0);
            float p02 = __expf(Sacc[nt0][2] + ca0);
            float p03 = __expf(Sacc[nt0][3] + cb0);
            float p10 = __expf(Sacc[nt1][0] + ca1);
            float p11 = __expf(Sacc[nt1][1] + cb1);
            float p12 = __expf(Sacc[nt1][2] + ca1);
            float p13 = __expf(Sacc[nt1][3] + cb1);
            l0s += p00 + p01 + p10 + p11;
            l1s += p02 + p03 + p12 + p13;

            uint32_t a[4];
            a[0] = pkh2(p00, p01);
            a[1] = pkh2(p02, p03);
            a[2] = pkh2(p10, p11);
            a[3] = pkh2(p12, p13);
#pragma unroll
            for (int dt = 0; dt < 4; dt++) {
                uint32_t bv[2];
                bv[0] = VsW[(dt * 8 + g) * 68 + 8 * j + tig];
                bv[1] = VsW[(dt * 8 + g) * 68 + 8 * j + 4 + tig];
                mma16(Oacc[dt], a, bv);
            }
        }

        if (kc + 1 < 8) {
            AT_STORE(st ^ 1);
            __syncthreads();
            if (kc + 2 < 8) AT_LOAD(kc + 2);
        }
    }
#undef AT_LOAD
#undef AT_STORE

    l0s += __shfl_xor_sync(~0u, l0s, 1); l0s += __shfl_xor_sync(~0u, l0s, 2);
    l1s += __shfl_xor_sync(~0u, l1s, 1); l1s += __shfl_xor_sync(~0u, l1s, 2);
    float r0inv = 1.f / l0s, r1inv = 1.f / l1s;

#pragma unroll
    for (int dt = 0; dt < 4; dt++) {
        int cc = h * DH_ + dt * 8 + 2 * tig;
        size_t rowa = (size_t)(b * N_ + m0 + wrb + g) * C_;
        size_t rowb = (size_t)(b * N_ + m0 + wrb + 8 + g) * C_;
        g_AO[rowa + cc]     = Oacc[dt][0] * r0inv;
        g_AO[rowa + cc + 1] = Oacc[dt][1] * r0inv;
        g_AO[rowb + cc]     = Oacc[dt][2] * r1inv;
        g_AO[rowb + cc + 1] = Oacc[dt][3] * r1inv;
    }
}

// ================= preprocessing ==============================================
__global__ void __launch_bounds__(256) scatter_kernel(const float* __restrict__ xs,
                                                      const float* __restrict__ loc) {
    const int tok0 = blockIdx.x << 3;
    const int c = threadIdx.x;
    int p[8];
#pragma unroll
    for (int i = 0; i < 8; i++) {
        int token = tok0 + i;
        int b = token >> 13;
        float lx = loc[(size_t)token * 2 + 0];
        float ly = loc[(size_t)token * 2 + 1];
        lx = fminf(fmaxf(lx, 0.f), 1.f) * 127.f;
        ly = fminf(fmaxf(ly, 0.f), 1.f) * 127.f;
        p[i] = (b << 14) + (int)rintf(ly) * HM_ + (int)rintf(lx);
    }
#pragma unroll
    for (int i = 0; i < 8; i++) {
        atomicAdd(&g_Fmap[(size_t)p[i] * C_ + c], xs[(size_t)(tok0 + i) * C_ + c]);
        if (c == 0) atomicAdd(&g_Cnt[p[i]], 1.0f);
    }
}

__global__ void __launch_bounds__(256) blur_fused_kernel() {
    __shared__ float sf[3][34][64];
    __shared__ float minv[3][34];
    __shared__ float msk[3][34];

    const int t = threadIdx.x;
    const int x0 = blockIdx.x << 5;
    const int y = blockIdx.y;
    const int b = blockIdx.z >> 2, cg = blockIdx.z & 3;
    const int cbase = cg << 6;

    if (t < 102) {
        int r = t / 34, px = t % 34;
        int gy = y + r - 1, gx = x0 + px - 1;
        float inv = 0.f, mk = 0.f;
        if (gy >= 0 && gy < HM_ && gx >= 0 && gx < HM_) {
            float cnt = g_Cnt[(b << 14) + gy * HM_ + gx];
            if (cnt > 0.f) { inv = 1.f / (cnt + 1e-6f); mk = 1.f; }
        }
        minv[r][px] = inv;
        msk[r][px] = mk;
    }
    __syncthreads();

    for (int idx = t; idx < 3 * 34 * 64; idx += 256) {
        int r = idx / (34 * 64);
        int rem = idx - r * (34 * 64);
        int px = rem >> 6, c = rem & 63;
        int gy = y + r - 1, gx = x0 + px - 1;
        float val = 0.f;
        if (gy >= 0 && gy < HM_ && gx >= 0 && gx < HM_) {
            int pix = (b << 14) + gy * HM_ + gx;
            val = g_Fmap[(size_t)pix * 256 + cbase + c] * minv[r][px];
        }
        sf[r][px][c] = val;
    }
    __syncthreads();

    const float e1 = 0.88249690258459546f;
    const float e2 = 0.77880078307140487f;
    const float nrm = 1.0f / (1.0f + 4.0f * e1 + 4.0f * e2);
    const float wc = nrm, we = e1 * nrm, wo = e2 * nrm;

    const int c = t & 63;
    const int pg = t >> 6;
#pragma unroll
    for (int i = 0; i < 8; i++) {
        int px = pg * 8 + i;
        int ps = px + 1;
        float msum =
            wo * (msk[0][ps - 1] + msk[0][ps + 1] + msk[2][ps - 1] + msk[2][ps + 1]) +
            we * (msk[0][ps] + msk[1][ps - 1] + msk[1][ps + 1] + msk[2][ps]) +
            wc * msk[1][ps];
        float fsum =
            wo * (sf[0][ps - 1][c] + sf[0][ps + 1][c] + sf[2][ps - 1][c] + sf[2][ps + 1][c]) +
            we * (sf[0][ps][c] + sf[1][ps - 1][c] + sf[1][ps + 1][c] + sf[2][ps][c]) +
            wc * sf[1][ps][c];
        float fint = (msum > 0.f) ? fsum / (msum + 1e-6f) : 0.f;
        float fc = sf[1][ps][c];
        float mc = msk[1][ps];
        int cp = (b << 14) + y * HM_ + x0 + px;
        g_Xm[(size_t)cp * 256 + cbase + c] = fc + (1.f - mc) * fint;
    }
}

__global__ void __launch_bounds__(256) wprep_kernel(const float* __restrict__ srw,
                                                    const float* __restrict__ Wk,
                                                    const float* __restrict__ Wv) {
    int blk = blockIdx.x;
    if (blk < 4096) {
        int idx = blk * 256 + threadIdx.x;
        int co = idx >> 12;
        int r = idx & 4095;
        int kk = r >> 8;
        int ci = r & 255;
        g_Wc[idx] = srw[(size_t)co * 4096 + ci * 16 + kk];
    } else {
        int idx = (blk - 4096) * 256 + threadIdx.x;
        int row = idx >> 8, c = idx & 255;
        g_Wkv[idx] = (row < 256) ? Wk[row * 256 + c] : Wv[(row - 256) * 256 + c];
    }
}

__global__ void __launch_bounds__(256) ln_kernel(const float* __restrict__ srb,
                                                 const float* __restrict__ lnw,
                                                 const float* __restrict__ lnb) {
    __shared__ float red[8];
    int row = blockIdx.x, c = threadIdx.x;
    int lane = c & 31, wrp = c >> 5;
    float v = srb[c];
#pragma unroll
    for (int s = 0; s < KSPL_; s++)
        v += g_CPart[(size_t)s * (B_ * NS_ * C_) + (size_t)row * C_ + c];
    float s = v;
#pragma unroll
    for (int o = 16; o; o >>= 1) s += __shfl_xor_sync(~0u, s, o);
    if (lane == 0) red[wrp] = s;
    __syncthreads();
    float mu = (red[0] + red[1] + red[2] + red[3] + red[4] + red[5] + red[6] + red[7]) * (1.f / 256.f);
    float d = v - mu;
    float s2 = d * d;
#pragma unroll
    for (int o = 16; o; o >>= 1) s2 += __shfl_xor_sync(~0u, s2, o);
    __syncthreads();
    if (lane == 0) red[wrp] = s2;
    __syncthreads();
    float var = (red[0] + red[1] + red[2] + red[3] + red[4] + red[5] + red[6] + red[7]) * (1.f / 256.f);
    g_Xs[(size_t)row * C_ + c] = d * rsqrtf(var + 1e-5f) * lnw[c] + lnb[c];
}

// ================= launch =====================================================
extern "C" void kernel_launch(void* const* d_in, const int* in_sizes, int n_in,
                              void* d_out, int out_size) {
    const float* x        = (const float*)d_in[0];
    const float* x_source = (const float*)d_in[1];
    const float* loc      = (const float*)d_in[2];
    const float* conf     = (const float*)d_in[3];
    const float* Wq       = (const float*)d_in[4];
    const float* Wk       = (const float*)d_in[5];
    const float* Wv       = (const float*)d_in[6];
    const float* sr_w     = (const float*)d_in[7];
    const float* sr_b     = (const float*)d_in[8];
    const float* ln_w     = (const float*)d_in[9];
    const float* ln_b     = (const float*)d_in[10];
    const float* Wp       = (const float*)d_in[11];
    const float* bp       = (const float*)d_in[12];
    float* out = (float*)d_out;

    float *pFmap, *pCnt, *pWkv, *pXs, *pAO;
    cudaGetSymbolAddress((void**)&pFmap, g_Fmap);
    cudaGetSymbolAddress((void**)&pCnt, g_Cnt);
    cudaGetSymbolAddress((void**)&pWkv, g_Wkv);
    cudaGetSymbolAddress((void**)&pXs, g_Xs);
    cudaGetSymbolAddress((void**)&pAO, g_AO);

    // smem: gemm = max(2 stages 61440, epi 67584) = 67584
    //       attn = Q 20480 + 2*(128*20+32*68+128)*4 = 20480 + 38912 = 59392
    const size_t SM128 = 67584;
    const size_t SMATT = 20480 + 2 * (128 * 20 + 32 * 68 + 128) * 4;
    cudaFuncSetAttribute((const void*)conv_q_kernel,
                         cudaFuncAttributeMaxDynamicSharedMemorySize, (int)SM128);
    cudaFuncSetAttribute((const void*)gemm_kernel,
                         cudaFuncAttributeMaxDynamicSharedMemorySize, (int)SM128);
    cudaFuncSetAttribute((const void*)kv_gemm_kernel,
                         cudaFuncAttributeMaxDynamicSharedMemorySize, (int)SM128);
    cudaFuncSetAttribute((const void*)attn_fused,
                         cudaFuncAttributeMaxDynamicSharedMemorySize, (int)SMATT);

    // token2map
    cudaMemsetAsync(pFmap, 0, (size_t)B_ * HW_ * C_ * sizeof(float));
    cudaMemsetAsync(pCnt, 0, (size_t)B_ * HW_ * sizeof(float));
    scatter_kernel<<<(B_ * N_) / 8, 256>>>(x_source, loc);
    blur_fused_kernel<<<dim3(4, HM_, B_ * 4), 256>>>();

    // weight prep
    wprep_kernel<<<4096 + 512, 256>>>(sr_w, Wk, Wv);

    // conv (split-K x8, implicit im2col) + q projection, one launch
    conv_q_kernel<<<dim3(2, 144, 8), 256, SM128>>>(x, Wq);
    ln_kernel<<<B_ * NS_, 256>>>(sr_b, ln_w, ln_b);

    // fused k+v projection with packing epilogue
    kv_gemm_kernel<<<dim3(4, 16), 256, SM128>>>(pXs, pWkv);

    // fused attention
    attn_fused<<<dim3(N_ / 128, B_ * HEADS_), 256, SMATT>>>(conf);

    // output projection (+bias)
    gemm_kernel<<<dim3(2, 128), 256, SM128>>>(pAO, C_, Wp, C_, out, C_, C_, bp);
}